// round 1
// baseline (speedup 1.0000x reference)
#include <cuda_runtime.h>
#include <math.h>

#define B_   2
#define S_   2048
#define D_   512
#define H_   8
#define DK_  64
#define DFF_ 2048
#define L_   2
#define ROWS (B_*S_)   /* 4096 */

#define ATTN_SMEM_BYTES ((2*64*64 + 2*64*68) * 4)

// ---------------- scratch (static device globals; no allocations) ----------------
__device__ float g_zr [ROWS * D_];
__device__ float g_zi [ROWS * D_];
__device__ float g_qr [ROWS * D_];
__device__ float g_qi [ROWS * D_];
__device__ float g_kr [ROWS * D_];
__device__ float g_ki [ROWS * D_];
__device__ float g_v  [ROWS * D_];
__device__ float g_ctx[ROWS * D_];
__device__ float g_t0 [ROWS * D_];
__device__ float g_z1 [ROWS * D_];
__device__ float g_ff [ROWS * DFF_];

// ---------------- embedding lookup ----------------
__global__ void __launch_bounds__(128) embed_kernel(
    const int* __restrict__ tok, const float* __restrict__ emb, float* __restrict__ zr)
{
    int row = blockIdx.x;
    int t = tok[row];
    *(float4*)(zr + (size_t)row * D_ + threadIdx.x * 4) =
        *(const float4*)(emb + (size_t)t * D_ + threadIdx.x * 4);
}

// ---------------- positional imaginary part ----------------
// zi[b,s,d] = sin(s * freq[d/2]),  freq_j = 10000^{-j/256}
__global__ void __launch_bounds__(256) posimag_kernel(float* __restrict__ zi)
{
    int s = blockIdx.x;
    int j = threadIdx.x;                 // 0..255
    float freq = expf(-((float)j * (1.0f/256.0f)) * 9.2103403719761836f); // ln(10000)
    float val = sinf((float)s * freq);
    float2 vv = make_float2(val, val);   // repeat_interleave(2)
    int d = j * 2;
    *(float2*)(zi + (size_t)(0 * S_ + s) * D_ + d) = vv;
    *(float2*)(zi + (size_t)(1 * S_ + s) * D_ + d) = vv;
}

// ---------------- generic tiled SGEMM: C = sign*(A@B) [+C] [+bias] [relu] ----------------
// M,N multiples of 128; K multiple of 16.
__global__ void __launch_bounds__(256) sgemm_kernel(
    const float* __restrict__ A, const float* __restrict__ B, float* __restrict__ C,
    int M, int N, int K, float sign, int accum,
    const float* __restrict__ bias, int relu)
{
    __shared__ float As[16][132];   // transposed A tile [k][m], padded
    __shared__ float Bs[16][128];   // B tile [k][n]

    const int tid = threadIdx.x;
    const int tm = tid >> 4, tn = tid & 15;
    const int bm = blockIdx.y, bn = blockIdx.x;
    const int arow = tid >> 2, ac4 = (tid & 3) * 4;
    const int brow = tid >> 5, bc4 = (tid & 31) * 4;

    const float* Ab = A + (size_t)bm * 128 * K;
    const float* Bb = B + (size_t)bn * 128;

    float acc[8][8];
    #pragma unroll
    for (int i = 0; i < 8; i++)
        #pragma unroll
        for (int j = 0; j < 8; j++) acc[i][j] = 0.f;

    for (int k0 = 0; k0 < K; k0 += 16) {
        float4 a0 = *(const float4*)(Ab + (size_t) arow        * K + k0 + ac4);
        float4 a1 = *(const float4*)(Ab + (size_t)(arow + 64)  * K + k0 + ac4);
        float4 b0 = *(const float4*)(Bb + (size_t)(k0 + brow)     * N + bc4);
        float4 b1 = *(const float4*)(Bb + (size_t)(k0 + brow + 8) * N + bc4);

        As[ac4+0][arow]    = a0.x; As[ac4+1][arow]    = a0.y;
        As[ac4+2][arow]    = a0.z; As[ac4+3][arow]    = a0.w;
        As[ac4+0][arow+64] = a1.x; As[ac4+1][arow+64] = a1.y;
        As[ac4+2][arow+64] = a1.z; As[ac4+3][arow+64] = a1.w;
        *(float4*)(&Bs[brow  ][bc4]) = b0;
        *(float4*)(&Bs[brow+8][bc4]) = b1;
        __syncthreads();

        #pragma unroll
        for (int k = 0; k < 16; k++) {
            float4 x0 = *(const float4*)(&As[k][tm*8]);
            float4 x1 = *(const float4*)(&As[k][tm*8+4]);
            float4 y0 = *(const float4*)(&Bs[k][tn*8]);
            float4 y1 = *(const float4*)(&Bs[k][tn*8+4]);
            float av[8] = {x0.x,x0.y,x0.z,x0.w,x1.x,x1.y,x1.z,x1.w};
            float bv[8] = {y0.x,y0.y,y0.z,y0.w,y1.x,y1.y,y1.z,y1.w};
            #pragma unroll
            for (int i = 0; i < 8; i++)
                #pragma unroll
                for (int j = 0; j < 8; j++)
                    acc[i][j] += av[i] * bv[j];
        }
        __syncthreads();
    }

    const int row0 = bm * 128 + tm * 8;
    const int col0 = bn * 128 + tn * 8;
    #pragma unroll
    for (int i = 0; i < 8; i++) {
        #pragma unroll
        for (int j = 0; j < 8; j++) {
            float vv = sign * acc[i][j];
            size_t idx = (size_t)(row0 + i) * N + col0 + j;
            if (accum) vv += C[idx];
            if (bias)  vv += bias[col0 + j];
            if (relu)  vv = fmaxf(vv, 0.f);
            C[idx] = vv;
        }
    }
}

// ---------------- fused complex-hybrid flash attention ----------------
// grid: (S/64, H, B); 256 threads as 16x16, each owns a 4x4 microtile.
__global__ void __launch_bounds__(256) attn_kernel(
    const float* __restrict__ Qr, const float* __restrict__ Qi,
    const float* __restrict__ Kr, const float* __restrict__ Ki,
    const float* __restrict__ Vv, float* __restrict__ Out)
{
    extern __shared__ float sm[];
    float* qr_s = sm;                   // [64][64]
    float* qi_s = sm + 64*64;           // [64][64]
    float* bufA = sm + 2*64*64;         // krT [d][col] (stride 68) -> later P [row][col]
    float* bufB = bufA + 64*68;         // kiT [d][col]             -> later V [col][d]

    const int q0 = blockIdx.x * 64;
    const int h  = blockIdx.y;
    const int b  = blockIdx.z;
    const int tid = threadIdx.x;
    const int ty = tid >> 4, tx = tid & 15;

    const size_t base = ((size_t)b * S_) * D_ + (size_t)h * DK_;

    // load Q tile (row-major over d)
    for (int i = tid; i < 64*16; i += 256) {
        int r = i >> 4, c4 = (i & 15) * 4;
        *(float4*)(qr_s + r*64 + c4) = *(const float4*)(Qr + base + (size_t)(q0 + r) * D_ + c4);
        *(float4*)(qi_s + r*64 + c4) = *(const float4*)(Qi + base + (size_t)(q0 + r) * D_ + c4);
    }

    float m_i[4], l_i[4], acc[4][4];
    #pragma unroll
    for (int i = 0; i < 4; i++) {
        m_i[i] = -1e30f; l_i[i] = 0.f;
        #pragma unroll
        for (int j = 0; j < 4; j++) acc[i][j] = 0.f;
    }
    __syncthreads();

    for (int k0 = 0; k0 < S_; k0 += 64) {
        // load K tile transposed
        for (int i = tid; i < 64*16; i += 256) {
            int r = i >> 4, c4 = (i & 15) * 4;
            float4 a = *(const float4*)(Kr + base + (size_t)(k0 + r) * D_ + c4);
            float4 c = *(const float4*)(Ki + base + (size_t)(k0 + r) * D_ + c4);
            bufA[(c4+0)*68 + r] = a.x; bufA[(c4+1)*68 + r] = a.y;
            bufA[(c4+2)*68 + r] = a.z; bufA[(c4+3)*68 + r] = a.w;
            bufB[(c4+0)*68 + r] = c.x; bufB[(c4+1)*68 + r] = c.y;
            bufB[(c4+2)*68 + r] = c.z; bufB[(c4+3)*68 + r] = c.w;
        }
        __syncthreads();

        float sr[4][4], si[4][4];
        #pragma unroll
        for (int i = 0; i < 4; i++)
            #pragma unroll
            for (int j = 0; j < 4; j++) { sr[i][j] = 0.f; si[i][j] = 0.f; }

        #pragma unroll 8
        for (int d = 0; d < 64; d++) {
            float ar[4], ai[4];
            #pragma unroll
            for (int i = 0; i < 4; i++) {
                ar[i] = qr_s[(ty*4 + i)*64 + d];
                ai[i] = qi_s[(ty*4 + i)*64 + d];
            }
            float4 br4 = *(const float4*)(bufA + d*68 + tx*4);
            float4 bi4 = *(const float4*)(bufB + d*68 + tx*4);
            float brv[4] = {br4.x, br4.y, br4.z, br4.w};
            float biv[4] = {bi4.x, bi4.y, bi4.z, bi4.w};
            #pragma unroll
            for (int i = 0; i < 4; i++)
                #pragma unroll
                for (int j = 0; j < 4; j++) {
                    sr[i][j] += ar[i]*brv[j] + ai[i]*biv[j];
                    si[i][j] += ai[i]*brv[j] - ar[i]*biv[j];
                }
        }

        // hybrid score + online softmax (scores overwritten into sr)
        float corr[4];
        #pragma unroll
        for (int i = 0; i < 4; i++) {
            float rmax = -1e30f;
            #pragma unroll
            for (int j = 0; j < 4; j++) {
                float a = sr[i][j], bb = si[i][j];
                float m2 = a*a + bb*bb;
                float sc;
                if (m2 > 0.f) {
                    float rinv = rsqrtf(m2);
                    // (SCALE*|s| + alpha*cos(angle)) / sqrt(DK)
                    sc = (0.125f * (m2 * rinv) + 0.3f * (a * rinv)) * 0.125f;
                } else {
                    sc = 0.3f * 0.125f;   // cos(angle(0)) := 1
                }
                sr[i][j] = sc;
                rmax = fmaxf(rmax, sc);
            }
            #pragma unroll
            for (int o = 8; o >= 1; o >>= 1)
                rmax = fmaxf(rmax, __shfl_xor_sync(0xffffffffu, rmax, o));
            float mnew = fmaxf(m_i[i], rmax);
            float c = __expf(m_i[i] - mnew);
            float rsum = 0.f;
            #pragma unroll
            for (int j = 0; j < 4; j++) {
                float e = __expf(sr[i][j] - mnew);
                sr[i][j] = e;
                rsum += e;
            }
            #pragma unroll
            for (int o = 8; o >= 1; o >>= 1)
                rsum += __shfl_xor_sync(0xffffffffu, rsum, o);
            l_i[i] = l_i[i] * c + rsum;
            m_i[i] = mnew;
            corr[i] = c;
        }
        __syncthreads();   // all threads done reading K tiles

        // P -> bufA, V -> bufB
        #pragma unroll
        for (int i = 0; i < 4; i++) {
            float4 pv = make_float4(sr[i][0], sr[i][1], sr[i][2], sr[i][3]);
            *(float4*)(bufA + (ty*4 + i)*68 + tx*4) = pv;
        }
        for (int i = tid; i < 64*16; i += 256) {
            int r = i >> 4, c4 = (i & 15) * 4;
            *(float4*)(bufB + r*68 + c4) =
                *(const float4*)(Vv + base + (size_t)(k0 + r) * D_ + c4);
        }
        #pragma unroll
        for (int i = 0; i < 4; i++)
            #pragma unroll
            for (int j = 0; j < 4; j++) acc[i][j] *= corr[i];
        __syncthreads();

        // O += P @ V
        #pragma unroll 8
        for (int c = 0; c < 64; c++) {
            float pv[4];
            #pragma unroll
            for (int i = 0; i < 4; i++) pv[i] = bufA[(ty*4 + i)*68 + c];
            float4 vv4 = *(const float4*)(bufB + c*68 + tx*4);
            float vvv[4] = {vv4.x, vv4.y, vv4.z, vv4.w};
            #pragma unroll
            for (int i = 0; i < 4; i++)
                #pragma unroll
                for (int j = 0; j < 4; j++)
                    acc[i][j] += pv[i] * vvv[j];
        }
        __syncthreads();
    }

    #pragma unroll
    for (int i = 0; i < 4; i++) {
        float inv = 1.f / l_i[i];
        float4 o4 = make_float4(acc[i][0]*inv, acc[i][1]*inv, acc[i][2]*inv, acc[i][3]*inv);
        *(float4*)(Out + base + (size_t)(q0 + ty*4 + i) * D_ + tx*4) = o4;
    }
}

// ---------------- fused residual + layernorm ----------------
__global__ void __launch_bounds__(128) ln_res_kernel(
    const float* __restrict__ x, const float* __restrict__ r,
    const float* __restrict__ g, const float* __restrict__ be,
    float* __restrict__ out)
{
    __shared__ float red[8];
    int row = blockIdx.x, tid = threadIdx.x;   // 128 threads * 4 = 512
    float4 xv = *(const float4*)(x + (size_t)row * D_ + tid * 4);
    float4 rv = *(const float4*)(r + (size_t)row * D_ + tid * 4);
    float v0 = xv.x + rv.x, v1 = xv.y + rv.y, v2 = xv.z + rv.z, v3 = xv.w + rv.w;
    float s  = v0 + v1 + v2 + v3;
    float s2 = v0*v0 + v1*v1 + v2*v2 + v3*v3;
    #pragma unroll
    for (int o = 16; o >= 1; o >>= 1) {
        s  += __shfl_xor_sync(0xffffffffu, s,  o);
        s2 += __shfl_xor_sync(0xffffffffu, s2, o);
    }
    int warp = tid >> 5, lane = tid & 31;
    if (lane == 0) { red[warp] = s; red[4 + warp] = s2; }
    __syncthreads();
    s  = red[0] + red[1] + red[2] + red[3];
    s2 = red[4] + red[5] + red[6] + red[7];
    float mu  = s  * (1.0f / D_);
    float var = s2 * (1.0f / D_) - mu * mu;
    float inv = rsqrtf(var + 1e-5f);
    float4 gv = *(const float4*)(g  + tid * 4);
    float4 bv = *(const float4*)(be + tid * 4);
    float4 o4;
    o4.x = (v0 - mu) * inv * gv.x + bv.x;
    o4.y = (v1 - mu) * inv * gv.y + bv.y;
    o4.z = (v2 - mu) * inv * gv.z + bv.z;
    o4.w = (v3 - mu) * inv * gv.w + bv.w;
    *(float4*)(out + (size_t)row * D_ + tid * 4) = o4;
}

// ---------------- classification head (C=2): warp per row ----------------
__global__ void __launch_bounds__(256) head_kernel(
    const float* __restrict__ z, const float* __restrict__ w,
    const float* __restrict__ hb, float* __restrict__ out)
{
    int warp = threadIdx.x >> 5, lane = threadIdx.x & 31;
    int row = blockIdx.x * 8 + warp;
    const float* zr = z + (size_t)row * D_;
    float s0 = 0.f, s1 = 0.f;
    for (int d = lane; d < D_; d += 32) {
        float zv = zr[d];
        s0 += zv * w[d*2 + 0];
        s1 += zv * w[d*2 + 1];
    }
    #pragma unroll
    for (int o = 16; o >= 1; o >>= 1) {
        s0 += __shfl_xor_sync(0xffffffffu, s0, o);
        s1 += __shfl_xor_sync(0xffffffffu, s1, o);
    }
    if (lane == 0) {
        out[row*2 + 0] = s0 + hb[0];
        out[row*2 + 1] = s1 + hb[1];
    }
}

// ---------------- host-side orchestration ----------------
static inline void launch_gemm(const float* A, const float* B, float* C,
                               int M, int N, int K, float sign, int accum,
                               const float* bias, int relu)
{
    dim3 grid(N / 128, M / 128);
    sgemm_kernel<<<grid, 256>>>(A, B, C, M, N, K, sign, accum, bias, relu);
}

extern "C" void kernel_launch(void* const* d_in, const int* in_sizes, int n_in,
                              void* d_out, int out_size)
{
    (void)in_sizes; (void)n_in; (void)out_size;
    const int*   tokens = (const int*)  d_in[0];
    const float* embed  = (const float*)d_in[1];
    const float* Wqr = (const float*)d_in[2];
    const float* Wqi = (const float*)d_in[3];
    const float* Wkr = (const float*)d_in[4];
    const float* Wki = (const float*)d_in[5];
    const float* Wv  = (const float*)d_in[6];
    const float* Wo  = (const float*)d_in[7];
    const float* bo  = (const float*)d_in[8];
    const float* W1  = (const float*)d_in[9];
    const float* b1  = (const float*)d_in[10];
    const float* W2  = (const float*)d_in[11];
    const float* b2  = (const float*)d_in[12];
    const float* g1  = (const float*)d_in[13];
    const float* be1 = (const float*)d_in[14];
    const float* g2  = (const float*)d_in[15];
    const float* be2 = (const float*)d_in[16];
    const float* hw  = (const float*)d_in[17];
    const float* hb  = (const float*)d_in[18];
    float* out = (float*)d_out;

    float *zr,*zi,*qr,*qi,*kr,*ki,*vv,*ctx,*t0,*z1,*ff;
    cudaGetSymbolAddress((void**)&zr,  g_zr);
    cudaGetSymbolAddress((void**)&zi,  g_zi);
    cudaGetSymbolAddress((void**)&qr,  g_qr);
    cudaGetSymbolAddress((void**)&qi,  g_qi);
    cudaGetSymbolAddress((void**)&kr,  g_kr);
    cudaGetSymbolAddress((void**)&ki,  g_ki);
    cudaGetSymbolAddress((void**)&vv,  g_v);
    cudaGetSymbolAddress((void**)&ctx, g_ctx);
    cudaGetSymbolAddress((void**)&t0,  g_t0);
    cudaGetSymbolAddress((void**)&z1,  g_z1);
    cudaGetSymbolAddress((void**)&ff,  g_ff);

    cudaFuncSetAttribute(attn_kernel, cudaFuncAttributeMaxDynamicSharedMemorySize,
                         ATTN_SMEM_BYTES);

    embed_kernel<<<ROWS, 128>>>(tokens, embed, zr);
    posimag_kernel<<<S_, 256>>>(zi);

    for (int l = 0; l < L_; l++) {
        const float* wqr = Wqr + (size_t)l * D_ * D_;
        const float* wqi = Wqi + (size_t)l * D_ * D_;
        const float* wkr = Wkr + (size_t)l * D_ * D_;
        const float* wki = Wki + (size_t)l * D_ * D_;
        const float* wv  = Wv  + (size_t)l * D_ * D_;
        const float* wo  = Wo  + (size_t)l * D_ * D_;
        const float* bo_l  = bo  + (size_t)l * D_;
        const float* w1  = W1  + (size_t)l * D_ * DFF_;
        const float* b1_l  = b1  + (size_t)l * DFF_;
        const float* w2  = W2  + (size_t)l * DFF_ * D_;
        const float* b2_l  = b2  + (size_t)l * D_;
        const float* g1_l  = g1  + (size_t)l * D_;
        const float* be1_l = be1 + (size_t)l * D_;
        const float* g2_l  = g2  + (size_t)l * D_;
        const float* be2_l = be2 + (size_t)l * D_;

        launch_gemm(zr, wqr, qr, ROWS, D_, D_, 1.f, 0, nullptr, 0);
        launch_gemm(zr, wqi, qi, ROWS, D_, D_, 1.f, 0, nullptr, 0);
        launch_gemm(zr, wkr, kr, ROWS, D_, D_, 1.f, 0, nullptr, 0);
        launch_gemm(zr, wki, ki, ROWS, D_, D_, 1.f, 0, nullptr, 0);
        if (l == 0) {
            // complex parts (zi nonzero only in layer 0)
            launch_gemm(zi, wqi, qr, ROWS, D_, D_, -1.f, 1, nullptr, 0);
            launch_gemm(zi, wqr, qi, ROWS, D_, D_,  1.f, 1, nullptr, 0);
            launch_gemm(zi, wki, kr, ROWS, D_, D_, -1.f, 1, nullptr, 0);
            launch_gemm(zi, wkr, ki, ROWS, D_, D_,  1.f, 1, nullptr, 0);
        }
        launch_gemm(zr, wv, vv, ROWS, D_, D_, 1.f, 0, nullptr, 0);

        dim3 ag(S_ / 64, H_, B_);
        attn_kernel<<<ag, 256, ATTN_SMEM_BYTES>>>(qr, qi, kr, ki, vv, ctx);

        launch_gemm(ctx, wo, t0, ROWS, D_, D_, 1.f, 0, bo_l, 0);
        ln_res_kernel<<<ROWS, 128>>>(zr, t0, g1_l, be1_l, z1);
        launch_gemm(z1, w1, ff, ROWS, DFF_, D_, 1.f, 0, b1_l, 1);   // + relu
        launch_gemm(ff, w2, t0, ROWS, D_, DFF_, 1.f, 0, b2_l, 0);
        ln_res_kernel<<<ROWS, 128>>>(z1, t0, g2_l, be2_l, zr);
    }

    head_kernel<<<ROWS / 8, 256>>>(zr, hw, hb, out);
}

// round 3
// speedup vs baseline: 1.4205x; 1.4205x over previous
#include <cuda_runtime.h>
#include <math.h>
#include <stdint.h>

#define B_   2
#define S_   2048
#define D_   512
#define H_   8
#define DK_  64
#define DFF_ 2048
#define L_   2
#define ROWS (B_*S_)   /* 4096 */

#define ATTN_SMEM_BYTES ((2*64*64 + 2*64*68) * 4)

// ---------------- scratch (static device globals; no allocations) ----------------
__device__ float g_zr [ROWS * D_];
__device__ float g_zi [ROWS * D_];
__device__ float g_qr [ROWS * D_];
__device__ float g_qi [ROWS * D_];
__device__ float g_kr [ROWS * D_];
__device__ float g_ki [ROWS * D_];
__device__ float g_v  [ROWS * D_];
__device__ float g_ctx[ROWS * D_];
__device__ float g_t0 [ROWS * D_];
__device__ float g_z1 [ROWS * D_];
__device__ float g_ff [ROWS * DFF_];
// transposed weights: per layer 6*(512*512) + 2*(512*2048) floats
#define WT_PER_LAYER (6*D_*D_ + 2*D_*DFF_)
__device__ float g_wt[L_ * WT_PER_LAYER];

__device__ __forceinline__ float to_tf32f(float x) {
    uint32_t r;
    asm("cvt.rna.tf32.f32 %0, %1;" : "=r"(r) : "f"(x));
    return __uint_as_float(r);
}

// ---------------- tf32 tensor-core GEMM: C = sign*(A@Bt^T) [+C] [+bias] [relu] ----
// A: [M x K] row-major fp32. Bt: [N x K] row-major fp32 (pre-transposed weights).
// M,N multiples of 128; K multiple of 32. Grid (N/128, M/128), 256 threads (8 warps).
// Warp grid 2x4; warp tile 64(m) x 32(n) = 4x4 fragments of m16n8k8.
__global__ void __launch_bounds__(256) tc_gemm_kernel(
    const float* __restrict__ A, const float* __restrict__ Bt, float* __restrict__ C,
    int M, int N, int K, float sign, int accum,
    const float* __restrict__ bias, int relu)
{
    __shared__ float As[128][36];
    __shared__ float Bs[128][36];

    const int tid  = threadIdx.x;
    const int wid  = tid >> 5, lane = tid & 31;
    const int gid  = lane >> 2, tig = lane & 3;
    const int wy   = wid >> 2, wx = wid & 3;
    const int bm   = blockIdx.y, bn = blockIdx.x;

    const float* Ab = A  + (size_t)bm * 128 * K;
    const float* Bb = Bt + (size_t)bn * 128 * K;

    const int lr = tid >> 3;          // 0..31
    const int lc = (tid & 7) * 4;     // 0..28

    float acc[4][4][4];
    #pragma unroll
    for (int i = 0; i < 4; i++)
        #pragma unroll
        for (int j = 0; j < 4; j++)
            #pragma unroll
            for (int r = 0; r < 4; r++) acc[i][j][r] = 0.f;

    const int nch = K >> 5;

    float4 ar[4], br[4];
    #pragma unroll
    for (int rr = 0; rr < 4; rr++) {
        ar[rr] = *(const float4*)(Ab + (size_t)(lr + rr*32) * K + lc);
        br[rr] = *(const float4*)(Bb + (size_t)(lr + rr*32) * K + lc);
    }

    for (int c = 0; c < nch; c++) {
        __syncthreads();
        #pragma unroll
        for (int rr = 0; rr < 4; rr++) {
            const int r = lr + rr * 32;
            As[r][lc+0] = to_tf32f(ar[rr].x); As[r][lc+1] = to_tf32f(ar[rr].y);
            As[r][lc+2] = to_tf32f(ar[rr].z); As[r][lc+3] = to_tf32f(ar[rr].w);
            Bs[r][lc+0] = to_tf32f(br[rr].x); Bs[r][lc+1] = to_tf32f(br[rr].y);
            Bs[r][lc+2] = to_tf32f(br[rr].z); Bs[r][lc+3] = to_tf32f(br[rr].w);
        }
        __syncthreads();

        if (c + 1 < nch) {
            const int kg = (c + 1) * 32 + lc;
            #pragma unroll
            for (int rr = 0; rr < 4; rr++) {
                ar[rr] = *(const float4*)(Ab + (size_t)(lr + rr*32) * K + kg);
                br[rr] = *(const float4*)(Bb + (size_t)(lr + rr*32) * K + kg);
            }
        }

        #pragma unroll
        for (int ks = 0; ks < 4; ks++) {
            const int k0 = ks * 8;
            uint32_t af[4][4];
            #pragma unroll
            for (int mf = 0; mf < 4; mf++) {
                const int r = wy * 64 + mf * 16;
                af[mf][0] = __float_as_uint(As[r + gid    ][k0 + tig    ]);
                af[mf][1] = __float_as_uint(As[r + gid + 8][k0 + tig    ]);
                af[mf][2] = __float_as_uint(As[r + gid    ][k0 + tig + 4]);
                af[mf][3] = __float_as_uint(As[r + gid + 8][k0 + tig + 4]);
            }
            uint32_t bf[4][2];
            #pragma unroll
            for (int nf = 0; nf < 4; nf++) {
                const int n = wx * 32 + nf * 8;
                bf[nf][0] = __float_as_uint(Bs[n + gid][k0 + tig    ]);
                bf[nf][1] = __float_as_uint(Bs[n + gid][k0 + tig + 4]);
            }
            #pragma unroll
            for (int mf = 0; mf < 4; mf++)
                #pragma unroll
                for (int nf = 0; nf < 4; nf++) {
                    asm volatile(
                        "mma.sync.aligned.m16n8k8.row.col.f32.tf32.tf32.f32 "
                        "{%0,%1,%2,%3}, {%4,%5,%6,%7}, {%8,%9}, {%0,%1,%2,%3};"
                        : "+f"(acc[mf][nf][0]), "+f"(acc[mf][nf][1]),
                          "+f"(acc[mf][nf][2]), "+f"(acc[mf][nf][3])
                        : "r"(af[mf][0]), "r"(af[mf][1]), "r"(af[mf][2]), "r"(af[mf][3]),
                          "r"(bf[nf][0]), "r"(bf[nf][1]));
                }
        }
    }

    // epilogue
    float2 bsv[4];
    if (bias) {
        #pragma unroll
        for (int nf = 0; nf < 4; nf++) {
            const int col = bn * 128 + wx * 32 + nf * 8 + tig * 2;
            bsv[nf] = *(const float2*)(bias + col);
        }
    }
    #pragma unroll
    for (int mf = 0; mf < 4; mf++) {
        const int row = bm * 128 + wy * 64 + mf * 16 + gid;
        #pragma unroll
        for (int nf = 0; nf < 4; nf++) {
            const int col = bn * 128 + wx * 32 + nf * 8 + tig * 2;
            #pragma unroll
            for (int half = 0; half < 2; half++) {
                const int r = row + half * 8;
                float2 v;
                v.x = sign * acc[mf][nf][half*2 + 0];
                v.y = sign * acc[mf][nf][half*2 + 1];
                float* cp = C + (size_t)r * N + col;
                if (accum) {
                    float2 cv = *(const float2*)cp;
                    v.x += cv.x; v.y += cv.y;
                }
                if (bias) { v.x += bsv[nf].x; v.y += bsv[nf].y; }
                if (relu) { v.x = fmaxf(v.x, 0.f); v.y = fmaxf(v.y, 0.f); }
                *(float2*)cp = v;
            }
        }
    }
}

// ---------------- weight transpose: out[c][r] = in[r][c] ----------------
__global__ void __launch_bounds__(256) transpose_kernel(
    const float* __restrict__ in, float* __restrict__ out, int R, int Cc)
{
    __shared__ float t[32][33];
    int r0 = blockIdx.y * 32, c0 = blockIdx.x * 32;
    #pragma unroll
    for (int i = threadIdx.y; i < 32; i += 8)
        t[i][threadIdx.x] = in[(size_t)(r0 + i) * Cc + c0 + threadIdx.x];
    __syncthreads();
    #pragma unroll
    for (int i = threadIdx.y; i < 32; i += 8)
        out[(size_t)(c0 + i) * R + r0 + threadIdx.x] = t[threadIdx.x][i];
}

// ---------------- embedding lookup ----------------
__global__ void __launch_bounds__(128) embed_kernel(
    const int* __restrict__ tok, const float* __restrict__ emb, float* __restrict__ zr)
{
    int row = blockIdx.x;
    int t = tok[row];
    *(float4*)(zr + (size_t)row * D_ + threadIdx.x * 4) =
        *(const float4*)(emb + (size_t)t * D_ + threadIdx.x * 4);
}

// ---------------- positional imaginary part ----------------
__global__ void __launch_bounds__(256) posimag_kernel(float* __restrict__ zi)
{
    int s = blockIdx.x;
    int j = threadIdx.x;
    float freq = expf(-((float)j * (1.0f/256.0f)) * 9.2103403719761836f);
    float val = sinf((float)s * freq);
    float2 vv = make_float2(val, val);
    int d = j * 2;
    *(float2*)(zi + (size_t)(0 * S_ + s) * D_ + d) = vv;
    *(float2*)(zi + (size_t)(1 * S_ + s) * D_ + d) = vv;
}

// ---------------- fused complex-hybrid flash attention ----------------
__global__ void __launch_bounds__(256) attn_kernel(
    const float* __restrict__ Qr, const float* __restrict__ Qi,
    const float* __restrict__ Kr, const float* __restrict__ Ki,
    const float* __restrict__ Vv, float* __restrict__ Out)
{
    extern __shared__ float sm[];
    float* qr_s = sm;
    float* qi_s = sm + 64*64;
    float* bufA = sm + 2*64*64;
    float* bufB = bufA + 64*68;

    const int q0 = blockIdx.x * 64;
    const int h  = blockIdx.y;
    const int b  = blockIdx.z;
    const int tid = threadIdx.x;
    const int ty = tid >> 4, tx = tid & 15;

    const size_t base = ((size_t)b * S_) * D_ + (size_t)h * DK_;

    for (int i = tid; i < 64*16; i += 256) {
        int r = i >> 4, c4 = (i & 15) * 4;
        *(float4*)(qr_s + r*64 + c4) = *(const float4*)(Qr + base + (size_t)(q0 + r) * D_ + c4);
        *(float4*)(qi_s + r*64 + c4) = *(const float4*)(Qi + base + (size_t)(q0 + r) * D_ + c4);
    }

    float m_i[4], l_i[4], acc[4][4];
    #pragma unroll
    for (int i = 0; i < 4; i++) {
        m_i[i] = -1e30f; l_i[i] = 0.f;
        #pragma unroll
        for (int j = 0; j < 4; j++) acc[i][j] = 0.f;
    }
    __syncthreads();

    for (int k0 = 0; k0 < S_; k0 += 64) {
        for (int i = tid; i < 64*16; i += 256) {
            int r = i >> 4, c4 = (i & 15) * 4;
            float4 a = *(const float4*)(Kr + base + (size_t)(k0 + r) * D_ + c4);
            float4 c = *(const float4*)(Ki + base + (size_t)(k0 + r) * D_ + c4);
            bufA[(c4+0)*68 + r] = a.x; bufA[(c4+1)*68 + r] = a.y;
            bufA[(c4+2)*68 + r] = a.z; bufA[(c4+3)*68 + r] = a.w;
            bufB[(c4+0)*68 + r] = c.x; bufB[(c4+1)*68 + r] = c.y;
            bufB[(c4+2)*68 + r] = c.z; bufB[(c4+3)*68 + r] = c.w;
        }
        __syncthreads();

        float sr[4][4], si[4][4];
        #pragma unroll
        for (int i = 0; i < 4; i++)
            #pragma unroll
            for (int j = 0; j < 4; j++) { sr[i][j] = 0.f; si[i][j] = 0.f; }

        #pragma unroll 8
        for (int d = 0; d < 64; d++) {
            float ar[4], ai[4];
            #pragma unroll
            for (int i = 0; i < 4; i++) {
                ar[i] = qr_s[(ty*4 + i)*64 + d];
                ai[i] = qi_s[(ty*4 + i)*64 + d];
            }
            float4 br4 = *(const float4*)(bufA + d*68 + tx*4);
            float4 bi4 = *(const float4*)(bufB + d*68 + tx*4);
            float brv[4] = {br4.x, br4.y, br4.z, br4.w};
            float biv[4] = {bi4.x, bi4.y, bi4.z, bi4.w};
            #pragma unroll
            for (int i = 0; i < 4; i++)
                #pragma unroll
                for (int j = 0; j < 4; j++) {
                    sr[i][j] += ar[i]*brv[j] + ai[i]*biv[j];
                    si[i][j] += ai[i]*brv[j] - ar[i]*biv[j];
                }
        }

        float corr[4];
        #pragma unroll
        for (int i = 0; i < 4; i++) {
            float rmax = -1e30f;
            #pragma unroll
            for (int j = 0; j < 4; j++) {
                float a = sr[i][j], bb = si[i][j];
                float m2 = a*a + bb*bb;
                float sc;
                if (m2 > 0.f) {
                    float rinv = rsqrtf(m2);
                    sc = (0.125f * (m2 * rinv) + 0.3f * (a * rinv)) * 0.125f;
                } else {
                    sc = 0.3f * 0.125f;
                }
                sr[i][j] = sc;
                rmax = fmaxf(rmax, sc);
            }
            #pragma unroll
            for (int o = 8; o >= 1; o >>= 1)
                rmax = fmaxf(rmax, __shfl_xor_sync(0xffffffffu, rmax, o));
            float mnew = fmaxf(m_i[i], rmax);
            float c = __expf(m_i[i] - mnew);
            float rsum = 0.f;
            #pragma unroll
            for (int j = 0; j < 4; j++) {
                float e = __expf(sr[i][j] - mnew);
                sr[i][j] = e;
                rsum += e;
            }
            #pragma unroll
            for (int o = 8; o >= 1; o >>= 1)
                rsum += __shfl_xor_sync(0xffffffffu, rsum, o);
            l_i[i] = l_i[i] * c + rsum;
            m_i[i] = mnew;
            corr[i] = c;
        }
        __syncthreads();

        #pragma unroll
        for (int i = 0; i < 4; i++) {
            float4 pv = make_float4(sr[i][0], sr[i][1], sr[i][2], sr[i][3]);
            *(float4*)(bufA + (ty*4 + i)*68 + tx*4) = pv;
        }
        for (int i = tid; i < 64*16; i += 256) {
            int r = i >> 4, c4 = (i & 15) * 4;
            *(float4*)(bufB + r*68 + c4) =
                *(const float4*)(Vv + base + (size_t)(k0 + r) * D_ + c4);
        }
        #pragma unroll
        for (int i = 0; i < 4; i++)
            #pragma unroll
            for (int j = 0; j < 4; j++) acc[i][j] *= corr[i];
        __syncthreads();

        #pragma unroll 8
        for (int c = 0; c < 64; c++) {
            float pv[4];
            #pragma unroll
            for (int i = 0; i < 4; i++) pv[i] = bufA[(ty*4 + i)*68 + c];
            float4 vv4 = *(const float4*)(bufB + c*68 + tx*4);
            float vvv[4] = {vv4.x, vv4.y, vv4.z, vv4.w};
            #pragma unroll
            for (int i = 0; i < 4; i++)
                #pragma unroll
                for (int j = 0; j < 4; j++)
                    acc[i][j] += pv[i] * vvv[j];
        }
        __syncthreads();
    }

    #pragma unroll
    for (int i = 0; i < 4; i++) {
        float inv = 1.f / l_i[i];
        float4 o4 = make_float4(acc[i][0]*inv, acc[i][1]*inv, acc[i][2]*inv, acc[i][3]*inv);
        *(float4*)(Out + base + (size_t)(q0 + ty*4 + i) * D_ + tx*4) = o4;
    }
}

// ---------------- fused residual + layernorm ----------------
__global__ void __launch_bounds__(128) ln_res_kernel(
    const float* __restrict__ x, const float* __restrict__ r,
    const float* __restrict__ g, const float* __restrict__ be,
    float* __restrict__ out)
{
    __shared__ float red[8];
    int row = blockIdx.x, tid = threadIdx.x;
    float4 xv = *(const float4*)(x + (size_t)row * D_ + tid * 4);
    float4 rv = *(const float4*)(r + (size_t)row * D_ + tid * 4);
    float v0 = xv.x + rv.x, v1 = xv.y + rv.y, v2 = xv.z + rv.z, v3 = xv.w + rv.w;
    float s  = v0 + v1 + v2 + v3;
    float s2 = v0*v0 + v1*v1 + v2*v2 + v3*v3;
    #pragma unroll
    for (int o = 16; o >= 1; o >>= 1) {
        s  += __shfl_xor_sync(0xffffffffu, s,  o);
        s2 += __shfl_xor_sync(0xffffffffu, s2, o);
    }
    int warp = tid >> 5, lane = tid & 31;
    if (lane == 0) { red[warp] = s; red[4 + warp] = s2; }
    __syncthreads();
    s  = red[0] + red[1] + red[2] + red[3];
    s2 = red[4] + red[5] + red[6] + red[7];
    float mu  = s  * (1.0f / D_);
    float var = s2 * (1.0f / D_) - mu * mu;
    float inv = rsqrtf(var + 1e-5f);
    float4 gv = *(const float4*)(g  + tid * 4);
    float4 bv = *(const float4*)(be + tid * 4);
    float4 o4;
    o4.x = (v0 - mu) * inv * gv.x + bv.x;
    o4.y = (v1 - mu) * inv * gv.y + bv.y;
    o4.z = (v2 - mu) * inv * gv.z + bv.z;
    o4.w = (v3 - mu) * inv * gv.w + bv.w;
    *(float4*)(out + (size_t)row * D_ + tid * 4) = o4;
}

// ---------------- classification head (C=2): warp per row ----------------
__global__ void __launch_bounds__(256) head_kernel(
    const float* __restrict__ z, const float* __restrict__ w,
    const float* __restrict__ hb, float* __restrict__ out)
{
    int warp = threadIdx.x >> 5, lane = threadIdx.x & 31;
    int row = blockIdx.x * 8 + warp;
    const float* zr = z + (size_t)row * D_;
    float s0 = 0.f, s1 = 0.f;
    for (int d = lane; d < D_; d += 32) {
        float zv = zr[d];
        s0 += zv * w[d*2 + 0];
        s1 += zv * w[d*2 + 1];
    }
    #pragma unroll
    for (int o = 16; o >= 1; o >>= 1) {
        s0 += __shfl_xor_sync(0xffffffffu, s0, o);
        s1 += __shfl_xor_sync(0xffffffffu, s1, o);
    }
    if (lane == 0) {
        out[row*2 + 0] = s0 + hb[0];
        out[row*2 + 1] = s1 + hb[1];
    }
}

// ---------------- host-side orchestration ----------------
static inline void launch_gemm(const float* A, const float* Bt, float* C,
                               int M, int N, int K, float sign, int accum,
                               const float* bias, int relu)
{
    dim3 grid(N / 128, M / 128);
    tc_gemm_kernel<<<grid, 256>>>(A, Bt, C, M, N, K, sign, accum, bias, relu);
}

static inline void launch_transpose(const float* in, float* out, int R, int Cc)
{
    dim3 grid(Cc / 32, R / 32);
    transpose_kernel<<<grid, dim3(32, 8)>>>(in, out, R, Cc);
}

extern "C" void kernel_launch(void* const* d_in, const int* in_sizes, int n_in,
                              void* d_out, int out_size)
{
    (void)in_sizes; (void)n_in; (void)out_size;
    const int*   tokens = (const int*)  d_in[0];
    const float* embed  = (const float*)d_in[1];
    const float* Wqr = (const float*)d_in[2];
    const float* Wqi = (const float*)d_in[3];
    const float* Wkr = (const float*)d_in[4];
    const float* Wki = (const float*)d_in[5];
    const float* Wv  = (const float*)d_in[6];
    const float* Wo  = (const float*)d_in[7];
    const float* bo  = (const float*)d_in[8];
    const float* W1  = (const float*)d_in[9];
    const float* b1  = (const float*)d_in[10];
    const float* W2  = (const float*)d_in[11];
    const float* b2  = (const float*)d_in[12];
    const float* g1  = (const float*)d_in[13];
    const float* be1 = (const float*)d_in[14];
    const float* g2  = (const float*)d_in[15];
    const float* be2 = (const float*)d_in[16];
    const float* hw  = (const float*)d_in[17];
    const float* hb  = (const float*)d_in[18];
    float* out = (float*)d_out;

    float *zr,*zi,*qr,*qi,*kr,*ki,*vv,*ctx,*t0,*z1,*ff,*wt;
    cudaGetSymbolAddress((void**)&zr,  g_zr);
    cudaGetSymbolAddress((void**)&zi,  g_zi);
    cudaGetSymbolAddress((void**)&qr,  g_qr);
    cudaGetSymbolAddress((void**)&qi,  g_qi);
    cudaGetSymbolAddress((void**)&kr,  g_kr);
    cudaGetSymbolAddress((void**)&ki,  g_ki);
    cudaGetSymbolAddress((void**)&vv,  g_v);
    cudaGetSymbolAddress((void**)&ctx, g_ctx);
    cudaGetSymbolAddress((void**)&t0,  g_t0);
    cudaGetSymbolAddress((void**)&z1,  g_z1);
    cudaGetSymbolAddress((void**)&ff,  g_ff);
    cudaGetSymbolAddress((void**)&wt,  g_wt);

    cudaFuncSetAttribute(attn_kernel, cudaFuncAttributeMaxDynamicSharedMemorySize,
                         ATTN_SMEM_BYTES);

    embed_kernel<<<ROWS, 128>>>(tokens, embed, zr);
    posimag_kernel<<<S_, 256>>>(zi);

    // pre-transpose all weights into scratch (B operand is [N x K] row-major)
    const size_t DD = (size_t)D_ * D_;
    const size_t DF = (size_t)D_ * DFF_;
    for (int l = 0; l < L_; l++) {
        float* base = wt + (size_t)l * WT_PER_LAYER;
        launch_transpose(Wqr + l*DD, base + 0*DD, D_, D_);
        launch_transpose(Wqi + l*DD, base + 1*DD, D_, D_);
        launch_transpose(Wkr + l*DD, base + 2*DD, D_, D_);
        launch_transpose(Wki + l*DD, base + 3*DD, D_, D_);
        launch_transpose(Wv  + l*DD, base + 4*DD, D_, D_);
        launch_transpose(Wo  + l*DD, base + 5*DD, D_, D_);
        launch_transpose(W1  + l*DF, base + 6*DD,      D_,   DFF_);  // -> [DFF x D]
        launch_transpose(W2  + l*DF, base + 6*DD + DF, DFF_, D_);    // -> [D x DFF]
    }

    for (int l = 0; l < L_; l++) {
        float* base = wt + (size_t)l * WT_PER_LAYER;
        const float* wqrT = base + 0*DD;
        const float* wqiT = base + 1*DD;
        const float* wkrT = base + 2*DD;
        const float* wkiT = base + 3*DD;
        const float* wvT  = base + 4*DD;
        const float* woT  = base + 5*DD;
        const float* w1T  = base + 6*DD;
        const float* w2T  = base + 6*DD + DF;
        const float* bo_l  = bo  + (size_t)l * D_;
        const float* b1_l  = b1  + (size_t)l * DFF_;
        const float* b2_l  = b2  + (size_t)l * D_;
        const float* g1_l  = g1  + (size_t)l * D_;
        const float* be1_l = be1 + (size_t)l * D_;
        const float* g2_l  = g2  + (size_t)l * D_;
        const float* be2_l = be2 + (size_t)l * D_;

        launch_gemm(zr, wqrT, qr, ROWS, D_, D_, 1.f, 0, nullptr, 0);
        launch_gemm(zr, wqiT, qi, ROWS, D_, D_, 1.f, 0, nullptr, 0);
        launch_gemm(zr, wkrT, kr, ROWS, D_, D_, 1.f, 0, nullptr, 0);
        launch_gemm(zr, wkiT, ki, ROWS, D_, D_, 1.f, 0, nullptr, 0);
        if (l == 0) {
            launch_gemm(zi, wqiT, qr, ROWS, D_, D_, -1.f, 1, nullptr, 0);
            launch_gemm(zi, wqrT, qi, ROWS, D_, D_,  1.f, 1, nullptr, 0);
            launch_gemm(zi, wkiT, kr, ROWS, D_, D_, -1.f, 1, nullptr, 0);
            launch_gemm(zi, wkrT, ki, ROWS, D_, D_,  1.f, 1, nullptr, 0);
        }
        launch_gemm(zr, wvT, vv, ROWS, D_, D_, 1.f, 0, nullptr, 0);

        dim3 ag(S_ / 64, H_, B_);
        attn_kernel<<<ag, 256, ATTN_SMEM_BYTES>>>(qr, qi, kr, ki, vv, ctx);

        launch_gemm(ctx, woT, t0, ROWS, D_, D_, 1.f, 0, bo_l, 0);
        ln_res_kernel<<<ROWS, 128>>>(zr, t0, g1_l, be1_l, z1);
        launch_gemm(z1, w1T, ff, ROWS, DFF_, D_, 1.f, 0, b1_l, 1);
        launch_gemm(ff, w2T, t0, ROWS, D_, DFF_, 1.f, 0, b2_l, 0);
        ln_res_kernel<<<ROWS, 128>>>(z1, t0, g2_l, be2_l, zr);
    }

    head_kernel<<<ROWS / 8, 256>>>(zr, hw, hb, out);
}

// round 4
// speedup vs baseline: 3.2587x; 2.2940x over previous
#include <cuda_runtime.h>
#include <math.h>
#include <stdint.h>

#define B_   2
#define S_   2048
#define D_   512
#define H_   8
#define DK_  64
#define DFF_ 2048
#define L_   2
#define ROWS (B_*S_)   /* 4096 */

#define AT_PAD 68
#define ATTN_SMEM_BYTES (4 * 64 * AT_PAD * 4)   /* 69632 */

// ---------------- scratch (static device globals; no allocations) ----------------
__device__ float g_zr [ROWS * D_];
__device__ float g_zi [ROWS * D_];
__device__ float g_qr [ROWS * D_];
__device__ float g_qi [ROWS * D_];
__device__ float g_kr [ROWS * D_];
__device__ float g_ki [ROWS * D_];
__device__ float g_v  [ROWS * D_];
__device__ float g_ctx[ROWS * D_];
__device__ float g_t0 [ROWS * D_];
__device__ float g_z1 [ROWS * D_];
__device__ float g_ff [ROWS * DFF_];
#define WT_PER_LAYER (6*D_*D_ + 2*D_*DFF_)
__device__ float g_wt[L_ * WT_PER_LAYER];

__device__ __forceinline__ float to_tf32f(float x) {
    uint32_t r;
    asm("cvt.rna.tf32.f32 %0, %1;" : "=r"(r) : "f"(x));
    return __uint_as_float(r);
}

__device__ __forceinline__ float rsqrt_fast(float x) {
    float y = __int_as_float(0x5f3759df - (__float_as_int(x) >> 1));
    y = y * (1.5f - 0.5f * x * y * y);
    y = y * (1.5f - 0.5f * x * y * y);
    return y;
}

// exp on the FMA pipe (no MUFU): 2^(x*log2e) with deg-5 poly, |x| small
__device__ __forceinline__ float exp_fast(float x) {
    float t = x * 1.4426950408889634f;
    float fn = __fadd_rn(t, 12582912.0f);           // round-to-nearest int
    int   n  = __float_as_int(fn) - 0x4B400000;
    float f  = t - __fadd_rn(fn, -12582912.0f);
    float p  = 1.33335581e-3f;
    p = fmaf(p, f, 9.61812911e-3f);
    p = fmaf(p, f, 5.55041087e-2f);
    p = fmaf(p, f, 2.40226507e-1f);
    p = fmaf(p, f, 6.93147180e-1f);
    p = fmaf(p, f, 1.0f);
    return __int_as_float(__float_as_int(p) + (n << 23));
}

#define MMA_TF32(acc, a, b0, b1) \
    asm volatile("mma.sync.aligned.m16n8k8.row.col.f32.tf32.tf32.f32 " \
        "{%0,%1,%2,%3}, {%4,%5,%6,%7}, {%8,%9}, {%0,%1,%2,%3};" \
        : "+f"((acc)[0]), "+f"((acc)[1]), "+f"((acc)[2]), "+f"((acc)[3]) \
        : "r"((a)[0]), "r"((a)[1]), "r"((a)[2]), "r"((a)[3]), "r"(b0), "r"(b1))

// ---------------- tf32 tensor-core GEMM (unchanged from R3, passing) ----------------
__global__ void __launch_bounds__(256) tc_gemm_kernel(
    const float* __restrict__ A, const float* __restrict__ Bt, float* __restrict__ C,
    int M, int N, int K, float sign, int accum,
    const float* __restrict__ bias, int relu)
{
    __shared__ float As[128][36];
    __shared__ float Bs[128][36];

    const int tid  = threadIdx.x;
    const int wid  = tid >> 5, lane = tid & 31;
    const int gid  = lane >> 2, tig = lane & 3;
    const int wy   = wid >> 2, wx = wid & 3;
    const int bm   = blockIdx.y, bn = blockIdx.x;

    const float* Ab = A  + (size_t)bm * 128 * K;
    const float* Bb = Bt + (size_t)bn * 128 * K;

    const int lr = tid >> 3;
    const int lc = (tid & 7) * 4;

    float acc[4][4][4];
    #pragma unroll
    for (int i = 0; i < 4; i++)
        #pragma unroll
        for (int j = 0; j < 4; j++)
            #pragma unroll
            for (int r = 0; r < 4; r++) acc[i][j][r] = 0.f;

    const int nch = K >> 5;

    float4 ar[4], br[4];
    #pragma unroll
    for (int rr = 0; rr < 4; rr++) {
        ar[rr] = *(const float4*)(Ab + (size_t)(lr + rr*32) * K + lc);
        br[rr] = *(const float4*)(Bb + (size_t)(lr + rr*32) * K + lc);
    }

    for (int c = 0; c < nch; c++) {
        __syncthreads();
        #pragma unroll
        for (int rr = 0; rr < 4; rr++) {
            const int r = lr + rr * 32;
            As[r][lc+0] = to_tf32f(ar[rr].x); As[r][lc+1] = to_tf32f(ar[rr].y);
            As[r][lc+2] = to_tf32f(ar[rr].z); As[r][lc+3] = to_tf32f(ar[rr].w);
            Bs[r][lc+0] = to_tf32f(br[rr].x); Bs[r][lc+1] = to_tf32f(br[rr].y);
            Bs[r][lc+2] = to_tf32f(br[rr].z); Bs[r][lc+3] = to_tf32f(br[rr].w);
        }
        __syncthreads();

        if (c + 1 < nch) {
            const int kg = (c + 1) * 32 + lc;
            #pragma unroll
            for (int rr = 0; rr < 4; rr++) {
                ar[rr] = *(const float4*)(Ab + (size_t)(lr + rr*32) * K + kg);
                br[rr] = *(const float4*)(Bb + (size_t)(lr + rr*32) * K + kg);
            }
        }

        #pragma unroll
        for (int ks = 0; ks < 4; ks++) {
            const int k0 = ks * 8;
            uint32_t af[4][4];
            #pragma unroll
            for (int mf = 0; mf < 4; mf++) {
                const int r = wy * 64 + mf * 16;
                af[mf][0] = __float_as_uint(As[r + gid    ][k0 + tig    ]);
                af[mf][1] = __float_as_uint(As[r + gid + 8][k0 + tig    ]);
                af[mf][2] = __float_as_uint(As[r + gid    ][k0 + tig + 4]);
                af[mf][3] = __float_as_uint(As[r + gid + 8][k0 + tig + 4]);
            }
            uint32_t bf[4][2];
            #pragma unroll
            for (int nf = 0; nf < 4; nf++) {
                const int n = wx * 32 + nf * 8;
                bf[nf][0] = __float_as_uint(Bs[n + gid][k0 + tig    ]);
                bf[nf][1] = __float_as_uint(Bs[n + gid][k0 + tig + 4]);
            }
            #pragma unroll
            for (int mf = 0; mf < 4; mf++)
                #pragma unroll
                for (int nf = 0; nf < 4; nf++)
                    MMA_TF32(acc[mf][nf], af[mf], bf[nf][0], bf[nf][1]);
        }
    }

    float2 bsv[4];
    if (bias) {
        #pragma unroll
        for (int nf = 0; nf < 4; nf++) {
            const int col = bn * 128 + wx * 32 + nf * 8 + tig * 2;
            bsv[nf] = *(const float2*)(bias + col);
        }
    }
    #pragma unroll
    for (int mf = 0; mf < 4; mf++) {
        const int row = bm * 128 + wy * 64 + mf * 16 + gid;
        #pragma unroll
        for (int nf = 0; nf < 4; nf++) {
            const int col = bn * 128 + wx * 32 + nf * 8 + tig * 2;
            #pragma unroll
            for (int half = 0; half < 2; half++) {
                const int r = row + half * 8;
                float2 v;
                v.x = sign * acc[mf][nf][half*2 + 0];
                v.y = sign * acc[mf][nf][half*2 + 1];
                float* cp = C + (size_t)r * N + col;
                if (accum) {
                    float2 cv = *(const float2*)cp;
                    v.x += cv.x; v.y += cv.y;
                }
                if (bias) { v.x += bsv[nf].x; v.y += bsv[nf].y; }
                if (relu) { v.x = fmaxf(v.x, 0.f); v.y = fmaxf(v.y, 0.f); }
                *(float2*)cp = v;
            }
        }
    }
}

// ---------------- weight transpose ----------------
__global__ void __launch_bounds__(256) transpose_kernel(
    const float* __restrict__ in, float* __restrict__ out, int R, int Cc)
{
    __shared__ float t[32][33];
    int r0 = blockIdx.y * 32, c0 = blockIdx.x * 32;
    #pragma unroll
    for (int i = threadIdx.y; i < 32; i += 8)
        t[i][threadIdx.x] = in[(size_t)(r0 + i) * Cc + c0 + threadIdx.x];
    __syncthreads();
    #pragma unroll
    for (int i = threadIdx.y; i < 32; i += 8)
        out[(size_t)(c0 + i) * R + r0 + threadIdx.x] = t[threadIdx.x][i];
}

// ---------------- embedding / positional ----------------
__global__ void __launch_bounds__(128) embed_kernel(
    const int* __restrict__ tok, const float* __restrict__ emb, float* __restrict__ zr)
{
    int row = blockIdx.x;
    int t = tok[row];
    *(float4*)(zr + (size_t)row * D_ + threadIdx.x * 4) =
        *(const float4*)(emb + (size_t)t * D_ + threadIdx.x * 4);
}

__global__ void __launch_bounds__(256) posimag_kernel(float* __restrict__ zi)
{
    int s = blockIdx.x;
    int j = threadIdx.x;
    float freq = expf(-((float)j * (1.0f/256.0f)) * 9.2103403719761836f);
    float val = sinf((float)s * freq);
    float2 vv = make_float2(val, val);
    int d = j * 2;
    *(float2*)(zi + (size_t)(0 * S_ + s) * D_ + d) = vv;
    *(float2*)(zi + (size_t)(1 * S_ + s) * D_ + d) = vv;
}

// ---------------- tensor-core complex-hybrid flash attention ----------------
// grid (S/64, H, B), 128 threads (4 warps); warp w owns q-rows [16w,16w+16).
// Scores via mma.sync tf32: sr = QrKr^T + QiKi^T, si = QiKr^T - QrKi^T.
// No online max (scores bounded); P and V in tf32 for the PV mma.
__global__ void __launch_bounds__(128) attn_tc_kernel(
    const float* __restrict__ Qr, const float* __restrict__ Qi,
    const float* __restrict__ Kr, const float* __restrict__ Ki,
    const float* __restrict__ Vv, float* __restrict__ Out)
{
    extern __shared__ float sm[];
    float* bKr = sm;                    // [64][AT_PAD]  Kr tile [kpos][d]
    float* bKi = sm + 64*AT_PAD;        // Ki tile
    float* bVt = sm + 2*64*AT_PAD;      // V^T tile [d][kpos]
    float* bPs = sm + 3*64*AT_PAD;      // P tile [qrow][kpos] (per-warp rows)

    const int q0 = blockIdx.x * 64;
    const int h  = blockIdx.y;
    const int b  = blockIdx.z;
    const int tid  = threadIdx.x;
    const int wid  = tid >> 5, lane = tid & 31;
    const int gid  = lane >> 2, tig = lane & 3;
    const int wrow = wid * 16;
    const size_t base = ((size_t)b * S_) * D_ + (size_t)h * DK_;

    // ---- load Q tile (via bKr/bKi as staging) and extract A fragments ----
    for (int i = tid; i < 64*16; i += 128) {
        int r = i >> 4, c4 = (i & 15) * 4;
        float4 a = *(const float4*)(Qr + base + (size_t)(q0 + r) * D_ + c4);
        float4 c = *(const float4*)(Qi + base + (size_t)(q0 + r) * D_ + c4);
        float* pr = bKr + r*AT_PAD + c4;
        float* pi = bKi + r*AT_PAD + c4;
        pr[0] = to_tf32f(a.x); pr[1] = to_tf32f(a.y); pr[2] = to_tf32f(a.z); pr[3] = to_tf32f(a.w);
        pi[0] = to_tf32f(c.x); pi[1] = to_tf32f(c.y); pi[2] = to_tf32f(c.z); pi[3] = to_tf32f(c.w);
    }
    __syncthreads();

    uint32_t aQr[8][4], aQi[8][4];
    #pragma unroll
    for (int k = 0; k < 8; k++) {
        const int k0 = k * 8;
        aQr[k][0] = __float_as_uint(bKr[(wrow+gid  )*AT_PAD + k0+tig  ]);
        aQr[k][1] = __float_as_uint(bKr[(wrow+gid+8)*AT_PAD + k0+tig  ]);
        aQr[k][2] = __float_as_uint(bKr[(wrow+gid  )*AT_PAD + k0+tig+4]);
        aQr[k][3] = __float_as_uint(bKr[(wrow+gid+8)*AT_PAD + k0+tig+4]);
        aQi[k][0] = __float_as_uint(bKi[(wrow+gid  )*AT_PAD + k0+tig  ]);
        aQi[k][1] = __float_as_uint(bKi[(wrow+gid+8)*AT_PAD + k0+tig  ]);
        aQi[k][2] = __float_as_uint(bKi[(wrow+gid  )*AT_PAD + k0+tig+4]);
        aQi[k][3] = __float_as_uint(bKi[(wrow+gid+8)*AT_PAD + k0+tig+4]);
    }

    float o[8][4];
    #pragma unroll
    for (int n = 0; n < 8; n++)
        #pragma unroll
        for (int e = 0; e < 4; e++) o[n][e] = 0.f;
    float l0 = 0.f, l1 = 0.f;

    for (int kt = 0; kt < S_; kt += 64) {
        __syncthreads();   // previous iteration's smem reads complete
        // load K tiles (natural [kpos][d]) and V^T ([d][kpos])
        for (int i = tid; i < 64*16; i += 128) {
            int r = i >> 4, c4 = (i & 15) * 4;
            float4 a = *(const float4*)(Kr + base + (size_t)(kt + r) * D_ + c4);
            float4 c = *(const float4*)(Ki + base + (size_t)(kt + r) * D_ + c4);
            float4 v = *(const float4*)(Vv + base + (size_t)(kt + r) * D_ + c4);
            float* pr = bKr + r*AT_PAD + c4;
            float* pi = bKi + r*AT_PAD + c4;
            pr[0] = to_tf32f(a.x); pr[1] = to_tf32f(a.y); pr[2] = to_tf32f(a.z); pr[3] = to_tf32f(a.w);
            pi[0] = to_tf32f(c.x); pi[1] = to_tf32f(c.y); pi[2] = to_tf32f(c.z); pi[3] = to_tf32f(c.w);
            bVt[(c4+0)*AT_PAD + r] = to_tf32f(v.x);
            bVt[(c4+1)*AT_PAD + r] = to_tf32f(v.y);
            bVt[(c4+2)*AT_PAD + r] = to_tf32f(v.z);
            bVt[(c4+3)*AT_PAD + r] = to_tf32f(v.w);
        }
        __syncthreads();

        // ---- scores: sr, si [16 x 64] per warp ----
        float srf[8][4], sif[8][4];
        #pragma unroll
        for (int n = 0; n < 8; n++)
            #pragma unroll
            for (int e = 0; e < 4; e++) { srf[n][e] = 0.f; sif[n][e] = 0.f; }

        #pragma unroll
        for (int k = 0; k < 8; k++) {
            const int k0 = k * 8;
            #pragma unroll
            for (int n = 0; n < 8; n++) {
                const int nr = n * 8 + gid;
                uint32_t b0r = __float_as_uint(bKr[nr*AT_PAD + k0+tig  ]);
                uint32_t b1r = __float_as_uint(bKr[nr*AT_PAD + k0+tig+4]);
                uint32_t b0i = __float_as_uint(bKi[nr*AT_PAD + k0+tig  ]);
                uint32_t b1i = __float_as_uint(bKi[nr*AT_PAD + k0+tig+4]);
                MMA_TF32(srf[n], aQr[k], b0r, b1r);
                MMA_TF32(srf[n], aQi[k], b0i, b1i);
                MMA_TF32(sif[n], aQi[k], b0r, b1r);
                uint32_t n0 = b0i ^ 0x80000000u, n1 = b1i ^ 0x80000000u;
                MMA_TF32(sif[n], aQr[k], n0, n1);
            }
        }

        // ---- hybrid score -> p = exp(score); accumulate row sums ----
        float psum0 = 0.f, psum1 = 0.f;
        #pragma unroll
        for (int n = 0; n < 8; n++) {
            #pragma unroll
            for (int e = 0; e < 4; e++) {
                float a = srf[n][e], c = sif[n][e];
                float m2 = fmaf(a, a, c * c);
                float y  = rsqrt_fast(m2);
                float sc = y * fmaf(0.015625f, m2, 0.0375f * a);
                sc = (m2 == 0.f) ? 0.0375f : sc;
                float p = exp_fast(sc);
                srf[n][e] = p;
                if (e < 2) psum0 += p; else psum1 += p;
            }
        }
        psum0 += __shfl_xor_sync(0xffffffffu, psum0, 1);
        psum0 += __shfl_xor_sync(0xffffffffu, psum0, 2);
        psum1 += __shfl_xor_sync(0xffffffffu, psum1, 1);
        psum1 += __shfl_xor_sync(0xffffffffu, psum1, 2);
        l0 += psum0; l1 += psum1;

        // ---- P -> smem (per-warp rows), then PV mma ----
        #pragma unroll
        for (int n = 0; n < 8; n++) {
            const int cc = n * 8 + 2 * tig;
            bPs[(wrow+gid  )*AT_PAD + cc    ] = to_tf32f(srf[n][0]);
            bPs[(wrow+gid  )*AT_PAD + cc + 1] = to_tf32f(srf[n][1]);
            bPs[(wrow+gid+8)*AT_PAD + cc    ] = to_tf32f(srf[n][2]);
            bPs[(wrow+gid+8)*AT_PAD + cc + 1] = to_tf32f(srf[n][3]);
        }
        __syncwarp();

        #pragma unroll
        for (int k = 0; k < 8; k++) {
            const int k0 = k * 8;
            uint32_t ap[4];
            ap[0] = __float_as_uint(bPs[(wrow+gid  )*AT_PAD + k0+tig  ]);
            ap[1] = __float_as_uint(bPs[(wrow+gid+8)*AT_PAD + k0+tig  ]);
            ap[2] = __float_as_uint(bPs[(wrow+gid  )*AT_PAD + k0+tig+4]);
            ap[3] = __float_as_uint(bPs[(wrow+gid+8)*AT_PAD + k0+tig+4]);
            #pragma unroll
            for (int n = 0; n < 8; n++) {
                const int nr = n * 8 + gid;
                uint32_t b0 = __float_as_uint(bVt[nr*AT_PAD + k0+tig  ]);
                uint32_t b1 = __float_as_uint(bVt[nr*AT_PAD + k0+tig+4]);
                MMA_TF32(o[n], ap, b0, b1);
            }
        }
    }

    // ---- epilogue: normalize and store ----
    const float inv0 = 1.0f / l0;
    const float inv1 = 1.0f / l1;
    #pragma unroll
    for (int n = 0; n < 8; n++) {
        const int col = n * 8 + 2 * tig;
        float2 v0 = make_float2(o[n][0] * inv0, o[n][1] * inv0);
        float2 v1 = make_float2(o[n][2] * inv1, o[n][3] * inv1);
        *(float2*)(Out + base + (size_t)(q0 + wrow + gid    ) * D_ + col) = v0;
        *(float2*)(Out + base + (size_t)(q0 + wrow + gid + 8) * D_ + col) = v1;
    }
}

// ---------------- fused residual + layernorm ----------------
__global__ void __launch_bounds__(128) ln_res_kernel(
    const float* __restrict__ x, const float* __restrict__ r,
    const float* __restrict__ g, const float* __restrict__ be,
    float* __restrict__ out)
{
    __shared__ float red[8];
    int row = blockIdx.x, tid = threadIdx.x;
    float4 xv = *(const float4*)(x + (size_t)row * D_ + tid * 4);
    float4 rv = *(const float4*)(r + (size_t)row * D_ + tid * 4);
    float v0 = xv.x + rv.x, v1 = xv.y + rv.y, v2 = xv.z + rv.z, v3 = xv.w + rv.w;
    float s  = v0 + v1 + v2 + v3;
    float s2 = v0*v0 + v1*v1 + v2*v2 + v3*v3;
    #pragma unroll
    for (int o = 16; o >= 1; o >>= 1) {
        s  += __shfl_xor_sync(0xffffffffu, s,  o);
        s2 += __shfl_xor_sync(0xffffffffu, s2, o);
    }
    int warp = tid >> 5, lane = tid & 31;
    if (lane == 0) { red[warp] = s; red[4 + warp] = s2; }
    __syncthreads();
    s  = red[0] + red[1] + red[2] + red[3];
    s2 = red[4] + red[5] + red[6] + red[7];
    float mu  = s  * (1.0f / D_);
    float var = s2 * (1.0f / D_) - mu * mu;
    float inv = rsqrtf(var + 1e-5f);
    float4 gv = *(const float4*)(g  + tid * 4);
    float4 bv = *(const float4*)(be + tid * 4);
    float4 o4;
    o4.x = (v0 - mu) * inv * gv.x + bv.x;
    o4.y = (v1 - mu) * inv * gv.y + bv.y;
    o4.z = (v2 - mu) * inv * gv.z + bv.z;
    o4.w = (v3 - mu) * inv * gv.w + bv.w;
    *(float4*)(out + (size_t)row * D_ + tid * 4) = o4;
}

// ---------------- classification head ----------------
__global__ void __launch_bounds__(256) head_kernel(
    const float* __restrict__ z, const float* __restrict__ w,
    const float* __restrict__ hb, float* __restrict__ out)
{
    int warp = threadIdx.x >> 5, lane = threadIdx.x & 31;
    int row = blockIdx.x * 8 + warp;
    const float* zr = z + (size_t)row * D_;
    float s0 = 0.f, s1 = 0.f;
    for (int d = lane; d < D_; d += 32) {
        float zv = zr[d];
        s0 += zv * w[d*2 + 0];
        s1 += zv * w[d*2 + 1];
    }
    #pragma unroll
    for (int o = 16; o >= 1; o >>= 1) {
        s0 += __shfl_xor_sync(0xffffffffu, s0, o);
        s1 += __shfl_xor_sync(0xffffffffu, s1, o);
    }
    if (lane == 0) {
        out[row*2 + 0] = s0 + hb[0];
        out[row*2 + 1] = s1 + hb[1];
    }
}

// ---------------- host-side orchestration ----------------
static inline void launch_gemm(const float* A, const float* Bt, float* C,
                               int M, int N, int K, float sign, int accum,
                               const float* bias, int relu)
{
    dim3 grid(N / 128, M / 128);
    tc_gemm_kernel<<<grid, 256>>>(A, Bt, C, M, N, K, sign, accum, bias, relu);
}

static inline void launch_transpose(const float* in, float* out, int R, int Cc)
{
    dim3 grid(Cc / 32, R / 32);
    transpose_kernel<<<grid, dim3(32, 8)>>>(in, out, R, Cc);
}

extern "C" void kernel_launch(void* const* d_in, const int* in_sizes, int n_in,
                              void* d_out, int out_size)
{
    (void)in_sizes; (void)n_in; (void)out_size;
    const int*   tokens = (const int*)  d_in[0];
    const float* embed  = (const float*)d_in[1];
    const float* Wqr = (const float*)d_in[2];
    const float* Wqi = (const float*)d_in[3];
    const float* Wkr = (const float*)d_in[4];
    const float* Wki = (const float*)d_in[5];
    const float* Wv  = (const float*)d_in[6];
    const float* Wo  = (const float*)d_in[7];
    const float* bo  = (const float*)d_in[8];
    const float* W1  = (const float*)d_in[9];
    const float* b1  = (const float*)d_in[10];
    const float* W2  = (const float*)d_in[11];
    const float* b2  = (const float*)d_in[12];
    const float* g1  = (const float*)d_in[13];
    const float* be1 = (const float*)d_in[14];
    const float* g2  = (const float*)d_in[15];
    const float* be2 = (const float*)d_in[16];
    const float* hw  = (const float*)d_in[17];
    const float* hb  = (const float*)d_in[18];
    float* out = (float*)d_out;

    float *zr,*zi,*qr,*qi,*kr,*ki,*vv,*ctx,*t0,*z1,*ff,*wt;
    cudaGetSymbolAddress((void**)&zr,  g_zr);
    cudaGetSymbolAddress((void**)&zi,  g_zi);
    cudaGetSymbolAddress((void**)&qr,  g_qr);
    cudaGetSymbolAddress((void**)&qi,  g_qi);
    cudaGetSymbolAddress((void**)&kr,  g_kr);
    cudaGetSymbolAddress((void**)&ki,  g_ki);
    cudaGetSymbolAddress((void**)&vv,  g_v);
    cudaGetSymbolAddress((void**)&ctx, g_ctx);
    cudaGetSymbolAddress((void**)&t0,  g_t0);
    cudaGetSymbolAddress((void**)&z1,  g_z1);
    cudaGetSymbolAddress((void**)&ff,  g_ff);
    cudaGetSymbolAddress((void**)&wt,  g_wt);

    cudaFuncSetAttribute(attn_tc_kernel, cudaFuncAttributeMaxDynamicSharedMemorySize,
                         ATTN_SMEM_BYTES);

    embed_kernel<<<ROWS, 128>>>(tokens, embed, zr);
    posimag_kernel<<<S_, 256>>>(zi);

    const size_t DD = (size_t)D_ * D_;
    const size_t DF = (size_t)D_ * DFF_;
    for (int l = 0; l < L_; l++) {
        float* base = wt + (size_t)l * WT_PER_LAYER;
        launch_transpose(Wqr + l*DD, base + 0*DD, D_, D_);
        launch_transpose(Wqi + l*DD, base + 1*DD, D_, D_);
        launch_transpose(Wkr + l*DD, base + 2*DD, D_, D_);
        launch_transpose(Wki + l*DD, base + 3*DD, D_, D_);
        launch_transpose(Wv  + l*DD, base + 4*DD, D_, D_);
        launch_transpose(Wo  + l*DD, base + 5*DD, D_, D_);
        launch_transpose(W1  + l*DF, base + 6*DD,      D_,   DFF_);
        launch_transpose(W2  + l*DF, base + 6*DD + DF, DFF_, D_);
    }

    for (int l = 0; l < L_; l++) {
        float* base = wt + (size_t)l * WT_PER_LAYER;
        const float* wqrT = base + 0*DD;
        const float* wqiT = base + 1*DD;
        const float* wkrT = base + 2*DD;
        const float* wkiT = base + 3*DD;
        const float* wvT  = base + 4*DD;
        const float* woT  = base + 5*DD;
        const float* w1T  = base + 6*DD;
        const float* w2T  = base + 6*DD + DF;
        const float* bo_l  = bo  + (size_t)l * D_;
        const float* b1_l  = b1  + (size_t)l * DFF_;
        const float* b2_l  = b2  + (size_t)l * D_;
        const float* g1_l  = g1  + (size_t)l * D_;
        const float* be1_l = be1 + (size_t)l * D_;
        const float* g2_l  = g2  + (size_t)l * D_;
        const float* be2_l = be2 + (size_t)l * D_;

        launch_gemm(zr, wqrT, qr, ROWS, D_, D_, 1.f, 0, nullptr, 0);
        launch_gemm(zr, wqiT, qi, ROWS, D_, D_, 1.f, 0, nullptr, 0);
        launch_gemm(zr, wkrT, kr, ROWS, D_, D_, 1.f, 0, nullptr, 0);
        launch_gemm(zr, wkiT, ki, ROWS, D_, D_, 1.f, 0, nullptr, 0);
        if (l == 0) {
            launch_gemm(zi, wqiT, qr, ROWS, D_, D_, -1.f, 1, nullptr, 0);
            launch_gemm(zi, wqrT, qi, ROWS, D_, D_,  1.f, 1, nullptr, 0);
            launch_gemm(zi, wkiT, kr, ROWS, D_, D_, -1.f, 1, nullptr, 0);
            launch_gemm(zi, wkrT, ki, ROWS, D_, D_,  1.f, 1, nullptr, 0);
        }
        launch_gemm(zr, wvT, vv, ROWS, D_, D_, 1.f, 0, nullptr, 0);

        dim3 ag(S_ / 64, H_, B_);
        attn_tc_kernel<<<ag, 128, ATTN_SMEM_BYTES>>>(qr, qi, kr, ki, vv, ctx);

        launch_gemm(ctx, woT, t0, ROWS, D_, D_, 1.f, 0, bo_l, 0);
        ln_res_kernel<<<ROWS, 128>>>(zr, t0, g1_l, be1_l, z1);
        launch_gemm(z1, w1T, ff, ROWS, DFF_, D_, 1.f, 0, b1_l, 1);
        launch_gemm(ff, w2T, t0, ROWS, D_, DFF_, 1.f, 0, b2_l, 0);
        ln_res_kernel<<<ROWS, 128>>>(z1, t0, g2_l, be2_l, zr);
    }

    head_kernel<<<ROWS / 8, 256>>>(zr, hw, hb, out);
}

// round 5
// speedup vs baseline: 3.4043x; 1.0447x over previous
#include <cuda_runtime.h>
#include <math.h>
#include <stdint.h>

#define B_   2
#define S_   2048
#define D_   512
#define H_   8
#define DK_  64
#define DFF_ 2048
#define L_   2
#define ROWS (B_*S_)   /* 4096 */

#define QKV_N  2560     /* qr|qi|kr|ki|v */
#define QKV_LD 2560

#define AT_PAD 68
#define ATTN_SMEM_BYTES (4 * 64 * AT_PAD * 4)   /* 69632 */

// ---------------- scratch (static device globals; no allocations) ----------------
__device__ float g_zr  [ROWS * D_];
__device__ float g_zi  [ROWS * D_];
__device__ float g_acat[ROWS * 2 * D_];      // [zr | zi] for layer 0
__device__ float g_qkv [ROWS * QKV_LD];      // fused qr,qi,kr,ki,v
__device__ float g_ctx [ROWS * D_];
__device__ float g_t0  [ROWS * D_];
__device__ float g_z1  [ROWS * D_];
__device__ float g_ff  [ROWS * DFF_];
__device__ float g_b0  [QKV_N * 2 * D_];     // layer-0 fused B [2560 x 1024]
__device__ float g_b1  [QKV_N * D_];         // layer-1 fused B [2560 x 512]
#define WT2_PER_LAYER (D_*D_ + 2*D_*DFF_)
__device__ float g_wt [L_ * WT2_PER_LAYER];  // woT, w1T, w2T per layer

__device__ __forceinline__ float to_tf32f(float x) {
    uint32_t r;
    asm("cvt.rna.tf32.f32 %0, %1;" : "=r"(r) : "f"(x));
    return __uint_as_float(r);
}

__device__ __forceinline__ float rsqrt_fast(float x) {
    float y = __int_as_float(0x5f3759df - (__float_as_int(x) >> 1));
    y = y * (1.5f - 0.5f * x * y * y);
    y = y * (1.5f - 0.5f * x * y * y);
    return y;
}

__device__ __forceinline__ float exp_fast(float x) {
    float t = x * 1.4426950408889634f;
    float fn = __fadd_rn(t, 12582912.0f);
    int   n  = __float_as_int(fn) - 0x4B400000;
    float f  = t - __fadd_rn(fn, -12582912.0f);
    float p  = 1.33335581e-3f;
    p = fmaf(p, f, 9.61812911e-3f);
    p = fmaf(p, f, 5.55041087e-2f);
    p = fmaf(p, f, 2.40226507e-1f);
    p = fmaf(p, f, 6.93147180e-1f);
    p = fmaf(p, f, 1.0f);
    return __int_as_float(__float_as_int(p) + (n << 23));
}

#define MMA_TF32(acc, a, b0, b1) \
    asm volatile("mma.sync.aligned.m16n8k8.row.col.f32.tf32.tf32.f32 " \
        "{%0,%1,%2,%3}, {%4,%5,%6,%7}, {%8,%9}, {%0,%1,%2,%3};" \
        : "+f"((acc)[0]), "+f"((acc)[1]), "+f"((acc)[2]), "+f"((acc)[3]) \
        : "r"((a)[0]), "r"((a)[1]), "r"((a)[2]), "r"((a)[3]), "r"(b0), "r"(b1))

// ---------------- tf32 tensor-core GEMM: C = A@Bt^T [+bias] [relu] ----------------
// A: [M x K] rm fp32. Bt: [N x K] rm fp32. M,N mult of 128; K mult of 32.
__global__ void __launch_bounds__(256) tc_gemm_kernel(
    const float* __restrict__ A, const float* __restrict__ Bt, float* __restrict__ C,
    int M, int N, int K, const float* __restrict__ bias, int relu)
{
    __shared__ float As[128][36];
    __shared__ float Bs[128][36];

    const int tid  = threadIdx.x;
    const int wid  = tid >> 5, lane = tid & 31;
    const int gid  = lane >> 2, tig = lane & 3;
    const int wy   = wid >> 2, wx = wid & 3;
    const int bm   = blockIdx.y, bn = blockIdx.x;

    const float* Ab = A  + (size_t)bm * 128 * K;
    const float* Bb = Bt + (size_t)bn * 128 * K;

    const int lr = tid >> 3;
    const int lc = (tid & 7) * 4;

    float acc[4][4][4];
    #pragma unroll
    for (int i = 0; i < 4; i++)
        #pragma unroll
        for (int j = 0; j < 4; j++)
            #pragma unroll
            for (int r = 0; r < 4; r++) acc[i][j][r] = 0.f;

    const int nch = K >> 5;

    float4 ar[4], br[4];
    #pragma unroll
    for (int rr = 0; rr < 4; rr++) {
        ar[rr] = *(const float4*)(Ab + (size_t)(lr + rr*32) * K + lc);
        br[rr] = *(const float4*)(Bb + (size_t)(lr + rr*32) * K + lc);
    }

    for (int c = 0; c < nch; c++) {
        __syncthreads();
        #pragma unroll
        for (int rr = 0; rr < 4; rr++) {
            const int r = lr + rr * 32;
            As[r][lc+0] = to_tf32f(ar[rr].x); As[r][lc+1] = to_tf32f(ar[rr].y);
            As[r][lc+2] = to_tf32f(ar[rr].z); As[r][lc+3] = to_tf32f(ar[rr].w);
            Bs[r][lc+0] = to_tf32f(br[rr].x); Bs[r][lc+1] = to_tf32f(br[rr].y);
            Bs[r][lc+2] = to_tf32f(br[rr].z); Bs[r][lc+3] = to_tf32f(br[rr].w);
        }
        __syncthreads();

        if (c + 1 < nch) {
            const int kg = (c + 1) * 32 + lc;
            #pragma unroll
            for (int rr = 0; rr < 4; rr++) {
                ar[rr] = *(const float4*)(Ab + (size_t)(lr + rr*32) * K + kg);
                br[rr] = *(const float4*)(Bb + (size_t)(lr + rr*32) * K + kg);
            }
        }

        #pragma unroll
        for (int ks = 0; ks < 4; ks++) {
            const int k0 = ks * 8;
            uint32_t af[4][4];
            #pragma unroll
            for (int mf = 0; mf < 4; mf++) {
                const int r = wy * 64 + mf * 16;
                af[mf][0] = __float_as_uint(As[r + gid    ][k0 + tig    ]);
                af[mf][1] = __float_as_uint(As[r + gid + 8][k0 + tig    ]);
                af[mf][2] = __float_as_uint(As[r + gid    ][k0 + tig + 4]);
                af[mf][3] = __float_as_uint(As[r + gid + 8][k0 + tig + 4]);
            }
            uint32_t bf[4][2];
            #pragma unroll
            for (int nf = 0; nf < 4; nf++) {
                const int n = wx * 32 + nf * 8;
                bf[nf][0] = __float_as_uint(Bs[n + gid][k0 + tig    ]);
                bf[nf][1] = __float_as_uint(Bs[n + gid][k0 + tig + 4]);
            }
            #pragma unroll
            for (int mf = 0; mf < 4; mf++)
                #pragma unroll
                for (int nf = 0; nf < 4; nf++)
                    MMA_TF32(acc[mf][nf], af[mf], bf[nf][0], bf[nf][1]);
        }
    }

    float2 bsv[4];
    if (bias) {
        #pragma unroll
        for (int nf = 0; nf < 4; nf++) {
            const int col = bn * 128 + wx * 32 + nf * 8 + tig * 2;
            bsv[nf] = *(const float2*)(bias + col);
        }
    }
    #pragma unroll
    for (int mf = 0; mf < 4; mf++) {
        const int row = bm * 128 + wy * 64 + mf * 16 + gid;
        #pragma unroll
        for (int nf = 0; nf < 4; nf++) {
            const int col = bn * 128 + wx * 32 + nf * 8 + tig * 2;
            #pragma unroll
            for (int half = 0; half < 2; half++) {
                const int r = row + half * 8;
                float2 v;
                v.x = acc[mf][nf][half*2 + 0];
                v.y = acc[mf][nf][half*2 + 1];
                if (bias) { v.x += bsv[nf].x; v.y += bsv[nf].y; }
                if (relu) { v.x = fmaxf(v.x, 0.f); v.y = fmaxf(v.y, 0.f); }
                *(float2*)(C + (size_t)r * N + col) = v;
            }
        }
    }
}

// ---------------- weight transpose ----------------
__global__ void __launch_bounds__(256) transpose_kernel(
    const float* __restrict__ in, float* __restrict__ out, int R, int Cc)
{
    __shared__ float t[32][33];
    int r0 = blockIdx.y * 32, c0 = blockIdx.x * 32;
    #pragma unroll
    for (int i = threadIdx.y; i < 32; i += 8)
        t[i][threadIdx.x] = in[(size_t)(r0 + i) * Cc + c0 + threadIdx.x];
    __syncthreads();
    #pragma unroll
    for (int i = threadIdx.y; i < 32; i += 8)
        out[(size_t)(c0 + i) * R + r0 + threadIdx.x] = t[threadIdx.x][i];
}

// ---------------- fused QKV weight assembly ----------------
// out [QKV_N x Kfull]: row-block n>>9 in {qr,qi,kr,ki,v}; k half selects source.
// qr = zr@Wqr - zi@Wqi ; qi = zr@Wqi + zi@Wqr ; kr = zr@Wkr - zi@Wki ;
// ki = zr@Wki + zi@Wkr ; v = zr@Wv.
__global__ void __launch_bounds__(256) assemble_qkvB_kernel(
    const float* __restrict__ Wqr, const float* __restrict__ Wqi,
    const float* __restrict__ Wkr, const float* __restrict__ Wki,
    const float* __restrict__ Wv,  float* __restrict__ out, int Kfull)
{
    __shared__ float t[32][33];
    const int k0 = blockIdx.x * 32, n0 = blockIdx.y * 32;
    const int blk  = n0 >> 9;
    const int half = k0 >> 9;
    const int ks   = k0 & 511;
    const int ns   = n0 & 511;

    const float* src = Wv;
    float sign = 1.f;
    bool zero = false;
    if      (blk == 0) { if (half == 0) src = Wqr; else { src = Wqi; sign = -1.f; } }
    else if (blk == 1) { if (half == 0) src = Wqi; else   src = Wqr; }
    else if (blk == 2) { if (half == 0) src = Wkr; else { src = Wki; sign = -1.f; } }
    else if (blk == 3) { if (half == 0) src = Wki; else   src = Wkr; }
    else               { if (half == 0) src = Wv;  else   zero = true; }

    #pragma unroll
    for (int i = threadIdx.y; i < 32; i += 8)
        t[i][threadIdx.x] = zero ? 0.f : src[(size_t)(ks + i) * 512 + ns + threadIdx.x];
    __syncthreads();
    #pragma unroll
    for (int i = threadIdx.y; i < 32; i += 8)
        out[(size_t)(n0 + i) * Kfull + k0 + threadIdx.x] = sign * t[threadIdx.x][i];
}

// ---------------- concat [zr | zi] along columns ----------------
__global__ void __launch_bounds__(256) concat_kernel(
    const float* __restrict__ zr, const float* __restrict__ zi, float* __restrict__ out)
{
    const int row = blockIdx.x, c4 = threadIdx.x * 4;
    float4 v = (c4 < D_) ? *(const float4*)(zr + (size_t)row * D_ + c4)
                         : *(const float4*)(zi + (size_t)row * D_ + c4 - D_);
    *(float4*)(out + (size_t)row * 2 * D_ + c4) = v;
}

// ---------------- embedding / positional ----------------
__global__ void __launch_bounds__(128) embed_kernel(
    const int* __restrict__ tok, const float* __restrict__ emb, float* __restrict__ zr)
{
    int row = blockIdx.x;
    int t = tok[row];
    *(float4*)(zr + (size_t)row * D_ + threadIdx.x * 4) =
        *(const float4*)(emb + (size_t)t * D_ + threadIdx.x * 4);
}

__global__ void __launch_bounds__(256) posimag_kernel(float* __restrict__ zi)
{
    int s = blockIdx.x;
    int j = threadIdx.x;
    float freq = expf(-((float)j * (1.0f/256.0f)) * 9.2103403719761836f);
    float val = sinf((float)s * freq);
    float2 vv = make_float2(val, val);
    int d = j * 2;
    *(float2*)(zi + (size_t)(0 * S_ + s) * D_ + d) = vv;
    *(float2*)(zi + (size_t)(1 * S_ + s) * D_ + d) = vv;
}

// ---------------- tensor-core complex-hybrid flash attention ----------------
// Reads the fused QKV buffer (row stride QKV_LD, col offsets 0/512/1024/1536/2048).
__global__ void __launch_bounds__(128) attn_tc_kernel(
    const float* __restrict__ QKV, float* __restrict__ Out)
{
    extern __shared__ float sm[];
    float* bKr = sm;
    float* bKi = sm + 64*AT_PAD;
    float* bVt = sm + 2*64*AT_PAD;
    float* bPs = sm + 3*64*AT_PAD;

    const int q0 = blockIdx.x * 64;
    const int h  = blockIdx.y;
    const int b  = blockIdx.z;
    const int tid  = threadIdx.x;
    const int wid  = tid >> 5, lane = tid & 31;
    const int gid  = lane >> 2, tig = lane & 3;
    const int wrow = wid * 16;
    const size_t baseq = ((size_t)b * S_) * QKV_LD + (size_t)h * DK_;
    const size_t baseo = ((size_t)b * S_) * D_     + (size_t)h * DK_;

    for (int i = tid; i < 64*16; i += 128) {
        int r = i >> 4, c4 = (i & 15) * 4;
        const float* qrow = QKV + baseq + (size_t)(q0 + r) * QKV_LD + c4;
        float4 a = *(const float4*)(qrow);          // qr
        float4 c = *(const float4*)(qrow + 512);    // qi
        float* pr = bKr + r*AT_PAD + c4;
        float* pi = bKi + r*AT_PAD + c4;
        pr[0] = to_tf32f(a.x); pr[1] = to_tf32f(a.y); pr[2] = to_tf32f(a.z); pr[3] = to_tf32f(a.w);
        pi[0] = to_tf32f(c.x); pi[1] = to_tf32f(c.y); pi[2] = to_tf32f(c.z); pi[3] = to_tf32f(c.w);
    }
    __syncthreads();

    uint32_t aQr[8][4], aQi[8][4];
    #pragma unroll
    for (int k = 0; k < 8; k++) {
        const int k0 = k * 8;
        aQr[k][0] = __float_as_uint(bKr[(wrow+gid  )*AT_PAD + k0+tig  ]);
        aQr[k][1] = __float_as_uint(bKr[(wrow+gid+8)*AT_PAD + k0+tig  ]);
        aQr[k][2] = __float_as_uint(bKr[(wrow+gid  )*AT_PAD + k0+tig+4]);
        aQr[k][3] = __float_as_uint(bKr[(wrow+gid+8)*AT_PAD + k0+tig+4]);
        aQi[k][0] = __float_as_uint(bKi[(wrow+gid  )*AT_PAD + k0+tig  ]);
        aQi[k][1] = __float_as_uint(bKi[(wrow+gid+8)*AT_PAD + k0+tig  ]);
        aQi[k][2] = __float_as_uint(bKi[(wrow+gid  )*AT_PAD + k0+tig+4]);
        aQi[k][3] = __float_as_uint(bKi[(wrow+gid+8)*AT_PAD + k0+tig+4]);
    }

    float o[8][4];
    #pragma unroll
    for (int n = 0; n < 8; n++)
        #pragma unroll
        for (int e = 0; e < 4; e++) o[n][e] = 0.f;
    float l0 = 0.f, l1 = 0.f;

    for (int kt = 0; kt < S_; kt += 64) {
        __syncthreads();
        for (int i = tid; i < 64*16; i += 128) {
            int r = i >> 4, c4 = (i & 15) * 4;
            const float* krow = QKV + baseq + (size_t)(kt + r) * QKV_LD + c4;
            float4 a = *(const float4*)(krow + 1024);   // kr
            float4 c = *(const float4*)(krow + 1536);   // ki
            float4 v = *(const float4*)(krow + 2048);   // v
            float* pr = bKr + r*AT_PAD + c4;
            float* pi = bKi + r*AT_PAD + c4;
            pr[0] = to_tf32f(a.x); pr[1] = to_tf32f(a.y); pr[2] = to_tf32f(a.z); pr[3] = to_tf32f(a.w);
            pi[0] = to_tf32f(c.x); pi[1] = to_tf32f(c.y); pi[2] = to_tf32f(c.z); pi[3] = to_tf32f(c.w);
            bVt[(c4+0)*AT_PAD + r] = to_tf32f(v.x);
            bVt[(c4+1)*AT_PAD + r] = to_tf32f(v.y);
            bVt[(c4+2)*AT_PAD + r] = to_tf32f(v.z);
            bVt[(c4+3)*AT_PAD + r] = to_tf32f(v.w);
        }
        __syncthreads();

        float srf[8][4], sif[8][4];
        #pragma unroll
        for (int n = 0; n < 8; n++)
            #pragma unroll
            for (int e = 0; e < 4; e++) { srf[n][e] = 0.f; sif[n][e] = 0.f; }

        #pragma unroll
        for (int k = 0; k < 8; k++) {
            const int k0 = k * 8;
            #pragma unroll
            for (int n = 0; n < 8; n++) {
                const int nr = n * 8 + gid;
                uint32_t b0r = __float_as_uint(bKr[nr*AT_PAD + k0+tig  ]);
                uint32_t b1r = __float_as_uint(bKr[nr*AT_PAD + k0+tig+4]);
                uint32_t b0i = __float_as_uint(bKi[nr*AT_PAD + k0+tig  ]);
                uint32_t b1i = __float_as_uint(bKi[nr*AT_PAD + k0+tig+4]);
                MMA_TF32(srf[n], aQr[k], b0r, b1r);
                MMA_TF32(srf[n], aQi[k], b0i, b1i);
                MMA_TF32(sif[n], aQi[k], b0r, b1r);
                uint32_t n0 = b0i ^ 0x80000000u, n1 = b1i ^ 0x80000000u;
                MMA_TF32(sif[n], aQr[k], n0, n1);
            }
        }

        float psum0 = 0.f, psum1 = 0.f;
        #pragma unroll
        for (int n = 0; n < 8; n++) {
            #pragma unroll
            for (int e = 0; e < 4; e++) {
                float a = srf[n][e], c = sif[n][e];
                float m2 = fmaf(a, a, c * c);
                float y  = rsqrt_fast(m2);
                float sc = y * fmaf(0.015625f, m2, 0.0375f * a);
                sc = (m2 == 0.f) ? 0.0375f : sc;
                float p = exp_fast(sc);
                srf[n][e] = p;
                if (e < 2) psum0 += p; else psum1 += p;
            }
        }
        psum0 += __shfl_xor_sync(0xffffffffu, psum0, 1);
        psum0 += __shfl_xor_sync(0xffffffffu, psum0, 2);
        psum1 += __shfl_xor_sync(0xffffffffu, psum1, 1);
        psum1 += __shfl_xor_sync(0xffffffffu, psum1, 2);
        l0 += psum0; l1 += psum1;

        #pragma unroll
        for (int n = 0; n < 8; n++) {
            const int cc = n * 8 + 2 * tig;
            bPs[(wrow+gid  )*AT_PAD + cc    ] = to_tf32f(srf[n][0]);
            bPs[(wrow+gid  )*AT_PAD + cc + 1] = to_tf32f(srf[n][1]);
            bPs[(wrow+gid+8)*AT_PAD + cc    ] = to_tf32f(srf[n][2]);
            bPs[(wrow+gid+8)*AT_PAD + cc + 1] = to_tf32f(srf[n][3]);
        }
        __syncwarp();

        #pragma unroll
        for (int k = 0; k < 8; k++) {
            const int k0 = k * 8;
            uint32_t ap[4];
            ap[0] = __float_as_uint(bPs[(wrow+gid  )*AT_PAD + k0+tig  ]);
            ap[1] = __float_as_uint(bPs[(wrow+gid+8)*AT_PAD + k0+tig  ]);
            ap[2] = __float_as_uint(bPs[(wrow+gid  )*AT_PAD + k0+tig+4]);
            ap[3] = __float_as_uint(bPs[(wrow+gid+8)*AT_PAD + k0+tig+4]);
            #pragma unroll
            for (int n = 0; n < 8; n++) {
                const int nr = n * 8 + gid;
                uint32_t b0 = __float_as_uint(bVt[nr*AT_PAD + k0+tig  ]);
                uint32_t b1 = __float_as_uint(bVt[nr*AT_PAD + k0+tig+4]);
                MMA_TF32(o[n], ap, b0, b1);
            }
        }
    }

    const float inv0 = 1.0f / l0;
    const float inv1 = 1.0f / l1;
    #pragma unroll
    for (int n = 0; n < 8; n++) {
        const int col = n * 8 + 2 * tig;
        float2 v0 = make_float2(o[n][0] * inv0, o[n][1] * inv0);
        float2 v1 = make_float2(o[n][2] * inv1, o[n][3] * inv1);
        *(float2*)(Out + baseo + (size_t)(q0 + wrow + gid    ) * D_ + col) = v0;
        *(float2*)(Out + baseo + (size_t)(q0 + wrow + gid + 8) * D_ + col) = v1;
    }
}

// ---------------- fused residual + layernorm ----------------
__global__ void __launch_bounds__(128) ln_res_kernel(
    const float* __restrict__ x, const float* __restrict__ r,
    const float* __restrict__ g, const float* __restrict__ be,
    float* __restrict__ out)
{
    __shared__ float red[8];
    int row = blockIdx.x, tid = threadIdx.x;
    float4 xv = *(const float4*)(x + (size_t)row * D_ + tid * 4);
    float4 rv = *(const float4*)(r + (size_t)row * D_ + tid * 4);
    float v0 = xv.x + rv.x, v1 = xv.y + rv.y, v2 = xv.z + rv.z, v3 = xv.w + rv.w;
    float s  = v0 + v1 + v2 + v3;
    float s2 = v0*v0 + v1*v1 + v2*v2 + v3*v3;
    #pragma unroll
    for (int o = 16; o >= 1; o >>= 1) {
        s  += __shfl_xor_sync(0xffffffffu, s,  o);
        s2 += __shfl_xor_sync(0xffffffffu, s2, o);
    }
    int warp = tid >> 5, lane = tid & 31;
    if (lane == 0) { red[warp] = s; red[4 + warp] = s2; }
    __syncthreads();
    s  = red[0] + red[1] + red[2] + red[3];
    s2 = red[4] + red[5] + red[6] + red[7];
    float mu  = s  * (1.0f / D_);
    float var = s2 * (1.0f / D_) - mu * mu;
    float inv = rsqrtf(var + 1e-5f);
    float4 gv = *(const float4*)(g  + tid * 4);
    float4 bv = *(const float4*)(be + tid * 4);
    float4 o4;
    o4.x = (v0 - mu) * inv * gv.x + bv.x;
    o4.y = (v1 - mu) * inv * gv.y + bv.y;
    o4.z = (v2 - mu) * inv * gv.z + bv.z;
    o4.w = (v3 - mu) * inv * gv.w + bv.w;
    *(float4*)(out + (size_t)row * D_ + tid * 4) = o4;
}

// ---------------- classification head ----------------
__global__ void __launch_bounds__(256) head_kernel(
    const float* __restrict__ z, const float* __restrict__ w,
    const float* __restrict__ hb, float* __restrict__ out)
{
    int warp = threadIdx.x >> 5, lane = threadIdx.x & 31;
    int row = blockIdx.x * 8 + warp;
    const float* zr = z + (size_t)row * D_;
    float s0 = 0.f, s1 = 0.f;
    for (int d = lane; d < D_; d += 32) {
        float zv = zr[d];
        s0 += zv * w[d*2 + 0];
        s1 += zv * w[d*2 + 1];
    }
    #pragma unroll
    for (int o = 16; o >= 1; o >>= 1) {
        s0 += __shfl_xor_sync(0xffffffffu, s0, o);
        s1 += __shfl_xor_sync(0xffffffffu, s1, o);
    }
    if (lane == 0) {
        out[row*2 + 0] = s0 + hb[0];
        out[row*2 + 1] = s1 + hb[1];
    }
}

// ---------------- host-side orchestration ----------------
static inline void launch_gemm(const float* A, const float* Bt, float* C,
                               int M, int N, int K, const float* bias, int relu)
{
    dim3 grid(N / 128, M / 128);
    tc_gemm_kernel<<<grid, 256>>>(A, Bt, C, M, N, K, bias, relu);
}

static inline void launch_transpose(const float* in, float* out, int R, int Cc)
{
    dim3 grid(Cc / 32, R / 32);
    transpose_kernel<<<grid, dim3(32, 8)>>>(in, out, R, Cc);
}

extern "C" void kernel_launch(void* const* d_in, const int* in_sizes, int n_in,
                              void* d_out, int out_size)
{
    (void)in_sizes; (void)n_in; (void)out_size;
    const int*   tokens = (const int*)  d_in[0];
    const float* embed  = (const float*)d_in[1];
    const float* Wqr = (const float*)d_in[2];
    const float* Wqi = (const float*)d_in[3];
    const float* Wkr = (const float*)d_in[4];
    const float* Wki = (const float*)d_in[5];
    const float* Wv  = (const float*)d_in[6];
    const float* Wo  = (const float*)d_in[7];
    const float* bo  = (const float*)d_in[8];
    const float* W1  = (const float*)d_in[9];
    const float* b1  = (const float*)d_in[10];
    const float* W2  = (const float*)d_in[11];
    const float* b2  = (const float*)d_in[12];
    const float* g1  = (const float*)d_in[13];
    const float* be1 = (const float*)d_in[14];
    const float* g2  = (const float*)d_in[15];
    const float* be2 = (const float*)d_in[16];
    const float* hw  = (const float*)d_in[17];
    const float* hb  = (const float*)d_in[18];
    float* out = (float*)d_out;

    float *zr,*zi,*acat,*qkv,*ctx,*t0,*z1,*ff,*b0,*b1b,*wt;
    cudaGetSymbolAddress((void**)&zr,   g_zr);
    cudaGetSymbolAddress((void**)&zi,   g_zi);
    cudaGetSymbolAddress((void**)&acat, g_acat);
    cudaGetSymbolAddress((void**)&qkv,  g_qkv);
    cudaGetSymbolAddress((void**)&ctx,  g_ctx);
    cudaGetSymbolAddress((void**)&t0,   g_t0);
    cudaGetSymbolAddress((void**)&z1,   g_z1);
    cudaGetSymbolAddress((void**)&ff,   g_ff);
    cudaGetSymbolAddress((void**)&b0,   g_b0);
    cudaGetSymbolAddress((void**)&b1b,  g_b1);
    cudaGetSymbolAddress((void**)&wt,   g_wt);

    cudaFuncSetAttribute(attn_tc_kernel, cudaFuncAttributeMaxDynamicSharedMemorySize,
                         ATTN_SMEM_BYTES);

    embed_kernel<<<ROWS, 128>>>(tokens, embed, zr);
    posimag_kernel<<<S_, 256>>>(zi);
    concat_kernel<<<ROWS, 256>>>(zr, zi, acat);

    const size_t DD = (size_t)D_ * D_;
    const size_t DF = (size_t)D_ * DFF_;

    // fused QKV weight assembly
    {
        dim3 g0(2 * D_ / 32, QKV_N / 32);
        assemble_qkvB_kernel<<<g0, dim3(32, 8)>>>(Wqr, Wqi, Wkr, Wki, Wv, b0, 2 * D_);
        dim3 g1d(D_ / 32, QKV_N / 32);
        assemble_qkvB_kernel<<<g1d, dim3(32, 8)>>>(Wqr + DD, Wqi + DD, Wkr + DD,
                                                   Wki + DD, Wv + DD, b1b, D_);
    }
    // Wo / W1 / W2 transposes
    for (int l = 0; l < L_; l++) {
        float* base = wt + (size_t)l * WT2_PER_LAYER;
        launch_transpose(Wo + l*DD, base,           D_,   D_);
        launch_transpose(W1 + l*DF, base + DD,      D_,   DFF_);
        launch_transpose(W2 + l*DF, base + DD + DF, DFF_, D_);
    }

    for (int l = 0; l < L_; l++) {
        float* base = wt + (size_t)l * WT2_PER_LAYER;
        const float* woT  = base;
        const float* w1T  = base + DD;
        const float* w2T  = base + DD + DF;
        const float* bo_l  = bo  + (size_t)l * D_;
        const float* b1_l  = b1  + (size_t)l * DFF_;
        const float* b2_l  = b2  + (size_t)l * D_;
        const float* g1_l  = g1  + (size_t)l * D_;
        const float* be1_l = be1 + (size_t)l * D_;
        const float* g2_l  = g2  + (size_t)l * D_;
        const float* be2_l = be2 + (size_t)l * D_;

        // fused QKV projection (single GEMM)
        if (l == 0)
            launch_gemm(acat, b0, qkv, ROWS, QKV_N, 2 * D_, nullptr, 0);
        else
            launch_gemm(zr, b1b, qkv, ROWS, QKV_N, D_, nullptr, 0);

        dim3 ag(S_ / 64, H_, B_);
        attn_tc_kernel<<<ag, 128, ATTN_SMEM_BYTES>>>(qkv, ctx);

        launch_gemm(ctx, woT, t0, ROWS, D_, D_, bo_l, 0);
        ln_res_kernel<<<ROWS, 128>>>(zr, t0, g1_l, be1_l, z1);
        launch_gemm(z1, w1T, ff, ROWS, DFF_, D_, b1_l, 1);
        launch_gemm(ff, w2T, t0, ROWS, D_, DFF_, b2_l, 0);
        ln_res_kernel<<<ROWS, 128>>>(z1, t0, g2_l, be2_l, zr);
    }

    head_kernel<<<ROWS / 8, 256>>>(zr, hw, hb, out);
}

// round 6
// speedup vs baseline: 4.7361x; 1.3912x over previous
#include <cuda_runtime.h>
#include <cuda_fp16.h>
#include <math.h>
#include <stdint.h>

#define B_   2
#define S_   2048
#define D_   512
#define H_   8
#define DK_  64
#define DFF_ 2048
#define L_   2
#define ROWS (B_*S_)   /* 4096 */

#define QKV_N  2560     /* qr|qi|kr|ki|v */
#define QKV_LD 2560

#define AT_ST 72        /* half stride for 64-wide attention tiles */

// ---------------- scratch (static device globals; no allocations) ----------------
__device__ float g_zr  [ROWS * D_];
__device__ float g_zi  [ROWS * D_];
__device__ float g_acat[ROWS * 2 * D_];
__device__ float g_qkv [ROWS * QKV_LD];
__device__ float g_ctx [ROWS * D_];
__device__ float g_t0  [ROWS * D_];
__device__ float g_z1  [ROWS * D_];
__device__ float g_ff  [ROWS * DFF_];
__device__ float g_b0  [QKV_N * 2 * D_];
__device__ float g_b1  [QKV_N * D_];
#define WT2_PER_LAYER (D_*D_ + 2*D_*DFF_)
__device__ float g_wt [L_ * WT2_PER_LAYER];

__device__ __forceinline__ uint32_t f22h(float a, float b) {
    __half2 h = __floats2half2_rn(a, b);
    return *(uint32_t*)&h;
}

__device__ __forceinline__ float rsqrt_fast(float x) {
    float y = __int_as_float(0x5f3759df - (__float_as_int(x) >> 1));
    y = y * (1.5f - 0.5f * x * y * y);
    y = y * (1.5f - 0.5f * x * y * y);
    return y;
}

__device__ __forceinline__ float exp_fast(float x) {
    float t = x * 1.4426950408889634f;
    float fn = __fadd_rn(t, 12582912.0f);
    int   n  = __float_as_int(fn) - 0x4B400000;
    float f  = t - __fadd_rn(fn, -12582912.0f);
    float p  = 1.33335581e-3f;
    p = fmaf(p, f, 9.61812911e-3f);
    p = fmaf(p, f, 5.55041087e-2f);
    p = fmaf(p, f, 2.40226507e-1f);
    p = fmaf(p, f, 6.93147180e-1f);
    p = fmaf(p, f, 1.0f);
    return __int_as_float(__float_as_int(p) + (n << 23));
}

#define MMA_F16(acc, a, b0, b1) \
    asm volatile("mma.sync.aligned.m16n8k16.row.col.f32.f16.f16.f32 " \
        "{%0,%1,%2,%3}, {%4,%5,%6,%7}, {%8,%9}, {%0,%1,%2,%3};" \
        : "+f"((acc)[0]), "+f"((acc)[1]), "+f"((acc)[2]), "+f"((acc)[3]) \
        : "r"((a)[0]), "r"((a)[1]), "r"((a)[2]), "r"((a)[3]), "r"(b0), "r"(b1))

// ---------------- fp16 tensor-core GEMM: C = A@Bt^T [+bias] [relu] ----------------
// A: [M x K] rm fp32. Bt: [N x K] rm fp32. M,N mult of 128; K mult of 32.
__global__ void __launch_bounds__(256) tc_gemm_kernel(
    const float* __restrict__ A, const float* __restrict__ Bt, float* __restrict__ C,
    int M, int N, int K, const float* __restrict__ bias, int relu)
{
    __shared__ __half As[128][40];
    __shared__ __half Bs[128][40];

    const int tid  = threadIdx.x;
    const int wid  = tid >> 5, lane = tid & 31;
    const int gid  = lane >> 2, tig = lane & 3;
    const int wy   = wid >> 2, wx = wid & 3;
    const int bm   = blockIdx.y, bn = blockIdx.x;

    const float* Ab = A  + (size_t)bm * 128 * K;
    const float* Bb = Bt + (size_t)bn * 128 * K;

    const int lr = tid >> 3;          // 0..31
    const int lc = (tid & 7) * 4;     // 0..28

    float acc[4][4][4];
    #pragma unroll
    for (int i = 0; i < 4; i++)
        #pragma unroll
        for (int j = 0; j < 4; j++)
            #pragma unroll
            for (int r = 0; r < 4; r++) acc[i][j][r] = 0.f;

    const int nch = K >> 5;

    float4 ar[4], br[4];
    #pragma unroll
    for (int rr = 0; rr < 4; rr++) {
        ar[rr] = *(const float4*)(Ab + (size_t)(lr + rr*32) * K + lc);
        br[rr] = *(const float4*)(Bb + (size_t)(lr + rr*32) * K + lc);
    }

    for (int c = 0; c < nch; c++) {
        __syncthreads();
        #pragma unroll
        for (int rr = 0; rr < 4; rr++) {
            const int r = lr + rr * 32;
            uint2 av = make_uint2(f22h(ar[rr].x, ar[rr].y), f22h(ar[rr].z, ar[rr].w));
            uint2 bv = make_uint2(f22h(br[rr].x, br[rr].y), f22h(br[rr].z, br[rr].w));
            *(uint2*)&As[r][lc] = av;
            *(uint2*)&Bs[r][lc] = bv;
        }
        __syncthreads();

        if (c + 1 < nch) {
            const int kg = (c + 1) * 32 + lc;
            #pragma unroll
            for (int rr = 0; rr < 4; rr++) {
                ar[rr] = *(const float4*)(Ab + (size_t)(lr + rr*32) * K + kg);
                br[rr] = *(const float4*)(Bb + (size_t)(lr + rr*32) * K + kg);
            }
        }

        #pragma unroll
        for (int ks = 0; ks < 2; ks++) {
            const int k0 = ks * 16 + 2 * tig;
            uint32_t af[4][4];
            #pragma unroll
            for (int mf = 0; mf < 4; mf++) {
                const int r = wy * 64 + mf * 16;
                af[mf][0] = *(const uint32_t*)&As[r + gid    ][k0    ];
                af[mf][1] = *(const uint32_t*)&As[r + gid + 8][k0    ];
                af[mf][2] = *(const uint32_t*)&As[r + gid    ][k0 + 8];
                af[mf][3] = *(const uint32_t*)&As[r + gid + 8][k0 + 8];
            }
            uint32_t bf[4][2];
            #pragma unroll
            for (int nf = 0; nf < 4; nf++) {
                const int n = wx * 32 + nf * 8;
                bf[nf][0] = *(const uint32_t*)&Bs[n + gid][k0    ];
                bf[nf][1] = *(const uint32_t*)&Bs[n + gid][k0 + 8];
            }
            #pragma unroll
            for (int mf = 0; mf < 4; mf++)
                #pragma unroll
                for (int nf = 0; nf < 4; nf++)
                    MMA_F16(acc[mf][nf], af[mf], bf[nf][0], bf[nf][1]);
        }
    }

    float2 bsv[4];
    if (bias) {
        #pragma unroll
        for (int nf = 0; nf < 4; nf++) {
            const int col = bn * 128 + wx * 32 + nf * 8 + tig * 2;
            bsv[nf] = *(const float2*)(bias + col);
        }
    }
    #pragma unroll
    for (int mf = 0; mf < 4; mf++) {
        const int row = bm * 128 + wy * 64 + mf * 16 + gid;
        #pragma unroll
        for (int nf = 0; nf < 4; nf++) {
            const int col = bn * 128 + wx * 32 + nf * 8 + tig * 2;
            #pragma unroll
            for (int half = 0; half < 2; half++) {
                const int r = row + half * 8;
                float2 v;
                v.x = acc[mf][nf][half*2 + 0];
                v.y = acc[mf][nf][half*2 + 1];
                if (bias) { v.x += bsv[nf].x; v.y += bsv[nf].y; }
                if (relu) { v.x = fmaxf(v.x, 0.f); v.y = fmaxf(v.y, 0.f); }
                *(float2*)(C + (size_t)r * N + col) = v;
            }
        }
    }
}

// ---------------- weight transpose ----------------
__global__ void __launch_bounds__(256) transpose_kernel(
    const float* __restrict__ in, float* __restrict__ out, int R, int Cc)
{
    __shared__ float t[32][33];
    int r0 = blockIdx.y * 32, c0 = blockIdx.x * 32;
    #pragma unroll
    for (int i = threadIdx.y; i < 32; i += 8)
        t[i][threadIdx.x] = in[(size_t)(r0 + i) * Cc + c0 + threadIdx.x];
    __syncthreads();
    #pragma unroll
    for (int i = threadIdx.y; i < 32; i += 8)
        out[(size_t)(c0 + i) * R + r0 + threadIdx.x] = t[threadIdx.x][i];
}

// ---------------- fused QKV weight assembly ----------------
__global__ void __launch_bounds__(256) assemble_qkvB_kernel(
    const float* __restrict__ Wqr, const float* __restrict__ Wqi,
    const float* __restrict__ Wkr, const float* __restrict__ Wki,
    const float* __restrict__ Wv,  float* __restrict__ out, int Kfull)
{
    __shared__ float t[32][33];
    const int k0 = blockIdx.x * 32, n0 = blockIdx.y * 32;
    const int blk  = n0 >> 9;
    const int half = k0 >> 9;
    const int ks   = k0 & 511;
    const int ns   = n0 & 511;

    const float* src = Wv;
    float sign = 1.f;
    bool zero = false;
    if      (blk == 0) { if (half == 0) src = Wqr; else { src = Wqi; sign = -1.f; } }
    else if (blk == 1) { if (half == 0) src = Wqi; else   src = Wqr; }
    else if (blk == 2) { if (half == 0) src = Wkr; else { src = Wki; sign = -1.f; } }
    else if (blk == 3) { if (half == 0) src = Wki; else   src = Wkr; }
    else               { if (half == 0) src = Wv;  else   zero = true; }

    #pragma unroll
    for (int i = threadIdx.y; i < 32; i += 8)
        t[i][threadIdx.x] = zero ? 0.f : src[(size_t)(ks + i) * 512 + ns + threadIdx.x];
    __syncthreads();
    #pragma unroll
    for (int i = threadIdx.y; i < 32; i += 8)
        out[(size_t)(n0 + i) * Kfull + k0 + threadIdx.x] = sign * t[threadIdx.x][i];
}

// ---------------- concat [zr | zi] ----------------
__global__ void __launch_bounds__(256) concat_kernel(
    const float* __restrict__ zr, const float* __restrict__ zi, float* __restrict__ out)
{
    const int row = blockIdx.x, c4 = threadIdx.x * 4;
    float4 v = (c4 < D_) ? *(const float4*)(zr + (size_t)row * D_ + c4)
                         : *(const float4*)(zi + (size_t)row * D_ + c4 - D_);
    *(float4*)(out + (size_t)row * 2 * D_ + c4) = v;
}

// ---------------- embedding / positional ----------------
__global__ void __launch_bounds__(128) embed_kernel(
    const int* __restrict__ tok, const float* __restrict__ emb, float* __restrict__ zr)
{
    int row = blockIdx.x;
    int t = tok[row];
    *(float4*)(zr + (size_t)row * D_ + threadIdx.x * 4) =
        *(const float4*)(emb + (size_t)t * D_ + threadIdx.x * 4);
}

__global__ void __launch_bounds__(256) posimag_kernel(float* __restrict__ zi)
{
    int s = blockIdx.x;
    int j = threadIdx.x;
    float freq = expf(-((float)j * (1.0f/256.0f)) * 9.2103403719761836f);
    float val = sinf((float)s * freq);
    float2 vv = make_float2(val, val);
    int d = j * 2;
    *(float2*)(zi + (size_t)(0 * S_ + s) * D_ + d) = vv;
    *(float2*)(zi + (size_t)(1 * S_ + s) * D_ + d) = vv;
}

// ---------------- fp16 tensor-core complex-hybrid flash attention ----------------
__global__ void __launch_bounds__(128) attn_tc_kernel(
    const float* __restrict__ QKV, float* __restrict__ Out)
{
    __shared__ __half bKr[64][AT_ST];
    __shared__ __half bKi[64][AT_ST];
    __shared__ __half bVt[64][AT_ST];   // V^T [d][kpos]
    __shared__ __half bPs[64][AT_ST];   // P [qrow][kpos]

    const int q0 = blockIdx.x * 64;
    const int h  = blockIdx.y;
    const int b  = blockIdx.z;
    const int tid  = threadIdx.x;
    const int wid  = tid >> 5, lane = tid & 31;
    const int gid  = lane >> 2, tig = lane & 3;
    const int wrow = wid * 16;
    const size_t baseq = ((size_t)b * S_) * QKV_LD + (size_t)h * DK_;
    const size_t baseo = ((size_t)b * S_) * D_     + (size_t)h * DK_;

    // ---- stage Q tile (through bKr/bKi) ----
    for (int i = tid; i < 64*16; i += 128) {
        int r = i >> 4, c4 = (i & 15) * 4;
        const float* qrow = QKV + baseq + (size_t)(q0 + r) * QKV_LD + c4;
        float4 a = *(const float4*)(qrow);          // qr
        float4 c = *(const float4*)(qrow + 512);    // qi
        *(uint2*)&bKr[r][c4] = make_uint2(f22h(a.x, a.y), f22h(a.z, a.w));
        *(uint2*)&bKi[r][c4] = make_uint2(f22h(c.x, c.y), f22h(c.z, c.w));
    }
    __syncthreads();

    uint32_t aQr[4][4], aQi[4][4];
    #pragma unroll
    for (int k = 0; k < 4; k++) {
        const int k0 = k * 16 + 2 * tig;
        aQr[k][0] = *(const uint32_t*)&bKr[wrow+gid  ][k0  ];
        aQr[k][1] = *(const uint32_t*)&bKr[wrow+gid+8][k0  ];
        aQr[k][2] = *(const uint32_t*)&bKr[wrow+gid  ][k0+8];
        aQr[k][3] = *(const uint32_t*)&bKr[wrow+gid+8][k0+8];
        aQi[k][0] = *(const uint32_t*)&bKi[wrow+gid  ][k0  ];
        aQi[k][1] = *(const uint32_t*)&bKi[wrow+gid+8][k0  ];
        aQi[k][2] = *(const uint32_t*)&bKi[wrow+gid  ][k0+8];
        aQi[k][3] = *(const uint32_t*)&bKi[wrow+gid+8][k0+8];
    }

    float o[8][4];
    #pragma unroll
    for (int n = 0; n < 8; n++)
        #pragma unroll
        for (int e = 0; e < 4; e++) o[n][e] = 0.f;
    float l0 = 0.f, l1 = 0.f;

    for (int kt = 0; kt < S_; kt += 64) {
        __syncthreads();
        for (int i = tid; i < 64*16; i += 128) {
            int r = i >> 4, c4 = (i & 15) * 4;
            const float* krow = QKV + baseq + (size_t)(kt + r) * QKV_LD + c4;
            float4 a = *(const float4*)(krow + 1024);   // kr
            float4 c = *(const float4*)(krow + 1536);   // ki
            float4 v = *(const float4*)(krow + 2048);   // v
            *(uint2*)&bKr[r][c4] = make_uint2(f22h(a.x, a.y), f22h(a.z, a.w));
            *(uint2*)&bKi[r][c4] = make_uint2(f22h(c.x, c.y), f22h(c.z, c.w));
            bVt[c4+0][r] = __float2half_rn(v.x);
            bVt[c4+1][r] = __float2half_rn(v.y);
            bVt[c4+2][r] = __float2half_rn(v.z);
            bVt[c4+3][r] = __float2half_rn(v.w);
        }
        __syncthreads();

        float srf[8][4], sif[8][4];
        #pragma unroll
        for (int n = 0; n < 8; n++)
            #pragma unroll
            for (int e = 0; e < 4; e++) { srf[n][e] = 0.f; sif[n][e] = 0.f; }

        #pragma unroll
        for (int k = 0; k < 4; k++) {
            const int k0 = k * 16 + 2 * tig;
            #pragma unroll
            for (int n = 0; n < 8; n++) {
                const int nr = n * 8 + gid;
                uint32_t b0r = *(const uint32_t*)&bKr[nr][k0  ];
                uint32_t b1r = *(const uint32_t*)&bKr[nr][k0+8];
                uint32_t b0i = *(const uint32_t*)&bKi[nr][k0  ];
                uint32_t b1i = *(const uint32_t*)&bKi[nr][k0+8];
                MMA_F16(srf[n], aQr[k], b0r, b1r);
                MMA_F16(srf[n], aQi[k], b0i, b1i);
                MMA_F16(sif[n], aQi[k], b0r, b1r);
                uint32_t n0 = b0i ^ 0x80008000u, n1 = b1i ^ 0x80008000u;
                MMA_F16(sif[n], aQr[k], n0, n1);
            }
        }

        float psum0 = 0.f, psum1 = 0.f;
        #pragma unroll
        for (int n = 0; n < 8; n++) {
            #pragma unroll
            for (int e = 0; e < 4; e++) {
                float a = srf[n][e], c = sif[n][e];
                float m2 = fmaf(a, a, c * c);
                float y  = rsqrt_fast(m2);
                float sc = y * fmaf(0.015625f, m2, 0.0375f * a);
                sc = (m2 == 0.f) ? 0.0375f : sc;
                float p = exp_fast(sc);
                srf[n][e] = p;
                if (e < 2) psum0 += p; else psum1 += p;
            }
        }
        psum0 += __shfl_xor_sync(0xffffffffu, psum0, 1);
        psum0 += __shfl_xor_sync(0xffffffffu, psum0, 2);
        psum1 += __shfl_xor_sync(0xffffffffu, psum1, 1);
        psum1 += __shfl_xor_sync(0xffffffffu, psum1, 2);
        l0 += psum0; l1 += psum1;

        // P -> smem as half (per-warp rows)
        #pragma unroll
        for (int n = 0; n < 8; n++) {
            const int cc = n * 8 + 2 * tig;
            *(uint32_t*)&bPs[wrow+gid  ][cc] = f22h(srf[n][0], srf[n][1]);
            *(uint32_t*)&bPs[wrow+gid+8][cc] = f22h(srf[n][2], srf[n][3]);
        }
        __syncwarp();

        #pragma unroll
        for (int k = 0; k < 4; k++) {
            const int k0 = k * 16 + 2 * tig;
            uint32_t ap[4];
            ap[0] = *(const uint32_t*)&bPs[wrow+gid  ][k0  ];
            ap[1] = *(const uint32_t*)&bPs[wrow+gid+8][k0  ];
            ap[2] = *(const uint32_t*)&bPs[wrow+gid  ][k0+8];
            ap[3] = *(const uint32_t*)&bPs[wrow+gid+8][k0+8];
            #pragma unroll
            for (int n = 0; n < 8; n++) {
                const int nr = n * 8 + gid;
                uint32_t b0 = *(const uint32_t*)&bVt[nr][k0  ];
                uint32_t b1 = *(const uint32_t*)&bVt[nr][k0+8];
                MMA_F16(o[n], ap, b0, b1);
            }
        }
    }

    const float inv0 = 1.0f / l0;
    const float inv1 = 1.0f / l1;
    #pragma unroll
    for (int n = 0; n < 8; n++) {
        const int col = n * 8 + 2 * tig;
        float2 v0 = make_float2(o[n][0] * inv0, o[n][1] * inv0);
        float2 v1 = make_float2(o[n][2] * inv1, o[n][3] * inv1);
        *(float2*)(Out + baseo + (size_t)(q0 + wrow + gid    ) * D_ + col) = v0;
        *(float2*)(Out + baseo + (size_t)(q0 + wrow + gid + 8) * D_ + col) = v1;
    }
}

// ---------------- fused residual + layernorm ----------------
__global__ void __launch_bounds__(128) ln_res_kernel(
    const float* __restrict__ x, const float* __restrict__ r,
    const float* __restrict__ g, const float* __restrict__ be,
    float* __restrict__ out)
{
    __shared__ float red[8];
    int row = blockIdx.x, tid = threadIdx.x;
    float4 xv = *(const float4*)(x + (size_t)row * D_ + tid * 4);
    float4 rv = *(const float4*)(r + (size_t)row * D_ + tid * 4);
    float v0 = xv.x + rv.x, v1 = xv.y + rv.y, v2 = xv.z + rv.z, v3 = xv.w + rv.w;
    float s  = v0 + v1 + v2 + v3;
    float s2 = v0*v0 + v1*v1 + v2*v2 + v3*v3;
    #pragma unroll
    for (int o = 16; o >= 1; o >>= 1) {
        s  += __shfl_xor_sync(0xffffffffu, s,  o);
        s2 += __shfl_xor_sync(0xffffffffu, s2, o);
    }
    int warp = tid >> 5, lane = tid & 31;
    if (lane == 0) { red[warp] = s; red[4 + warp] = s2; }
    __syncthreads();
    s  = red[0] + red[1] + red[2] + red[3];
    s2 = red[4] + red[5] + red[6] + red[7];
    float mu  = s  * (1.0f / D_);
    float var = s2 * (1.0f / D_) - mu * mu;
    float inv = rsqrtf(var + 1e-5f);
    float4 gv = *(const float4*)(g  + tid * 4);
    float4 bv = *(const float4*)(be + tid * 4);
    float4 o4;
    o4.x = (v0 - mu) * inv * gv.x + bv.x;
    o4.y = (v1 - mu) * inv * gv.y + bv.y;
    o4.z = (v2 - mu) * inv * gv.z + bv.z;
    o4.w = (v3 - mu) * inv * gv.w + bv.w;
    *(float4*)(out + (size_t)row * D_ + tid * 4) = o4;
}

// ---------------- classification head ----------------
__global__ void __launch_bounds__(256) head_kernel(
    const float* __restrict__ z, const float* __restrict__ w,
    const float* __restrict__ hb, float* __restrict__ out)
{
    int warp = threadIdx.x >> 5, lane = threadIdx.x & 31;
    int row = blockIdx.x * 8 + warp;
    const float* zr = z + (size_t)row * D_;
    float s0 = 0.f, s1 = 0.f;
    for (int d = lane; d < D_; d += 32) {
        float zv = zr[d];
        s0 += zv * w[d*2 + 0];
        s1 += zv * w[d*2 + 1];
    }
    #pragma unroll
    for (int o = 16; o >= 1; o >>= 1) {
        s0 += __shfl_xor_sync(0xffffffffu, s0, o);
        s1 += __shfl_xor_sync(0xffffffffu, s1, o);
    }
    if (lane == 0) {
        out[row*2 + 0] = s0 + hb[0];
        out[row*2 + 1] = s1 + hb[1];
    }
}

// ---------------- host-side orchestration ----------------
static inline void launch_gemm(const float* A, const float* Bt, float* C,
                               int M, int N, int K, const float* bias, int relu)
{
    dim3 grid(N / 128, M / 128);
    tc_gemm_kernel<<<grid, 256>>>(A, Bt, C, M, N, K, bias, relu);
}

static inline void launch_transpose(const float* in, float* out, int R, int Cc)
{
    dim3 grid(Cc / 32, R / 32);
    transpose_kernel<<<grid, dim3(32, 8)>>>(in, out, R, Cc);
}

extern "C" void kernel_launch(void* const* d_in, const int* in_sizes, int n_in,
                              void* d_out, int out_size)
{
    (void)in_sizes; (void)n_in; (void)out_size;
    const int*   tokens = (const int*)  d_in[0];
    const float* embed  = (const float*)d_in[1];
    const float* Wqr = (const float*)d_in[2];
    const float* Wqi = (const float*)d_in[3];
    const float* Wkr = (const float*)d_in[4];
    const float* Wki = (const float*)d_in[5];
    const float* Wv  = (const float*)d_in[6];
    const float* Wo  = (const float*)d_in[7];
    const float* bo  = (const float*)d_in[8];
    const float* W1  = (const float*)d_in[9];
    const float* b1  = (const float*)d_in[10];
    const float* W2  = (const float*)d_in[11];
    const float* b2  = (const float*)d_in[12];
    const float* g1  = (const float*)d_in[13];
    const float* be1 = (const float*)d_in[14];
    const float* g2  = (const float*)d_in[15];
    const float* be2 = (const float*)d_in[16];
    const float* hw  = (const float*)d_in[17];
    const float* hb  = (const float*)d_in[18];
    float* out = (float*)d_out;

    float *zr,*zi,*acat,*qkv,*ctx,*t0,*z1,*ff,*b0,*b1b,*wt;
    cudaGetSymbolAddress((void**)&zr,   g_zr);
    cudaGetSymbolAddress((void**)&zi,   g_zi);
    cudaGetSymbolAddress((void**)&acat, g_acat);
    cudaGetSymbolAddress((void**)&qkv,  g_qkv);
    cudaGetSymbolAddress((void**)&ctx,  g_ctx);
    cudaGetSymbolAddress((void**)&t0,   g_t0);
    cudaGetSymbolAddress((void**)&z1,   g_z1);
    cudaGetSymbolAddress((void**)&ff,   g_ff);
    cudaGetSymbolAddress((void**)&b0,   g_b0);
    cudaGetSymbolAddress((void**)&b1b,  g_b1);
    cudaGetSymbolAddress((void**)&wt,   g_wt);

    embed_kernel<<<ROWS, 128>>>(tokens, embed, zr);
    posimag_kernel<<<S_, 256>>>(zi);
    concat_kernel<<<ROWS, 256>>>(zr, zi, acat);

    const size_t DD = (size_t)D_ * D_;
    const size_t DF = (size_t)D_ * DFF_;

    {
        dim3 g0(2 * D_ / 32, QKV_N / 32);
        assemble_qkvB_kernel<<<g0, dim3(32, 8)>>>(Wqr, Wqi, Wkr, Wki, Wv, b0, 2 * D_);
        dim3 g1d(D_ / 32, QKV_N / 32);
        assemble_qkvB_kernel<<<g1d, dim3(32, 8)>>>(Wqr + DD, Wqi + DD, Wkr + DD,
                                                   Wki + DD, Wv + DD, b1b, D_);
    }
    for (int l = 0; l < L_; l++) {
        float* base = wt + (size_t)l * WT2_PER_LAYER;
        launch_transpose(Wo + l*DD, base,           D_,   D_);
        launch_transpose(W1 + l*DF, base + DD,      D_,   DFF_);
        launch_transpose(W2 + l*DF, base + DD + DF, DFF_, D_);
    }

    for (int l = 0; l < L_; l++) {
        float* base = wt + (size_t)l * WT2_PER_LAYER;
        const float* woT  = base;
        const float* w1T  = base + DD;
        const float* w2T  = base + DD + DF;
        const float* bo_l  = bo  + (size_t)l * D_;
        const float* b1_l  = b1  + (size_t)l * DFF_;
        const float* b2_l  = b2  + (size_t)l * D_;
        const float* g1_l  = g1  + (size_t)l * D_;
        const float* be1_l = be1 + (size_t)l * D_;
        const float* g2_l  = g2  + (size_t)l * D_;
        const float* be2_l = be2 + (size_t)l * D_;

        if (l == 0)
            launch_gemm(acat, b0, qkv, ROWS, QKV_N, 2 * D_, nullptr, 0);
        else
            launch_gemm(zr, b1b, qkv, ROWS, QKV_N, D_, nullptr, 0);

        dim3 ag(S_ / 64, H_, B_);
        attn_tc_kernel<<<ag, 128>>>(qkv, ctx);

        launch_gemm(ctx, woT, t0, ROWS, D_, D_, bo_l, 0);
        ln_res_kernel<<<ROWS, 128>>>(zr, t0, g1_l, be1_l, z1);
        launch_gemm(z1, w1T, ff, ROWS, DFF_, D_, b1_l, 1);
        launch_gemm(ff, w2T, t0, ROWS, D_, DFF_, b2_l, 0);
        ln_res_kernel<<<ROWS, 128>>>(z1, t0, g2_l, be2_l, zr);
    }

    head_kernel<<<ROWS / 8, 256>>>(zr, hw, hb, out);
}

// round 7
// speedup vs baseline: 4.8493x; 1.0239x over previous
#include <cuda_runtime.h>
#include <cuda_fp16.h>
#include <math.h>
#include <stdint.h>

#define B_   2
#define S_   2048
#define D_   512
#define H_   8
#define DK_  64
#define DFF_ 2048
#define L_   2
#define ROWS (B_*S_)   /* 4096 */

#define QKV_N  2560     /* qr|qi|kr|ki|v */
#define QKV_LD 2560

#define AT_ST 72        /* half stride for attention tiles */

// ---------------- scratch (static device globals; no allocations) ----------------
__device__ float  g_zr  [ROWS * D_];
__device__ float  g_zi  [ROWS * D_];
__device__ float  g_acat[ROWS * 2 * D_];
__device__ __half g_qkvh[ROWS * QKV_LD];
__device__ float  g_ctx [ROWS * D_];
__device__ float  g_t0  [ROWS * D_];
__device__ float  g_z1  [ROWS * D_];
__device__ float  g_ff  [ROWS * DFF_];
__device__ float  g_b0  [QKV_N * 2 * D_];
__device__ float  g_b1  [QKV_N * D_];
#define WT2_PER_LAYER (D_*D_ + 2*D_*DFF_)
__device__ float  g_wt [L_ * WT2_PER_LAYER];

__device__ __forceinline__ uint32_t f22h(float a, float b) {
    __half2 h = __floats2half2_rn(a, b);
    return *(uint32_t*)&h;
}

__device__ __forceinline__ float rsqrt_fast(float x) {
    float y = __int_as_float(0x5f3759df - (__float_as_int(x) >> 1));
    y = y * (1.5f - 0.5f * x * y * y);
    y = y * (1.5f - 0.5f * x * y * y);
    return y;
}

__device__ __forceinline__ float exp_fast(float x) {
    float t = x * 1.4426950408889634f;
    float fn = __fadd_rn(t, 12582912.0f);
    int   n  = __float_as_int(fn) - 0x4B400000;
    float f  = t - __fadd_rn(fn, -12582912.0f);
    float p  = 1.33335581e-3f;
    p = fmaf(p, f, 9.61812911e-3f);
    p = fmaf(p, f, 5.55041087e-2f);
    p = fmaf(p, f, 2.40226507e-1f);
    p = fmaf(p, f, 6.93147180e-1f);
    p = fmaf(p, f, 1.0f);
    return __int_as_float(__float_as_int(p) + (n << 23));
}

#define MMA_F16(acc, a, b0, b1) \
    asm volatile("mma.sync.aligned.m16n8k16.row.col.f32.f16.f16.f32 " \
        "{%0,%1,%2,%3}, {%4,%5,%6,%7}, {%8,%9}, {%0,%1,%2,%3};" \
        : "+f"((acc)[0]), "+f"((acc)[1]), "+f"((acc)[2]), "+f"((acc)[3]) \
        : "r"((a)[0]), "r"((a)[1]), "r"((a)[2]), "r"((a)[3]), "r"(b0), "r"(b1))

// ---------------- fp16 tensor-core GEMM: C = A@Bt^T [+bias] [relu] ----------------
// A: [M x K] rm fp32. Bt: [N x K] rm fp32. out_half: write __half instead of float.
__global__ void __launch_bounds__(256) tc_gemm_kernel(
    const float* __restrict__ A, const float* __restrict__ Bt, void* __restrict__ C,
    int M, int N, int K, const float* __restrict__ bias, int relu, int out_half)
{
    __shared__ __half As[128][40];
    __shared__ __half Bs[128][40];

    const int tid  = threadIdx.x;
    const int wid  = tid >> 5, lane = tid & 31;
    const int gid  = lane >> 2, tig = lane & 3;
    const int wy   = wid >> 2, wx = wid & 3;
    const int bm   = blockIdx.y, bn = blockIdx.x;

    const float* Ab = A  + (size_t)bm * 128 * K;
    const float* Bb = Bt + (size_t)bn * 128 * K;

    const int lr = tid >> 3;
    const int lc = (tid & 7) * 4;

    float acc[4][4][4];
    #pragma unroll
    for (int i = 0; i < 4; i++)
        #pragma unroll
        for (int j = 0; j < 4; j++)
            #pragma unroll
            for (int r = 0; r < 4; r++) acc[i][j][r] = 0.f;

    const int nch = K >> 5;

    float4 ar[4], br[4];
    #pragma unroll
    for (int rr = 0; rr < 4; rr++) {
        ar[rr] = *(const float4*)(Ab + (size_t)(lr + rr*32) * K + lc);
        br[rr] = *(const float4*)(Bb + (size_t)(lr + rr*32) * K + lc);
    }

    for (int c = 0; c < nch; c++) {
        __syncthreads();
        #pragma unroll
        for (int rr = 0; rr < 4; rr++) {
            const int r = lr + rr * 32;
            *(uint2*)&As[r][lc] = make_uint2(f22h(ar[rr].x, ar[rr].y), f22h(ar[rr].z, ar[rr].w));
            *(uint2*)&Bs[r][lc] = make_uint2(f22h(br[rr].x, br[rr].y), f22h(br[rr].z, br[rr].w));
        }
        __syncthreads();

        if (c + 1 < nch) {
            const int kg = (c + 1) * 32 + lc;
            #pragma unroll
            for (int rr = 0; rr < 4; rr++) {
                ar[rr] = *(const float4*)(Ab + (size_t)(lr + rr*32) * K + kg);
                br[rr] = *(const float4*)(Bb + (size_t)(lr + rr*32) * K + kg);
            }
        }

        #pragma unroll
        for (int ks = 0; ks < 2; ks++) {
            const int k0 = ks * 16 + 2 * tig;
            uint32_t af[4][4];
            #pragma unroll
            for (int mf = 0; mf < 4; mf++) {
                const int r = wy * 64 + mf * 16;
                af[mf][0] = *(const uint32_t*)&As[r + gid    ][k0    ];
                af[mf][1] = *(const uint32_t*)&As[r + gid + 8][k0    ];
                af[mf][2] = *(const uint32_t*)&As[r + gid    ][k0 + 8];
                af[mf][3] = *(const uint32_t*)&As[r + gid + 8][k0 + 8];
            }
            uint32_t bf[4][2];
            #pragma unroll
            for (int nf = 0; nf < 4; nf++) {
                const int n = wx * 32 + nf * 8;
                bf[nf][0] = *(const uint32_t*)&Bs[n + gid][k0    ];
                bf[nf][1] = *(const uint32_t*)&Bs[n + gid][k0 + 8];
            }
            #pragma unroll
            for (int mf = 0; mf < 4; mf++)
                #pragma unroll
                for (int nf = 0; nf < 4; nf++)
                    MMA_F16(acc[mf][nf], af[mf], bf[nf][0], bf[nf][1]);
        }
    }

    float2 bsv[4];
    if (bias) {
        #pragma unroll
        for (int nf = 0; nf < 4; nf++) {
            const int col = bn * 128 + wx * 32 + nf * 8 + tig * 2;
            bsv[nf] = *(const float2*)(bias + col);
        }
    }
    #pragma unroll
    for (int mf = 0; mf < 4; mf++) {
        const int row = bm * 128 + wy * 64 + mf * 16 + gid;
        #pragma unroll
        for (int nf = 0; nf < 4; nf++) {
            const int col = bn * 128 + wx * 32 + nf * 8 + tig * 2;
            #pragma unroll
            for (int half = 0; half < 2; half++) {
                const int r = row + half * 8;
                float vx = acc[mf][nf][half*2 + 0];
                float vy = acc[mf][nf][half*2 + 1];
                if (bias) { vx += bsv[nf].x; vy += bsv[nf].y; }
                if (relu) { vx = fmaxf(vx, 0.f); vy = fmaxf(vy, 0.f); }
                if (out_half) {
                    *(uint32_t*)((__half*)C + (size_t)r * N + col) = f22h(vx, vy);
                } else {
                    *(float2*)((float*)C + (size_t)r * N + col) = make_float2(vx, vy);
                }
            }
        }
    }
}

// ---------------- weight transpose ----------------
__global__ void __launch_bounds__(256) transpose_kernel(
    const float* __restrict__ in, float* __restrict__ out, int R, int Cc)
{
    __shared__ float t[32][33];
    int r0 = blockIdx.y * 32, c0 = blockIdx.x * 32;
    #pragma unroll
    for (int i = threadIdx.y; i < 32; i += 8)
        t[i][threadIdx.x] = in[(size_t)(r0 + i) * Cc + c0 + threadIdx.x];
    __syncthreads();
    #pragma unroll
    for (int i = threadIdx.y; i < 32; i += 8)
        out[(size_t)(c0 + i) * R + r0 + threadIdx.x] = t[threadIdx.x][i];
}

// ---------------- fused QKV weight assembly ----------------
__global__ void __launch_bounds__(256) assemble_qkvB_kernel(
    const float* __restrict__ Wqr, const float* __restrict__ Wqi,
    const float* __restrict__ Wkr, const float* __restrict__ Wki,
    const float* __restrict__ Wv,  float* __restrict__ out, int Kfull)
{
    __shared__ float t[32][33];
    const int k0 = blockIdx.x * 32, n0 = blockIdx.y * 32;
    const int blk  = n0 >> 9;
    const int half = k0 >> 9;
    const int ks   = k0 & 511;
    const int ns   = n0 & 511;

    const float* src = Wv;
    float sign = 1.f;
    bool zero = false;
    if      (blk == 0) { if (half == 0) src = Wqr; else { src = Wqi; sign = -1.f; } }
    else if (blk == 1) { if (half == 0) src = Wqi; else   src = Wqr; }
    else if (blk == 2) { if (half == 0) src = Wkr; else { src = Wki; sign = -1.f; } }
    else if (blk == 3) { if (half == 0) src = Wki; else   src = Wkr; }
    else               { if (half == 0) src = Wv;  else   zero = true; }

    #pragma unroll
    for (int i = threadIdx.y; i < 32; i += 8)
        t[i][threadIdx.x] = zero ? 0.f : src[(size_t)(ks + i) * 512 + ns + threadIdx.x];
    __syncthreads();
    #pragma unroll
    for (int i = threadIdx.y; i < 32; i += 8)
        out[(size_t)(n0 + i) * Kfull + k0 + threadIdx.x] = sign * t[threadIdx.x][i];
}

// ---------------- concat [zr | zi] ----------------
__global__ void __launch_bounds__(256) concat_kernel(
    const float* __restrict__ zr, const float* __restrict__ zi, float* __restrict__ out)
{
    const int row = blockIdx.x, c4 = threadIdx.x * 4;
    float4 v = (c4 < D_) ? *(const float4*)(zr + (size_t)row * D_ + c4)
                         : *(const float4*)(zi + (size_t)row * D_ + c4 - D_);
    *(float4*)(out + (size_t)row * 2 * D_ + c4) = v;
}

// ---------------- embedding / positional ----------------
__global__ void __launch_bounds__(128) embed_kernel(
    const int* __restrict__ tok, const float* __restrict__ emb, float* __restrict__ zr)
{
    int row = blockIdx.x;
    int t = tok[row];
    *(float4*)(zr + (size_t)row * D_ + threadIdx.x * 4) =
        *(const float4*)(emb + (size_t)t * D_ + threadIdx.x * 4);
}

__global__ void __launch_bounds__(256) posimag_kernel(float* __restrict__ zi)
{
    int s = blockIdx.x;
    int j = threadIdx.x;
    float freq = expf(-((float)j * (1.0f/256.0f)) * 9.2103403719761836f);
    float val = sinf((float)s * freq);
    float2 vv = make_float2(val, val);
    int d = j * 2;
    *(float2*)(zi + (size_t)(0 * S_ + s) * D_ + d) = vv;
    *(float2*)(zi + (size_t)(1 * S_ + s) * D_ + d) = vv;
}

// ---------------- fp16 tensor-core complex-hybrid flash attention ----------------
// 128 q-rows per CTA, 8 warps, QKV is fp16 in gmem.
__global__ void __launch_bounds__(256) attn_tc_kernel(
    const __half* __restrict__ QKV, float* __restrict__ Out)
{
    __shared__ __half bKr[64][AT_ST];
    __shared__ __half bKi[64][AT_ST];
    __shared__ __half bVt[64][AT_ST];    // V^T [d][kpos]
    __shared__ __half bPs[128][AT_ST];   // P [qrow][kpos]; also Q staging

    const int q0 = blockIdx.x * 128;
    const int h  = blockIdx.y;
    const int b  = blockIdx.z;
    const int tid  = threadIdx.x;
    const int wid  = tid >> 5, lane = tid & 31;
    const int gid  = lane >> 2, tig = lane & 3;
    const int wrow = wid * 16;
    const size_t baseq = ((size_t)b * S_) * QKV_LD + (size_t)h * DK_;
    const size_t baseo = ((size_t)b * S_) * D_     + (size_t)h * DK_;

    // ---- stage Q (two passes through bPs: qr then qi) ----
    uint32_t aQr[4][4], aQi[4][4];
    #pragma unroll
    for (int pass = 0; pass < 2; pass++) {
        const int off = pass ? 512 : 0;
        for (int i = tid; i < 128*8; i += 256) {
            int r = i >> 3, c8 = (i & 7) * 8;
            *(uint4*)&bPs[r][c8] =
                *(const uint4*)(QKV + baseq + (size_t)(q0 + r) * QKV_LD + off + c8);
        }
        __syncthreads();
        #pragma unroll
        for (int k = 0; k < 4; k++) {
            const int k0 = k * 16 + 2 * tig;
            uint32_t* dst = pass ? aQi[k] : aQr[k];
            dst[0] = *(const uint32_t*)&bPs[wrow+gid  ][k0  ];
            dst[1] = *(const uint32_t*)&bPs[wrow+gid+8][k0  ];
            dst[2] = *(const uint32_t*)&bPs[wrow+gid  ][k0+8];
            dst[3] = *(const uint32_t*)&bPs[wrow+gid+8][k0+8];
        }
        __syncthreads();
    }

    float o[8][4];
    #pragma unroll
    for (int n = 0; n < 8; n++)
        #pragma unroll
        for (int e = 0; e < 4; e++) o[n][e] = 0.f;
    float l0 = 0.f, l1 = 0.f;

    for (int kt = 0; kt < S_; kt += 64) {
        __syncthreads();
        // stage K tiles (plain copies) + V transpose
        for (int i = tid; i < 64*8; i += 256) {
            int r = i >> 3, c8 = (i & 7) * 8;
            const __half* krow = QKV + baseq + (size_t)(kt + r) * QKV_LD + c8;
            *(uint4*)&bKr[r][c8] = *(const uint4*)(krow + 1024);
            *(uint4*)&bKi[r][c8] = *(const uint4*)(krow + 1536);
            uint4 vv = *(const uint4*)(krow + 2048);
            const __half* vh = (const __half*)&vv;
            #pragma unroll
            for (int j = 0; j < 8; j++) bVt[c8 + j][r] = vh[j];
        }
        __syncthreads();

        float srf[8][4], sif[8][4];
        #pragma unroll
        for (int n = 0; n < 8; n++)
            #pragma unroll
            for (int e = 0; e < 4; e++) { srf[n][e] = 0.f; sif[n][e] = 0.f; }

        #pragma unroll
        for (int k = 0; k < 4; k++) {
            const int k0 = k * 16 + 2 * tig;
            #pragma unroll
            for (int n = 0; n < 8; n++) {
                const int nr = n * 8 + gid;
                uint32_t b0r = *(const uint32_t*)&bKr[nr][k0  ];
                uint32_t b1r = *(const uint32_t*)&bKr[nr][k0+8];
                uint32_t b0i = *(const uint32_t*)&bKi[nr][k0  ];
                uint32_t b1i = *(const uint32_t*)&bKi[nr][k0+8];
                MMA_F16(srf[n], aQr[k], b0r, b1r);
                MMA_F16(srf[n], aQi[k], b0i, b1i);
                MMA_F16(sif[n], aQi[k], b0r, b1r);
                uint32_t n0 = b0i ^ 0x80008000u, n1 = b1i ^ 0x80008000u;
                MMA_F16(sif[n], aQr[k], n0, n1);
            }
        }

        float psum0 = 0.f, psum1 = 0.f;
        #pragma unroll
        for (int n = 0; n < 8; n++) {
            #pragma unroll
            for (int e = 0; e < 4; e++) {
                float a = srf[n][e], c = sif[n][e];
                float m2 = fmaf(a, a, c * c);
                float y  = rsqrt_fast(m2);
                float sc = y * fmaf(0.015625f, m2, 0.0375f * a);
                sc = (m2 == 0.f) ? 0.0375f : sc;
                float p = exp_fast(sc);
                srf[n][e] = p;
                if (e < 2) psum0 += p; else psum1 += p;
            }
        }
        psum0 += __shfl_xor_sync(0xffffffffu, psum0, 1);
        psum0 += __shfl_xor_sync(0xffffffffu, psum0, 2);
        psum1 += __shfl_xor_sync(0xffffffffu, psum1, 1);
        psum1 += __shfl_xor_sync(0xffffffffu, psum1, 2);
        l0 += psum0; l1 += psum1;

        #pragma unroll
        for (int n = 0; n < 8; n++) {
            const int cc = n * 8 + 2 * tig;
            *(uint32_t*)&bPs[wrow+gid  ][cc] = f22h(srf[n][0], srf[n][1]);
            *(uint32_t*)&bPs[wrow+gid+8][cc] = f22h(srf[n][2], srf[n][3]);
        }
        __syncwarp();

        #pragma unroll
        for (int k = 0; k < 4; k++) {
            const int k0 = k * 16 + 2 * tig;
            uint32_t ap[4];
            ap[0] = *(const uint32_t*)&bPs[wrow+gid  ][k0  ];
            ap[1] = *(const uint32_t*)&bPs[wrow+gid+8][k0  ];
            ap[2] = *(const uint32_t*)&bPs[wrow+gid  ][k0+8];
            ap[3] = *(const uint32_t*)&bPs[wrow+gid+8][k0+8];
            #pragma unroll
            for (int n = 0; n < 8; n++) {
                const int nr = n * 8 + gid;
                uint32_t b0 = *(const uint32_t*)&bVt[nr][k0  ];
                uint32_t b1 = *(const uint32_t*)&bVt[nr][k0+8];
                MMA_F16(o[n], ap, b0, b1);
            }
        }
    }

    const float inv0 = 1.0f / l0;
    const float inv1 = 1.0f / l1;
    #pragma unroll
    for (int n = 0; n < 8; n++) {
        const int col = n * 8 + 2 * tig;
        float2 v0 = make_float2(o[n][0] * inv0, o[n][1] * inv0);
        float2 v1 = make_float2(o[n][2] * inv1, o[n][3] * inv1);
        *(float2*)(Out + baseo + (size_t)(q0 + wrow + gid    ) * D_ + col) = v0;
        *(float2*)(Out + baseo + (size_t)(q0 + wrow + gid + 8) * D_ + col) = v1;
    }
}

// ---------------- fused residual + layernorm ----------------
__global__ void __launch_bounds__(128) ln_res_kernel(
    const float* __restrict__ x, const float* __restrict__ r,
    const float* __restrict__ g, const float* __restrict__ be,
    float* __restrict__ out)
{
    __shared__ float red[8];
    int row = blockIdx.x, tid = threadIdx.x;
    float4 xv = *(const float4*)(x + (size_t)row * D_ + tid * 4);
    float4 rv = *(const float4*)(r + (size_t)row * D_ + tid * 4);
    float v0 = xv.x + rv.x, v1 = xv.y + rv.y, v2 = xv.z + rv.z, v3 = xv.w + rv.w;
    float s  = v0 + v1 + v2 + v3;
    float s2 = v0*v0 + v1*v1 + v2*v2 + v3*v3;
    #pragma unroll
    for (int o = 16; o >= 1; o >>= 1) {
        s  += __shfl_xor_sync(0xffffffffu, s,  o);
        s2 += __shfl_xor_sync(0xffffffffu, s2, o);
    }
    int warp = tid >> 5, lane = tid & 31;
    if (lane == 0) { red[warp] = s; red[4 + warp] = s2; }
    __syncthreads();
    s  = red[0] + red[1] + red[2] + red[3];
    s2 = red[4] + red[5] + red[6] + red[7];
    float mu  = s  * (1.0f / D_);
    float var = s2 * (1.0f / D_) - mu * mu;
    float inv = rsqrtf(var + 1e-5f);
    float4 gv = *(const float4*)(g  + tid * 4);
    float4 bv = *(const float4*)(be + tid * 4);
    float4 o4;
    o4.x = (v0 - mu) * inv * gv.x + bv.x;
    o4.y = (v1 - mu) * inv * gv.y + bv.y;
    o4.z = (v2 - mu) * inv * gv.z + bv.z;
    o4.w = (v3 - mu) * inv * gv.w + bv.w;
    *(float4*)(out + (size_t)row * D_ + tid * 4) = o4;
}

// ---------------- classification head ----------------
__global__ void __launch_bounds__(256) head_kernel(
    const float* __restrict__ z, const float* __restrict__ w,
    const float* __restrict__ hb, float* __restrict__ out)
{
    int warp = threadIdx.x >> 5, lane = threadIdx.x & 31;
    int row = blockIdx.x * 8 + warp;
    const float* zr = z + (size_t)row * D_;
    float s0 = 0.f, s1 = 0.f;
    for (int d = lane; d < D_; d += 32) {
        float zv = zr[d];
        s0 += zv * w[d*2 + 0];
        s1 += zv * w[d*2 + 1];
    }
    #pragma unroll
    for (int o = 16; o >= 1; o >>= 1) {
        s0 += __shfl_xor_sync(0xffffffffu, s0, o);
        s1 += __shfl_xor_sync(0xffffffffu, s1, o);
    }
    if (lane == 0) {
        out[row*2 + 0] = s0 + hb[0];
        out[row*2 + 1] = s1 + hb[1];
    }
}

// ---------------- host-side orchestration ----------------
static inline void launch_gemm(const float* A, const float* Bt, void* C,
                               int M, int N, int K, const float* bias, int relu,
                               int out_half)
{
    dim3 grid(N / 128, M / 128);
    tc_gemm_kernel<<<grid, 256>>>(A, Bt, C, M, N, K, bias, relu, out_half);
}

static inline void launch_transpose(const float* in, float* out, int R, int Cc)
{
    dim3 grid(Cc / 32, R / 32);
    transpose_kernel<<<grid, dim3(32, 8)>>>(in, out, R, Cc);
}

extern "C" void kernel_launch(void* const* d_in, const int* in_sizes, int n_in,
                              void* d_out, int out_size)
{
    (void)in_sizes; (void)n_in; (void)out_size;
    const int*   tokens = (const int*)  d_in[0];
    const float* embed  = (const float*)d_in[1];
    const float* Wqr = (const float*)d_in[2];
    const float* Wqi = (const float*)d_in[3];
    const float* Wkr = (const float*)d_in[4];
    const float* Wki = (const float*)d_in[5];
    const float* Wv  = (const float*)d_in[6];
    const float* Wo  = (const float*)d_in[7];
    const float* bo  = (const float*)d_in[8];
    const float* W1  = (const float*)d_in[9];
    const float* b1  = (const float*)d_in[10];
    const float* W2  = (const float*)d_in[11];
    const float* b2  = (const float*)d_in[12];
    const float* g1  = (const float*)d_in[13];
    const float* be1 = (const float*)d_in[14];
    const float* g2  = (const float*)d_in[15];
    const float* be2 = (const float*)d_in[16];
    const float* hw  = (const float*)d_in[17];
    const float* hb  = (const float*)d_in[18];
    float* out = (float*)d_out;

    float *zr,*zi,*acat,*ctx,*t0,*z1,*ff,*b0,*b1b,*wt;
    __half *qkvh;
    cudaGetSymbolAddress((void**)&zr,   g_zr);
    cudaGetSymbolAddress((void**)&zi,   g_zi);
    cudaGetSymbolAddress((void**)&acat, g_acat);
    cudaGetSymbolAddress((void**)&qkvh, g_qkvh);
    cudaGetSymbolAddress((void**)&ctx,  g_ctx);
    cudaGetSymbolAddress((void**)&t0,   g_t0);
    cudaGetSymbolAddress((void**)&z1,   g_z1);
    cudaGetSymbolAddress((void**)&ff,   g_ff);
    cudaGetSymbolAddress((void**)&b0,   g_b0);
    cudaGetSymbolAddress((void**)&b1b,  g_b1);
    cudaGetSymbolAddress((void**)&wt,   g_wt);

    embed_kernel<<<ROWS, 128>>>(tokens, embed, zr);
    posimag_kernel<<<S_, 256>>>(zi);
    concat_kernel<<<ROWS, 256>>>(zr, zi, acat);

    const size_t DD = (size_t)D_ * D_;
    const size_t DF = (size_t)D_ * DFF_;

    {
        dim3 g0(2 * D_ / 32, QKV_N / 32);
        assemble_qkvB_kernel<<<g0, dim3(32, 8)>>>(Wqr, Wqi, Wkr, Wki, Wv, b0, 2 * D_);
        dim3 g1d(D_ / 32, QKV_N / 32);
        assemble_qkvB_kernel<<<g1d, dim3(32, 8)>>>(Wqr + DD, Wqi + DD, Wkr + DD,
                                                   Wki + DD, Wv + DD, b1b, D_);
    }
    for (int l = 0; l < L_; l++) {
        float* base = wt + (size_t)l * WT2_PER_LAYER;
        launch_transpose(Wo + l*DD, base,           D_,   D_);
        launch_transpose(W1 + l*DF, base + DD,      D_,   DFF_);
        launch_transpose(W2 + l*DF, base + DD + DF, DFF_, D_);
    }

    for (int l = 0; l < L_; l++) {
        float* base = wt + (size_t)l * WT2_PER_LAYER;
        const float* woT  = base;
        const float* w1T  = base + DD;
        const float* w2T  = base + DD + DF;
        const float* bo_l  = bo  + (size_t)l * D_;
        const float* b1_l  = b1  + (size_t)l * DFF_;
        const float* b2_l  = b2  + (size_t)l * D_;
        const float* g1_l  = g1  + (size_t)l * D_;
        const float* be1_l = be1 + (size_t)l * D_;
        const float* g2_l  = g2  + (size_t)l * D_;
        const float* be2_l = be2 + (size_t)l * D_;

        if (l == 0)
            launch_gemm(acat, b0, qkvh, ROWS, QKV_N, 2 * D_, nullptr, 0, 1);
        else
            launch_gemm(zr, b1b, qkvh, ROWS, QKV_N, D_, nullptr, 0, 1);

        dim3 ag(S_ / 128, H_, B_);
        attn_tc_kernel<<<ag, 256>>>(qkvh, ctx);

        launch_gemm(ctx, woT, t0, ROWS, D_, D_, bo_l, 0, 0);
        ln_res_kernel<<<ROWS, 128>>>(zr, t0, g1_l, be1_l, z1);
        launch_gemm(z1, w1T, ff, ROWS, DFF_, D_, b1_l, 1, 0);
        launch_gemm(ff, w2T, t0, ROWS, D_, DFF_, b2_l, 0, 0);
        ln_res_kernel<<<ROWS, 128>>>(z1, t0, g2_l, be2_l, zr);
    }

    head_kernel<<<ROWS / 8, 256>>>(zr, hw, hb, out);
}

// round 8
// speedup vs baseline: 5.2576x; 1.0842x over previous
#include <cuda_runtime.h>
#include <cuda_fp16.h>
#include <math.h>
#include <stdint.h>

#define B_   2
#define S_   2048
#define D_   512
#define H_   8
#define DK_  64
#define DFF_ 2048
#define L_   2
#define ROWS (B_*S_)   /* 4096 */

#define QKV_N  2560
#define QKV_LD 2560
#define AT_ST 72

// ---------------- scratch ----------------
__device__ float  g_zr  [ROWS * D_];
__device__ __half g_zrh [ROWS * D_];
__device__ __half g_acat[ROWS * 2 * D_];
__device__ __half g_qkvh[ROWS * QKV_LD];
__device__ __half g_ctxh[ROWS * D_];
__device__ float  g_t0  [ROWS * D_];
__device__ float  g_z1  [ROWS * D_];
__device__ __half g_z1h [ROWS * D_];
__device__ __half g_ffh [ROWS * DFF_];
__device__ __half g_b0h [QKV_N * 2 * D_];
__device__ __half g_b1h [QKV_N * D_];
#define WT2_PER_LAYER (D_*D_ + 2*D_*DFF_)
__device__ __half g_wth [L_ * WT2_PER_LAYER];

__device__ __forceinline__ uint32_t f22h(float a, float b) {
    __half2 h = __floats2half2_rn(a, b);
    return *(uint32_t*)&h;
}

__device__ __forceinline__ float rsqrt_fast(float x) {
    float y = __int_as_float(0x5f3759df - (__float_as_int(x) >> 1));
    y = y * (1.5f - 0.5f * x * y * y);
    y = y * (1.5f - 0.5f * x * y * y);
    return y;
}

__device__ __forceinline__ float exp_fast(float x) {
    float t = x * 1.4426950408889634f;
    float fn = __fadd_rn(t, 12582912.0f);
    int   n  = __float_as_int(fn) - 0x4B400000;
    float f  = t - __fadd_rn(fn, -12582912.0f);
    float p  = 1.33335581e-3f;
    p = fmaf(p, f, 9.61812911e-3f);
    p = fmaf(p, f, 5.55041087e-2f);
    p = fmaf(p, f, 2.40226507e-1f);
    p = fmaf(p, f, 6.93147180e-1f);
    p = fmaf(p, f, 1.0f);
    return __int_as_float(__float_as_int(p) + (n << 23));
}

#define MMA_F16(acc, a, b0, b1) \
    asm volatile("mma.sync.aligned.m16n8k16.row.col.f32.f16.f16.f32 " \
        "{%0,%1,%2,%3}, {%4,%5,%6,%7}, {%8,%9}, {%0,%1,%2,%3};" \
        : "+f"((acc)[0]), "+f"((acc)[1]), "+f"((acc)[2]), "+f"((acc)[3]) \
        : "r"((a)[0]), "r"((a)[1]), "r"((a)[2]), "r"((a)[3]), "r"(b0), "r"(b1))

__device__ __forceinline__ void cp_async16(void* smem, const void* gmem) {
    uint32_t s = (uint32_t)__cvta_generic_to_shared(smem);
    asm volatile("cp.async.cg.shared.global [%0], [%1], 16;" :: "r"(s), "l"(gmem));
}
#define CP_COMMIT() asm volatile("cp.async.commit_group;" ::: "memory")
#define CP_WAIT0()  asm volatile("cp.async.wait_group 0;"  ::: "memory")

// ---------------- all-fp16 pipelined tensor-core GEMM ----------------
// A: [M x K] rm fp16. Bt: [N x K] rm fp16. K mult of 32; M,N mult of 128.
__global__ void __launch_bounds__(256) tc_gemm_h_kernel(
    const __half* __restrict__ A, const __half* __restrict__ Bt, void* __restrict__ C,
    int M, int N, int K, const float* __restrict__ bias, int relu, int out_half)
{
    __shared__ __half As[2][128][40];
    __shared__ __half Bs[2][128][40];

    const int tid  = threadIdx.x;
    const int wid  = tid >> 5, lane = tid & 31;
    const int gid  = lane >> 2, tig = lane & 3;
    const int wy   = wid >> 2, wx = wid & 3;
    const int bm   = blockIdx.y, bn = blockIdx.x;

    const __half* Ab = A  + (size_t)bm * 128 * K;
    const __half* Bb = Bt + (size_t)bn * 128 * K;

    const int lr = tid >> 2;          // 0..63
    const int c8 = (tid & 3) * 8;     // 0..24

    float acc[4][4][4];
    #pragma unroll
    for (int i = 0; i < 4; i++)
        #pragma unroll
        for (int j = 0; j < 4; j++)
            #pragma unroll
            for (int r = 0; r < 4; r++) acc[i][j][r] = 0.f;

    const int nch = K >> 5;

    // prologue: load chunk 0 into stage 0
    {
        const __half* a0 = Ab + (size_t)lr * K + c8;
        const __half* b0 = Bb + (size_t)lr * K + c8;
        cp_async16(&As[0][lr     ][c8], a0);
        cp_async16(&As[0][lr + 64][c8], a0 + (size_t)64 * K);
        cp_async16(&Bs[0][lr     ][c8], b0);
        cp_async16(&Bs[0][lr + 64][c8], b0 + (size_t)64 * K);
        CP_COMMIT();
    }

    for (int c = 0; c < nch; c++) {
        CP_WAIT0();
        __syncthreads();
        if (c + 1 < nch) {
            const int s = (c + 1) & 1;
            const int kg = (c + 1) * 32 + c8;
            const __half* a0 = Ab + (size_t)lr * K + kg;
            const __half* b0 = Bb + (size_t)lr * K + kg;
            cp_async16(&As[s][lr     ][c8], a0);
            cp_async16(&As[s][lr + 64][c8], a0 + (size_t)64 * K);
            cp_async16(&Bs[s][lr     ][c8], b0);
            cp_async16(&Bs[s][lr + 64][c8], b0 + (size_t)64 * K);
            CP_COMMIT();
        }
        const int s = c & 1;
        #pragma unroll
        for (int ks = 0; ks < 2; ks++) {
            const int k0 = ks * 16 + 2 * tig;
            uint32_t af[4][4];
            #pragma unroll
            for (int mf = 0; mf < 4; mf++) {
                const int r = wy * 64 + mf * 16;
                af[mf][0] = *(const uint32_t*)&As[s][r + gid    ][k0    ];
                af[mf][1] = *(const uint32_t*)&As[s][r + gid + 8][k0    ];
                af[mf][2] = *(const uint32_t*)&As[s][r + gid    ][k0 + 8];
                af[mf][3] = *(const uint32_t*)&As[s][r + gid + 8][k0 + 8];
            }
            uint32_t bf[4][2];
            #pragma unroll
            for (int nf = 0; nf < 4; nf++) {
                const int n = wx * 32 + nf * 8;
                bf[nf][0] = *(const uint32_t*)&Bs[s][n + gid][k0    ];
                bf[nf][1] = *(const uint32_t*)&Bs[s][n + gid][k0 + 8];
            }
            #pragma unroll
            for (int mf = 0; mf < 4; mf++)
                #pragma unroll
                for (int nf = 0; nf < 4; nf++)
                    MMA_F16(acc[mf][nf], af[mf], bf[nf][0], bf[nf][1]);
        }
        __syncthreads();
    }

    float2 bsv[4];
    if (bias) {
        #pragma unroll
        for (int nf = 0; nf < 4; nf++) {
            const int col = bn * 128 + wx * 32 + nf * 8 + tig * 2;
            bsv[nf] = *(const float2*)(bias + col);
        }
    }
    #pragma unroll
    for (int mf = 0; mf < 4; mf++) {
        const int row = bm * 128 + wy * 64 + mf * 16 + gid;
        #pragma unroll
        for (int nf = 0; nf < 4; nf++) {
            const int col = bn * 128 + wx * 32 + nf * 8 + tig * 2;
            #pragma unroll
            for (int half = 0; half < 2; half++) {
                const int r = row + half * 8;
                float vx = acc[mf][nf][half*2 + 0];
                float vy = acc[mf][nf][half*2 + 1];
                if (bias) { vx += bsv[nf].x; vy += bsv[nf].y; }
                if (relu) { vx = fmaxf(vx, 0.f); vy = fmaxf(vy, 0.f); }
                if (out_half) {
                    *(uint32_t*)((__half*)C + (size_t)r * N + col) = f22h(vx, vy);
                } else {
                    *(float2*)((float*)C + (size_t)r * N + col) = make_float2(vx, vy);
                }
            }
        }
    }
}

// ---------------- weight transpose (fp32 -> fp16) ----------------
__global__ void __launch_bounds__(256) transpose_h_kernel(
    const float* __restrict__ in, __half* __restrict__ out, int R, int Cc)
{
    __shared__ float t[32][33];
    int r0 = blockIdx.y * 32, c0 = blockIdx.x * 32;
    #pragma unroll
    for (int i = threadIdx.y; i < 32; i += 8)
        t[i][threadIdx.x] = in[(size_t)(r0 + i) * Cc + c0 + threadIdx.x];
    __syncthreads();
    #pragma unroll
    for (int i = threadIdx.y; i < 32; i += 8)
        out[(size_t)(c0 + i) * R + r0 + threadIdx.x] = __float2half_rn(t[threadIdx.x][i]);
}

// ---------------- fused QKV weight assembly (fp16 out) ----------------
__global__ void __launch_bounds__(256) assemble_qkvB_kernel(
    const float* __restrict__ Wqr, const float* __restrict__ Wqi,
    const float* __restrict__ Wkr, const float* __restrict__ Wki,
    const float* __restrict__ Wv,  __half* __restrict__ out, int Kfull)
{
    __shared__ float t[32][33];
    const int k0 = blockIdx.x * 32, n0 = blockIdx.y * 32;
    const int blk  = n0 >> 9;
    const int half = k0 >> 9;
    const int ks   = k0 & 511;
    const int ns   = n0 & 511;

    const float* src = Wv;
    float sign = 1.f;
    bool zero = false;
    if      (blk == 0) { if (half == 0) src = Wqr; else { src = Wqi; sign = -1.f; } }
    else if (blk == 1) { if (half == 0) src = Wqi; else   src = Wqr; }
    else if (blk == 2) { if (half == 0) src = Wkr; else { src = Wki; sign = -1.f; } }
    else if (blk == 3) { if (half == 0) src = Wki; else   src = Wkr; }
    else               { if (half == 0) src = Wv;  else   zero = true; }

    #pragma unroll
    for (int i = threadIdx.y; i < 32; i += 8)
        t[i][threadIdx.x] = zero ? 0.f : src[(size_t)(ks + i) * 512 + ns + threadIdx.x];
    __syncthreads();
    #pragma unroll
    for (int i = threadIdx.y; i < 32; i += 8)
        out[(size_t)(n0 + i) * Kfull + k0 + threadIdx.x] =
            __float2half_rn(sign * t[threadIdx.x][i]);
}

// ---------------- embedding (writes fp32 zr + fp16 acat left) ----------------
__global__ void __launch_bounds__(128) embed_kernel(
    const int* __restrict__ tok, const float* __restrict__ emb,
    float* __restrict__ zr, __half* __restrict__ acat)
{
    int row = blockIdx.x;
    int t = tok[row];
    int c4 = threadIdx.x * 4;
    float4 v = *(const float4*)(emb + (size_t)t * D_ + c4);
    *(float4*)(zr + (size_t)row * D_ + c4) = v;
    *(uint2*)(acat + (size_t)row * 2 * D_ + c4) =
        make_uint2(f22h(v.x, v.y), f22h(v.z, v.w));
}

// ---------------- positional imaginary (writes fp16 acat right) ----------------
__global__ void __launch_bounds__(256) posimag_kernel(__half* __restrict__ acat)
{
    int s = blockIdx.x;
    int j = threadIdx.x;
    float freq = expf(-((float)j * (1.0f/256.0f)) * 9.2103403719761836f);
    float val = sinf((float)s * freq);
    uint32_t vv = f22h(val, val);
    int d = D_ + j * 2;
    *(uint32_t*)(acat + (size_t)(0 * S_ + s) * 2 * D_ + d) = vv;
    *(uint32_t*)(acat + (size_t)(1 * S_ + s) * 2 * D_ + d) = vv;
}

// ---------------- fp16 tensor-core complex-hybrid flash attention ----------------
__global__ void __launch_bounds__(256) attn_tc_kernel(
    const __half* __restrict__ QKV, __half* __restrict__ Out)
{
    __shared__ __half bKr[64][AT_ST];
    __shared__ __half bKi[64][AT_ST];
    __shared__ __half bVt[64][AT_ST];
    __shared__ __half bPs[128][AT_ST];

    const int q0 = blockIdx.x * 128;
    const int h  = blockIdx.y;
    const int b  = blockIdx.z;
    const int tid  = threadIdx.x;
    const int wid  = tid >> 5, lane = tid & 31;
    const int gid  = lane >> 2, tig = lane & 3;
    const int wrow = wid * 16;
    const size_t baseq = ((size_t)b * S_) * QKV_LD + (size_t)h * DK_;
    const size_t baseo = ((size_t)b * S_) * D_     + (size_t)h * DK_;

    uint32_t aQr[4][4], aQi[4][4];
    #pragma unroll
    for (int pass = 0; pass < 2; pass++) {
        const int off = pass ? 512 : 0;
        for (int i = tid; i < 128*8; i += 256) {
            int r = i >> 3, c8 = (i & 7) * 8;
            *(uint4*)&bPs[r][c8] =
                *(const uint4*)(QKV + baseq + (size_t)(q0 + r) * QKV_LD + off + c8);
        }
        __syncthreads();
        #pragma unroll
        for (int k = 0; k < 4; k++) {
            const int k0 = k * 16 + 2 * tig;
            uint32_t* dst = pass ? aQi[k] : aQr[k];
            dst[0] = *(const uint32_t*)&bPs[wrow+gid  ][k0  ];
            dst[1] = *(const uint32_t*)&bPs[wrow+gid+8][k0  ];
            dst[2] = *(const uint32_t*)&bPs[wrow+gid  ][k0+8];
            dst[3] = *(const uint32_t*)&bPs[wrow+gid+8][k0+8];
        }
        __syncthreads();
    }

    float o[8][4];
    #pragma unroll
    for (int n = 0; n < 8; n++)
        #pragma unroll
        for (int e = 0; e < 4; e++) o[n][e] = 0.f;
    float l0 = 0.f, l1 = 0.f;

    for (int kt = 0; kt < S_; kt += 64) {
        __syncthreads();
        for (int i = tid; i < 64*8; i += 256) {
            int r = i >> 3, c8 = (i & 7) * 8;
            const __half* krow = QKV + baseq + (size_t)(kt + r) * QKV_LD + c8;
            *(uint4*)&bKr[r][c8] = *(const uint4*)(krow + 1024);
            *(uint4*)&bKi[r][c8] = *(const uint4*)(krow + 1536);
            uint4 vv = *(const uint4*)(krow + 2048);
            const __half* vh = (const __half*)&vv;
            #pragma unroll
            for (int j = 0; j < 8; j++) bVt[c8 + j][r] = vh[j];
        }
        __syncthreads();

        float srf[8][4], sif[8][4];
        #pragma unroll
        for (int n = 0; n < 8; n++)
            #pragma unroll
            for (int e = 0; e < 4; e++) { srf[n][e] = 0.f; sif[n][e] = 0.f; }

        #pragma unroll
        for (int k = 0; k < 4; k++) {
            const int k0 = k * 16 + 2 * tig;
            #pragma unroll
            for (int n = 0; n < 8; n++) {
                const int nr = n * 8 + gid;
                uint32_t b0r = *(const uint32_t*)&bKr[nr][k0  ];
                uint32_t b1r = *(const uint32_t*)&bKr[nr][k0+8];
                uint32_t b0i = *(const uint32_t*)&bKi[nr][k0  ];
                uint32_t b1i = *(const uint32_t*)&bKi[nr][k0+8];
                MMA_F16(srf[n], aQr[k], b0r, b1r);
                MMA_F16(srf[n], aQi[k], b0i, b1i);
                MMA_F16(sif[n], aQi[k], b0r, b1r);
                uint32_t n0 = b0i ^ 0x80008000u, n1 = b1i ^ 0x80008000u;
                MMA_F16(sif[n], aQr[k], n0, n1);
            }
        }

        float psum0 = 0.f, psum1 = 0.f;
        #pragma unroll
        for (int n = 0; n < 8; n++) {
            #pragma unroll
            for (int e = 0; e < 4; e++) {
                float a = srf[n][e], c = sif[n][e];
                float m2 = fmaf(a, a, c * c);
                float y  = rsqrt_fast(m2);
                float sc = y * fmaf(0.015625f, m2, 0.0375f * a);
                sc = (m2 == 0.f) ? 0.0375f : sc;
                float p = exp_fast(sc);
                srf[n][e] = p;
                if (e < 2) psum0 += p; else psum1 += p;
            }
        }
        psum0 += __shfl_xor_sync(0xffffffffu, psum0, 1);
        psum0 += __shfl_xor_sync(0xffffffffu, psum0, 2);
        psum1 += __shfl_xor_sync(0xffffffffu, psum1, 1);
        psum1 += __shfl_xor_sync(0xffffffffu, psum1, 2);
        l0 += psum0; l1 += psum1;

        #pragma unroll
        for (int n = 0; n < 8; n++) {
            const int cc = n * 8 + 2 * tig;
            *(uint32_t*)&bPs[wrow+gid  ][cc] = f22h(srf[n][0], srf[n][1]);
            *(uint32_t*)&bPs[wrow+gid+8][cc] = f22h(srf[n][2], srf[n][3]);
        }
        __syncwarp();

        #pragma unroll
        for (int k = 0; k < 4; k++) {
            const int k0 = k * 16 + 2 * tig;
            uint32_t ap[4];
            ap[0] = *(const uint32_t*)&bPs[wrow+gid  ][k0  ];
            ap[1] = *(const uint32_t*)&bPs[wrow+gid+8][k0  ];
            ap[2] = *(const uint32_t*)&bPs[wrow+gid  ][k0+8];
            ap[3] = *(const uint32_t*)&bPs[wrow+gid+8][k0+8];
            #pragma unroll
            for (int n = 0; n < 8; n++) {
                const int nr = n * 8 + gid;
                uint32_t b0 = *(const uint32_t*)&bVt[nr][k0  ];
                uint32_t b1 = *(const uint32_t*)&bVt[nr][k0+8];
                MMA_F16(o[n], ap, b0, b1);
            }
        }
    }

    const float inv0 = 1.0f / l0;
    const float inv1 = 1.0f / l1;
    #pragma unroll
    for (int n = 0; n < 8; n++) {
        const int col = n * 8 + 2 * tig;
        *(uint32_t*)(Out + baseo + (size_t)(q0 + wrow + gid    ) * D_ + col) =
            f22h(o[n][0] * inv0, o[n][1] * inv0);
        *(uint32_t*)(Out + baseo + (size_t)(q0 + wrow + gid + 8) * D_ + col) =
            f22h(o[n][2] * inv1, o[n][3] * inv1);
    }
}

// ---------------- fused residual + layernorm (fp32 + fp16 twin out) ----------------
__global__ void __launch_bounds__(128) ln_res_kernel(
    const float* __restrict__ x, const float* __restrict__ r,
    const float* __restrict__ g, const float* __restrict__ be,
    float* __restrict__ outf, __half* __restrict__ outh)
{
    __shared__ float red[8];
    int row = blockIdx.x, tid = threadIdx.x;
    float4 xv = *(const float4*)(x + (size_t)row * D_ + tid * 4);
    float4 rv = *(const float4*)(r + (size_t)row * D_ + tid * 4);
    float v0 = xv.x + rv.x, v1 = xv.y + rv.y, v2 = xv.z + rv.z, v3 = xv.w + rv.w;
    float s  = v0 + v1 + v2 + v3;
    float s2 = v0*v0 + v1*v1 + v2*v2 + v3*v3;
    #pragma unroll
    for (int o = 16; o >= 1; o >>= 1) {
        s  += __shfl_xor_sync(0xffffffffu, s,  o);
        s2 += __shfl_xor_sync(0xffffffffu, s2, o);
    }
    int warp = tid >> 5, lane = tid & 31;
    if (lane == 0) { red[warp] = s; red[4 + warp] = s2; }
    __syncthreads();
    s  = red[0] + red[1] + red[2] + red[3];
    s2 = red[4] + red[5] + red[6] + red[7];
    float mu  = s  * (1.0f / D_);
    float var = s2 * (1.0f / D_) - mu * mu;
    float inv = rsqrtf(var + 1e-5f);
    float4 gv = *(const float4*)(g  + tid * 4);
    float4 bv = *(const float4*)(be + tid * 4);
    float4 o4;
    o4.x = (v0 - mu) * inv * gv.x + bv.x;
    o4.y = (v1 - mu) * inv * gv.y + bv.y;
    o4.z = (v2 - mu) * inv * gv.z + bv.z;
    o4.w = (v3 - mu) * inv * gv.w + bv.w;
    *(float4*)(outf + (size_t)row * D_ + tid * 4) = o4;
    *(uint2*)(outh + (size_t)row * D_ + tid * 4) =
        make_uint2(f22h(o4.x, o4.y), f22h(o4.z, o4.w));
}

// ---------------- classification head ----------------
__global__ void __launch_bounds__(256) head_kernel(
    const float* __restrict__ z, const float* __restrict__ w,
    const float* __restrict__ hb, float* __restrict__ out)
{
    int warp = threadIdx.x >> 5, lane = threadIdx.x & 31;
    int row = blockIdx.x * 8 + warp;
    const float* zr = z + (size_t)row * D_;
    float s0 = 0.f, s1 = 0.f;
    for (int d = lane; d < D_; d += 32) {
        float zv = zr[d];
        s0 += zv * w[d*2 + 0];
        s1 += zv * w[d*2 + 1];
    }
    #pragma unroll
    for (int o = 16; o >= 1; o >>= 1) {
        s0 += __shfl_xor_sync(0xffffffffu, s0, o);
        s1 += __shfl_xor_sync(0xffffffffu, s1, o);
    }
    if (lane == 0) {
        out[row*2 + 0] = s0 + hb[0];
        out[row*2 + 1] = s1 + hb[1];
    }
}

// ---------------- host-side orchestration ----------------
static inline void launch_gemm(const __half* A, const __half* Bt, void* C,
                               int M, int N, int K, const float* bias, int relu,
                               int out_half)
{
    dim3 grid(N / 128, M / 128);
    tc_gemm_h_kernel<<<grid, 256>>>(A, Bt, C, M, N, K, bias, relu, out_half);
}

static inline void launch_transpose(const float* in, __half* out, int R, int Cc)
{
    dim3 grid(Cc / 32, R / 32);
    transpose_h_kernel<<<grid, dim3(32, 8)>>>(in, out, R, Cc);
}

extern "C" void kernel_launch(void* const* d_in, const int* in_sizes, int n_in,
                              void* d_out, int out_size)
{
    (void)in_sizes; (void)n_in; (void)out_size;
    const int*   tokens = (const int*)  d_in[0];
    const float* embed  = (const float*)d_in[1];
    const float* Wqr = (const float*)d_in[2];
    const float* Wqi = (const float*)d_in[3];
    const float* Wkr = (const float*)d_in[4];
    const float* Wki = (const float*)d_in[5];
    const float* Wv  = (const float*)d_in[6];
    const float* Wo  = (const float*)d_in[7];
    const float* bo  = (const float*)d_in[8];
    const float* W1  = (const float*)d_in[9];
    const float* b1  = (const float*)d_in[10];
    const float* W2  = (const float*)d_in[11];
    const float* b2  = (const float*)d_in[12];
    const float* g1  = (const float*)d_in[13];
    const float* be1 = (const float*)d_in[14];
    const float* g2  = (const float*)d_in[15];
    const float* be2 = (const float*)d_in[16];
    const float* hw  = (const float*)d_in[17];
    const float* hb  = (const float*)d_in[18];
    float* out = (float*)d_out;

    float *zr,*t0,*z1;
    __half *zrh,*acat,*qkvh,*ctxh,*z1h,*ffh,*b0h,*b1h,*wth;
    cudaGetSymbolAddress((void**)&zr,   g_zr);
    cudaGetSymbolAddress((void**)&zrh,  g_zrh);
    cudaGetSymbolAddress((void**)&acat, g_acat);
    cudaGetSymbolAddress((void**)&qkvh, g_qkvh);
    cudaGetSymbolAddress((void**)&ctxh, g_ctxh);
    cudaGetSymbolAddress((void**)&t0,   g_t0);
    cudaGetSymbolAddress((void**)&z1,   g_z1);
    cudaGetSymbolAddress((void**)&z1h,  g_z1h);
    cudaGetSymbolAddress((void**)&ffh,  g_ffh);
    cudaGetSymbolAddress((void**)&b0h,  g_b0h);
    cudaGetSymbolAddress((void**)&b1h,  g_b1h);
    cudaGetSymbolAddress((void**)&wth,  g_wth);

    embed_kernel<<<ROWS, 128>>>(tokens, embed, zr, acat);
    posimag_kernel<<<S_, 256>>>(acat);

    const size_t DD = (size_t)D_ * D_;
    const size_t DF = (size_t)D_ * DFF_;

    {
        dim3 g0(2 * D_ / 32, QKV_N / 32);
        assemble_qkvB_kernel<<<g0, dim3(32, 8)>>>(Wqr, Wqi, Wkr, Wki, Wv, b0h, 2 * D_);
        dim3 g1d(D_ / 32, QKV_N / 32);
        assemble_qkvB_kernel<<<g1d, dim3(32, 8)>>>(Wqr + DD, Wqi + DD, Wkr + DD,
                                                   Wki + DD, Wv + DD, b1h, D_);
    }
    for (int l = 0; l < L_; l++) {
        __half* base = wth + (size_t)l * WT2_PER_LAYER;
        launch_transpose(Wo + l*DD, base,           D_,   D_);
        launch_transpose(W1 + l*DF, base + DD,      D_,   DFF_);
        launch_transpose(W2 + l*DF, base + DD + DF, DFF_, D_);
    }

    for (int l = 0; l < L_; l++) {
        __half* base = wth + (size_t)l * WT2_PER_LAYER;
        const __half* woT  = base;
        const __half* w1T  = base + DD;
        const __half* w2T  = base + DD + DF;
        const float* bo_l  = bo  + (size_t)l * D_;
        const float* b1_l  = b1  + (size_t)l * DFF_;
        const float* b2_l  = b2  + (size_t)l * D_;
        const float* g1_l  = g1  + (size_t)l * D_;
        const float* be1_l = be1 + (size_t)l * D_;
        const float* g2_l  = g2  + (size_t)l * D_;
        const float* be2_l = be2 + (size_t)l * D_;

        if (l == 0)
            launch_gemm(acat, b0h, qkvh, ROWS, QKV_N, 2 * D_, nullptr, 0, 1);
        else
            launch_gemm(zrh, b1h, qkvh, ROWS, QKV_N, D_, nullptr, 0, 1);

        dim3 ag(S_ / 128, H_, B_);
        attn_tc_kernel<<<ag, 256>>>(qkvh, ctxh);

        launch_gemm(ctxh, woT, t0, ROWS, D_, D_, bo_l, 0, 0);
        ln_res_kernel<<<ROWS, 128>>>(zr, t0, g1_l, be1_l, z1, z1h);
        launch_gemm(z1h, w1T, ffh, ROWS, DFF_, D_, b1_l, 1, 1);
        launch_gemm(ffh, w2T, t0, ROWS, D_, DFF_, b2_l, 0, 0);
        ln_res_kernel<<<ROWS, 128>>>(z1, t0, g2_l, be2_l, zr, zrh);
    }

    head_kernel<<<ROWS / 8, 256>>>(zr, hw, hb, out);
}

// round 9
// speedup vs baseline: 6.5432x; 1.2445x over previous
#include <cuda_runtime.h>
#include <cuda_fp16.h>
#include <math.h>
#include <stdint.h>

#define B_   2
#define S_   2048
#define D_   512
#define H_   8
#define DK_  64
#define DFF_ 2048
#define L_   2
#define ROWS (B_*S_)   /* 4096 */

#define QKV_N  2560
#define QKV_LD 2560
#define AT_ST 72
#define ATTN_SMEM_BYTES (6 * 64 * AT_ST * 2)   /* 55296 */

// ---------------- scratch ----------------
__device__ float  g_zr  [ROWS * D_];
__device__ __half g_zrh [ROWS * D_];
__device__ __half g_acat[ROWS * 2 * D_];
__device__ __half g_qkvh[ROWS * QKV_LD];
__device__ __half g_ctxh[ROWS * D_];
__device__ float  g_t0  [ROWS * D_];
__device__ float  g_z1  [ROWS * D_];
__device__ __half g_z1h [ROWS * D_];
__device__ __half g_ffh [ROWS * DFF_];
__device__ __half g_b0h [QKV_N * 2 * D_];
__device__ __half g_b1h [QKV_N * D_];
#define WT2_PER_LAYER (D_*D_ + 2*D_*DFF_)
__device__ __half g_wth [L_ * WT2_PER_LAYER];

__device__ __forceinline__ uint32_t f22h(float a, float b) {
    __half2 h = __floats2half2_rn(a, b);
    return *(uint32_t*)&h;
}

__device__ __forceinline__ float rsqrt_fast(float x) {
    float y = __int_as_float(0x5f3759df - (__float_as_int(x) >> 1));
    y = y * (1.5f - 0.5f * x * y * y);
    y = y * (1.5f - 0.5f * x * y * y);
    return y;
}

// exp for |x| <= ~0.6: direct degree-5 Taylor (max err ~ x^6/720)
__device__ __forceinline__ float exp_poly(float x) {
    float p = 8.3333337e-3f;
    p = fmaf(p, x, 4.1666668e-2f);
    p = fmaf(p, x, 0.16666667f);
    p = fmaf(p, x, 0.5f);
    p = fmaf(p, x, 1.0f);
    p = fmaf(p, x, 1.0f);
    return p;
}

#define MMA_F16(acc, a, b0, b1) \
    asm volatile("mma.sync.aligned.m16n8k16.row.col.f32.f16.f16.f32 " \
        "{%0,%1,%2,%3}, {%4,%5,%6,%7}, {%8,%9}, {%0,%1,%2,%3};" \
        : "+f"((acc)[0]), "+f"((acc)[1]), "+f"((acc)[2]), "+f"((acc)[3]) \
        : "r"((a)[0]), "r"((a)[1]), "r"((a)[2]), "r"((a)[3]), "r"(b0), "r"(b1))

__device__ __forceinline__ void cp_async16(void* smem, const void* gmem) {
    uint32_t s = (uint32_t)__cvta_generic_to_shared(smem);
    asm volatile("cp.async.cg.shared.global [%0], [%1], 16;" :: "r"(s), "l"(gmem));
}
#define CP_COMMIT() asm volatile("cp.async.commit_group;" ::: "memory")
#define CP_WAIT0()  asm volatile("cp.async.wait_group 0;"  ::: "memory")

__device__ __forceinline__ void ldmx4(uint32_t* r, uint32_t addr) {
    asm volatile("ldmatrix.sync.aligned.m8n8.x4.shared.b16 {%0,%1,%2,%3}, [%4];"
        : "=r"(r[0]), "=r"(r[1]), "=r"(r[2]), "=r"(r[3]) : "r"(addr));
}
__device__ __forceinline__ void ldmx2(uint32_t& r0, uint32_t& r1, uint32_t addr) {
    asm volatile("ldmatrix.sync.aligned.m8n8.x2.shared.b16 {%0,%1}, [%2];"
        : "=r"(r0), "=r"(r1) : "r"(addr));
}
__device__ __forceinline__ void ldmx2t(uint32_t& r0, uint32_t& r1, uint32_t addr) {
    asm volatile("ldmatrix.sync.aligned.m8n8.x2.trans.shared.b16 {%0,%1}, [%2];"
        : "=r"(r0), "=r"(r1) : "r"(addr));
}

// ---------------- all-fp16 pipelined tensor-core GEMM ----------------
__global__ void __launch_bounds__(256) tc_gemm_h_kernel(
    const __half* __restrict__ A, const __half* __restrict__ Bt, void* __restrict__ C,
    int M, int N, int K, const float* __restrict__ bias, int relu, int out_half)
{
    __shared__ __half As[2][128][40];
    __shared__ __half Bs[2][128][40];

    const int tid  = threadIdx.x;
    const int wid  = tid >> 5, lane = tid & 31;
    const int gid  = lane >> 2, tig = lane & 3;
    const int wy   = wid >> 2, wx = wid & 3;
    const int bm   = blockIdx.y, bn = blockIdx.x;

    const __half* Ab = A  + (size_t)bm * 128 * K;
    const __half* Bb = Bt + (size_t)bn * 128 * K;

    const int lr = tid >> 2;
    const int c8 = (tid & 3) * 8;

    const uint32_t As_sh = (uint32_t)__cvta_generic_to_shared(As);
    const uint32_t Bs_sh = (uint32_t)__cvta_generic_to_shared(Bs);
    // per-thread ldmatrix lane offsets (in halves)
    const uint32_t a_lo = (uint32_t)(lane & 15) * 40 + ((lane >> 4) << 3);
    const uint32_t b_lo = (uint32_t)(lane & 7)  * 40 + (lane & 8);

    float acc[4][4][4];
    #pragma unroll
    for (int i = 0; i < 4; i++)
        #pragma unroll
        for (int j = 0; j < 4; j++)
            #pragma unroll
            for (int r = 0; r < 4; r++) acc[i][j][r] = 0.f;

    const int nch = K >> 5;

    {
        const __half* a0 = Ab + (size_t)lr * K + c8;
        const __half* b0 = Bb + (size_t)lr * K + c8;
        cp_async16(&As[0][lr     ][c8], a0);
        cp_async16(&As[0][lr + 64][c8], a0 + (size_t)64 * K);
        cp_async16(&Bs[0][lr     ][c8], b0);
        cp_async16(&Bs[0][lr + 64][c8], b0 + (size_t)64 * K);
        CP_COMMIT();
    }

    for (int c = 0; c < nch; c++) {
        CP_WAIT0();
        __syncthreads();
        if (c + 1 < nch) {
            const int sn = (c + 1) & 1;
            const int kg = (c + 1) * 32 + c8;
            const __half* a0 = Ab + (size_t)lr * K + kg;
            const __half* b0 = Bb + (size_t)lr * K + kg;
            cp_async16(&As[sn][lr     ][c8], a0);
            cp_async16(&As[sn][lr + 64][c8], a0 + (size_t)64 * K);
            cp_async16(&Bs[sn][lr     ][c8], b0);
            cp_async16(&Bs[sn][lr + 64][c8], b0 + (size_t)64 * K);
            CP_COMMIT();
        }
        const int s = c & 1;
        const uint32_t abase = As_sh + (uint32_t)s * 128 * 40 * 2;
        const uint32_t bbase = Bs_sh + (uint32_t)s * 128 * 40 * 2;
        #pragma unroll
        for (int ks = 0; ks < 2; ks++) {
            uint32_t af[4][4];
            #pragma unroll
            for (int mf = 0; mf < 4; mf++)
                ldmx4(af[mf], abase + ((uint32_t)(wy*64 + mf*16) * 40 + ks*16 + a_lo) * 2);
            uint32_t bf[4][2];
            #pragma unroll
            for (int nf = 0; nf < 4; nf++)
                ldmx2(bf[nf][0], bf[nf][1],
                      bbase + ((uint32_t)(wx*32 + nf*8) * 40 + ks*16 + b_lo) * 2);
            #pragma unroll
            for (int mf = 0; mf < 4; mf++)
                #pragma unroll
                for (int nf = 0; nf < 4; nf++)
                    MMA_F16(acc[mf][nf], af[mf], bf[nf][0], bf[nf][1]);
        }
        __syncthreads();
    }

    float2 bsv[4];
    if (bias) {
        #pragma unroll
        for (int nf = 0; nf < 4; nf++) {
            const int col = bn * 128 + wx * 32 + nf * 8 + tig * 2;
            bsv[nf] = *(const float2*)(bias + col);
        }
    }
    #pragma unroll
    for (int mf = 0; mf < 4; mf++) {
        const int row = bm * 128 + wy * 64 + mf * 16 + gid;
        #pragma unroll
        for (int nf = 0; nf < 4; nf++) {
            const int col = bn * 128 + wx * 32 + nf * 8 + tig * 2;
            #pragma unroll
            for (int half = 0; half < 2; half++) {
                const int r = row + half * 8;
                float vx = acc[mf][nf][half*2 + 0];
                float vy = acc[mf][nf][half*2 + 1];
                if (bias) { vx += bsv[nf].x; vy += bsv[nf].y; }
                if (relu) { vx = fmaxf(vx, 0.f); vy = fmaxf(vy, 0.f); }
                if (out_half) {
                    *(uint32_t*)((__half*)C + (size_t)r * N + col) = f22h(vx, vy);
                } else {
                    *(float2*)((float*)C + (size_t)r * N + col) = make_float2(vx, vy);
                }
            }
        }
    }
}

// ---------------- weight transpose (fp32 -> fp16) ----------------
__global__ void __launch_bounds__(256) transpose_h_kernel(
    const float* __restrict__ in, __half* __restrict__ out, int R, int Cc)
{
    __shared__ float t[32][33];
    int r0 = blockIdx.y * 32, c0 = blockIdx.x * 32;
    #pragma unroll
    for (int i = threadIdx.y; i < 32; i += 8)
        t[i][threadIdx.x] = in[(size_t)(r0 + i) * Cc + c0 + threadIdx.x];
    __syncthreads();
    #pragma unroll
    for (int i = threadIdx.y; i < 32; i += 8)
        out[(size_t)(c0 + i) * R + r0 + threadIdx.x] = __float2half_rn(t[threadIdx.x][i]);
}

// ---------------- fused QKV weight assembly (fp16 out) ----------------
__global__ void __launch_bounds__(256) assemble_qkvB_kernel(
    const float* __restrict__ Wqr, const float* __restrict__ Wqi,
    const float* __restrict__ Wkr, const float* __restrict__ Wki,
    const float* __restrict__ Wv,  __half* __restrict__ out, int Kfull)
{
    __shared__ float t[32][33];
    const int k0 = blockIdx.x * 32, n0 = blockIdx.y * 32;
    const int blk  = n0 >> 9;
    const int half = k0 >> 9;
    const int ks   = k0 & 511;
    const int ns   = n0 & 511;

    const float* src = Wv;
    float sign = 1.f;
    bool zero = false;
    if      (blk == 0) { if (half == 0) src = Wqr; else { src = Wqi; sign = -1.f; } }
    else if (blk == 1) { if (half == 0) src = Wqi; else   src = Wqr; }
    else if (blk == 2) { if (half == 0) src = Wkr; else { src = Wki; sign = -1.f; } }
    else if (blk == 3) { if (half == 0) src = Wki; else   src = Wkr; }
    else               { if (half == 0) src = Wv;  else   zero = true; }

    #pragma unroll
    for (int i = threadIdx.y; i < 32; i += 8)
        t[i][threadIdx.x] = zero ? 0.f : src[(size_t)(ks + i) * 512 + ns + threadIdx.x];
    __syncthreads();
    #pragma unroll
    for (int i = threadIdx.y; i < 32; i += 8)
        out[(size_t)(n0 + i) * Kfull + k0 + threadIdx.x] =
            __float2half_rn(sign * t[threadIdx.x][i]);
}

// ---------------- embedding / positional ----------------
__global__ void __launch_bounds__(128) embed_kernel(
    const int* __restrict__ tok, const float* __restrict__ emb,
    float* __restrict__ zr, __half* __restrict__ acat)
{
    int row = blockIdx.x;
    int t = tok[row];
    int c4 = threadIdx.x * 4;
    float4 v = *(const float4*)(emb + (size_t)t * D_ + c4);
    *(float4*)(zr + (size_t)row * D_ + c4) = v;
    *(uint2*)(acat + (size_t)row * 2 * D_ + c4) =
        make_uint2(f22h(v.x, v.y), f22h(v.z, v.w));
}

__global__ void __launch_bounds__(256) posimag_kernel(__half* __restrict__ acat)
{
    int s = blockIdx.x;
    int j = threadIdx.x;
    float freq = expf(-((float)j * (1.0f/256.0f)) * 9.2103403719761836f);
    float val = sinf((float)s * freq);
    uint32_t vv = f22h(val, val);
    int d = D_ + j * 2;
    *(uint32_t*)(acat + (size_t)(0 * S_ + s) * 2 * D_ + d) = vv;
    *(uint32_t*)(acat + (size_t)(1 * S_ + s) * 2 * D_ + d) = vv;
}

// ---------------- fp16 TC complex-hybrid flash attention ----------------
// 128 q-rows/CTA, 8 warps. cp.async double-buffered K/Ki/V staging,
// ldmatrix fragments, P kept in registers (accumulator->A-fragment mapping).
__global__ void __launch_bounds__(256) attn_tc_kernel(
    const __half* __restrict__ QKV, __half* __restrict__ Out)
{
    extern __shared__ __half smh[];
    __half (*bKr)[AT_ST] = (__half(*)[AT_ST])smh;   // 128 rows: 2 stages x 64
    __half (*bKi)[AT_ST] = bKr + 128;
    __half (*bV )[AT_ST] = bKi + 128;

    const int q0 = blockIdx.x * 128;
    const int h  = blockIdx.y;
    const int b  = blockIdx.z;
    const int tid  = threadIdx.x;
    const int wid  = tid >> 5, lane = tid & 31;
    const int gid  = lane >> 2, tig = lane & 3;
    const int wrow = wid * 16;
    const size_t baseq = ((size_t)b * S_) * QKV_LD + (size_t)h * DK_;
    const size_t baseo = ((size_t)b * S_) * D_     + (size_t)h * DK_;

    const uint32_t kr_sh = (uint32_t)__cvta_generic_to_shared(bKr);
    const uint32_t ki_sh = (uint32_t)__cvta_generic_to_shared(bKi);
    const uint32_t v_sh  = (uint32_t)__cvta_generic_to_shared(bV);

    // ---- stage Q (qr into bKr[0..127], qi into bKi[0..127]) ----
    for (int i = tid; i < 128*8; i += 256) {
        int r = i >> 3, c8 = (i & 7) * 8;
        const __half* qrow = QKV + baseq + (size_t)(q0 + r) * QKV_LD + c8;
        *(uint4*)&bKr[r][c8] = *(const uint4*)(qrow);
        *(uint4*)&bKi[r][c8] = *(const uint4*)(qrow + 512);
    }
    __syncthreads();

    uint32_t aQr[4][4], aQi[4][4];
    {
        const uint32_t ro = ((uint32_t)(wrow + (lane & 15)) * AT_ST + ((lane >> 4) << 3)) * 2;
        #pragma unroll
        for (int k = 0; k < 4; k++) {
            ldmx4(aQr[k], kr_sh + ro + k * 32);
            ldmx4(aQi[k], ki_sh + ro + k * 32);
        }
    }
    __syncthreads();

    float o[8][4];
    #pragma unroll
    for (int n = 0; n < 8; n++)
        #pragma unroll
        for (int e = 0; e < 4; e++) o[n][e] = 0.f;
    float l0 = 0.f, l1 = 0.f;

    // ldmatrix per-lane offsets (in halves)
    const uint32_t kb_lo = (uint32_t)(lane & 7) * AT_ST + (lane & 8);
    const uint32_t vb_lo = (uint32_t)(lane & 15) * AT_ST;

    // prologue: stage tile 0 into stage 0
    {
        for (int i = tid; i < 64*8; i += 256) {
            int r = i >> 3, c8 = (i & 7) * 8;
            const __half* krow = QKV + baseq + (size_t)r * QKV_LD + c8;
            cp_async16(&bKr[r][c8], krow + 1024);
            cp_async16(&bKi[r][c8], krow + 1536);
            cp_async16(&bV [r][c8], krow + 2048);
        }
        CP_COMMIT();
    }

    const int NT = S_ / 64;
    for (int ti = 0; ti < NT; ti++) {
        CP_WAIT0();
        __syncthreads();
        if (ti + 1 < NT) {
            const int sn = (ti + 1) & 1;
            const int kt = (ti + 1) * 64;
            for (int i = tid; i < 64*8; i += 256) {
                int r = i >> 3, c8 = (i & 7) * 8;
                const __half* krow = QKV + baseq + (size_t)(kt + r) * QKV_LD + c8;
                cp_async16(&bKr[sn*64 + r][c8], krow + 1024);
                cp_async16(&bKi[sn*64 + r][c8], krow + 1536);
                cp_async16(&bV [sn*64 + r][c8], krow + 2048);
            }
            CP_COMMIT();
        }
        const int s = ti & 1;
        const uint32_t soff = (uint32_t)(s * 64) * AT_ST * 2;

        // ---- scores ----
        float srf[8][4], sif[8][4];
        #pragma unroll
        for (int n = 0; n < 8; n++)
            #pragma unroll
            for (int e = 0; e < 4; e++) { srf[n][e] = 0.f; sif[n][e] = 0.f; }

        #pragma unroll
        for (int k = 0; k < 4; k++) {
            #pragma unroll
            for (int n = 0; n < 8; n++) {
                const uint32_t off = soff + ((uint32_t)(n * 8) * AT_ST + k * 16 + kb_lo) * 2;
                uint32_t b0r, b1r, b0i, b1i;
                ldmx2(b0r, b1r, kr_sh + off);
                ldmx2(b0i, b1i, ki_sh + off);
                MMA_F16(srf[n], aQr[k], b0r, b1r);
                MMA_F16(srf[n], aQi[k], b0i, b1i);
                MMA_F16(sif[n], aQi[k], b0r, b1r);
                uint32_t n0 = b0i ^ 0x80008000u, n1 = b1i ^ 0x80008000u;
                MMA_F16(sif[n], aQr[k], n0, n1);
            }
        }

        // ---- hybrid score -> p ----
        float psum0 = 0.f, psum1 = 0.f;
        #pragma unroll
        for (int n = 0; n < 8; n++) {
            #pragma unroll
            for (int e = 0; e < 4; e++) {
                float a = srf[n][e], c = sif[n][e];
                float m2 = fmaf(a, a, c * c);
                float y  = rsqrt_fast(m2);
                float sc = y * fmaf(0.015625f, m2, 0.0375f * a);
                sc = (m2 == 0.f) ? 0.0375f : sc;
                float p = exp_poly(sc);
                srf[n][e] = p;
                if (e < 2) psum0 += p; else psum1 += p;
            }
        }
        psum0 += __shfl_xor_sync(0xffffffffu, psum0, 1);
        psum0 += __shfl_xor_sync(0xffffffffu, psum0, 2);
        psum1 += __shfl_xor_sync(0xffffffffu, psum1, 1);
        psum1 += __shfl_xor_sync(0xffffffffu, psum1, 2);
        l0 += psum0; l1 += psum1;

        // ---- PV: P stays in registers; V fragments via ldmatrix.trans ----
        #pragma unroll
        for (int kc = 0; kc < 4; kc++) {
            uint32_t ap[4];
            ap[0] = f22h(srf[2*kc  ][0], srf[2*kc  ][1]);
            ap[1] = f22h(srf[2*kc  ][2], srf[2*kc  ][3]);
            ap[2] = f22h(srf[2*kc+1][0], srf[2*kc+1][1]);
            ap[3] = f22h(srf[2*kc+1][2], srf[2*kc+1][3]);
            #pragma unroll
            for (int n = 0; n < 8; n++) {
                const uint32_t off = soff + ((uint32_t)(kc * 16) * AT_ST + n * 8 + vb_lo) * 2;
                uint32_t b0, b1;
                ldmx2t(b0, b1, v_sh + off);
                MMA_F16(o[n], ap, b0, b1);
            }
        }
    }

    const float inv0 = 1.0f / l0;
    const float inv1 = 1.0f / l1;
    #pragma unroll
    for (int n = 0; n < 8; n++) {
        const int col = n * 8 + 2 * tig;
        *(uint32_t*)(Out + baseo + (size_t)(q0 + wrow + gid    ) * D_ + col) =
            f22h(o[n][0] * inv0, o[n][1] * inv0);
        *(uint32_t*)(Out + baseo + (size_t)(q0 + wrow + gid + 8) * D_ + col) =
            f22h(o[n][2] * inv1, o[n][3] * inv1);
    }
}

// ---------------- fused residual + layernorm ----------------
__global__ void __launch_bounds__(128) ln_res_kernel(
    const float* __restrict__ x, const float* __restrict__ r,
    const float* __restrict__ g, const float* __restrict__ be,
    float* __restrict__ outf, __half* __restrict__ outh)
{
    __shared__ float red[8];
    int row = blockIdx.x, tid = threadIdx.x;
    float4 xv = *(const float4*)(x + (size_t)row * D_ + tid * 4);
    float4 rv = *(const float4*)(r + (size_t)row * D_ + tid * 4);
    float v0 = xv.x + rv.x, v1 = xv.y + rv.y, v2 = xv.z + rv.z, v3 = xv.w + rv.w;
    float s  = v0 + v1 + v2 + v3;
    float s2 = v0*v0 + v1*v1 + v2*v2 + v3*v3;
    #pragma unroll
    for (int o = 16; o >= 1; o >>= 1) {
        s  += __shfl_xor_sync(0xffffffffu, s,  o);
        s2 += __shfl_xor_sync(0xffffffffu, s2, o);
    }
    int warp = tid >> 5, lane = tid & 31;
    if (lane == 0) { red[warp] = s; red[4 + warp] = s2; }
    __syncthreads();
    s  = red[0] + red[1] + red[2] + red[3];
    s2 = red[4] + red[5] + red[6] + red[7];
    float mu  = s  * (1.0f / D_);
    float var = s2 * (1.0f / D_) - mu * mu;
    float inv = rsqrtf(var + 1e-5f);
    float4 gv = *(const float4*)(g  + tid * 4);
    float4 bv = *(const float4*)(be + tid * 4);
    float4 o4;
    o4.x = (v0 - mu) * inv * gv.x + bv.x;
    o4.y = (v1 - mu) * inv * gv.y + bv.y;
    o4.z = (v2 - mu) * inv * gv.z + bv.z;
    o4.w = (v3 - mu) * inv * gv.w + bv.w;
    *(float4*)(outf + (size_t)row * D_ + tid * 4) = o4;
    *(uint2*)(outh + (size_t)row * D_ + tid * 4) =
        make_uint2(f22h(o4.x, o4.y), f22h(o4.z, o4.w));
}

// ---------------- classification head ----------------
__global__ void __launch_bounds__(256) head_kernel(
    const float* __restrict__ z, const float* __restrict__ w,
    const float* __restrict__ hb, float* __restrict__ out)
{
    int warp = threadIdx.x >> 5, lane = threadIdx.x & 31;
    int row = blockIdx.x * 8 + warp;
    const float* zr = z + (size_t)row * D_;
    float s0 = 0.f, s1 = 0.f;
    for (int d = lane; d < D_; d += 32) {
        float zv = zr[d];
        s0 += zv * w[d*2 + 0];
        s1 += zv * w[d*2 + 1];
    }
    #pragma unroll
    for (int o = 16; o >= 1; o >>= 1) {
        s0 += __shfl_xor_sync(0xffffffffu, s0, o);
        s1 += __shfl_xor_sync(0xffffffffu, s1, o);
    }
    if (lane == 0) {
        out[row*2 + 0] = s0 + hb[0];
        out[row*2 + 1] = s1 + hb[1];
    }
}

// ---------------- host-side orchestration ----------------
static inline void launch_gemm(const __half* A, const __half* Bt, void* C,
                               int M, int N, int K, const float* bias, int relu,
                               int out_half)
{
    dim3 grid(N / 128, M / 128);
    tc_gemm_h_kernel<<<grid, 256>>>(A, Bt, C, M, N, K, bias, relu, out_half);
}

static inline void launch_transpose(const float* in, __half* out, int R, int Cc)
{
    dim3 grid(Cc / 32, R / 32);
    transpose_h_kernel<<<grid, dim3(32, 8)>>>(in, out, R, Cc);
}

extern "C" void kernel_launch(void* const* d_in, const int* in_sizes, int n_in,
                              void* d_out, int out_size)
{
    (void)in_sizes; (void)n_in; (void)out_size;
    const int*   tokens = (const int*)  d_in[0];
    const float* embed  = (const float*)d_in[1];
    const float* Wqr = (const float*)d_in[2];
    const float* Wqi = (const float*)d_in[3];
    const float* Wkr = (const float*)d_in[4];
    const float* Wki = (const float*)d_in[5];
    const float* Wv  = (const float*)d_in[6];
    const float* Wo  = (const float*)d_in[7];
    const float* bo  = (const float*)d_in[8];
    const float* W1  = (const float*)d_in[9];
    const float* b1  = (const float*)d_in[10];
    const float* W2  = (const float*)d_in[11];
    const float* b2  = (const float*)d_in[12];
    const float* g1  = (const float*)d_in[13];
    const float* be1 = (const float*)d_in[14];
    const float* g2  = (const float*)d_in[15];
    const float* be2 = (const float*)d_in[16];
    const float* hw  = (const float*)d_in[17];
    const float* hb  = (const float*)d_in[18];
    float* out = (float*)d_out;

    float *zr,*t0,*z1;
    __half *zrh,*acat,*qkvh,*ctxh,*z1h,*ffh,*b0h,*b1h,*wth;
    cudaGetSymbolAddress((void**)&zr,   g_zr);
    cudaGetSymbolAddress((void**)&zrh,  g_zrh);
    cudaGetSymbolAddress((void**)&acat, g_acat);
    cudaGetSymbolAddress((void**)&qkvh, g_qkvh);
    cudaGetSymbolAddress((void**)&ctxh, g_ctxh);
    cudaGetSymbolAddress((void**)&t0,   g_t0);
    cudaGetSymbolAddress((void**)&z1,   g_z1);
    cudaGetSymbolAddress((void**)&z1h,  g_z1h);
    cudaGetSymbolAddress((void**)&ffh,  g_ffh);
    cudaGetSymbolAddress((void**)&b0h,  g_b0h);
    cudaGetSymbolAddress((void**)&b1h,  g_b1h);
    cudaGetSymbolAddress((void**)&wth,  g_wth);

    cudaFuncSetAttribute(attn_tc_kernel, cudaFuncAttributeMaxDynamicSharedMemorySize,
                         ATTN_SMEM_BYTES);

    embed_kernel<<<ROWS, 128>>>(tokens, embed, zr, acat);
    posimag_kernel<<<S_, 256>>>(acat);

    const size_t DD = (size_t)D_ * D_;
    const size_t DF = (size_t)D_ * DFF_;

    {
        dim3 g0(2 * D_ / 32, QKV_N / 32);
        assemble_qkvB_kernel<<<g0, dim3(32, 8)>>>(Wqr, Wqi, Wkr, Wki, Wv, b0h, 2 * D_);
        dim3 g1d(D_ / 32, QKV_N / 32);
        assemble_qkvB_kernel<<<g1d, dim3(32, 8)>>>(Wqr + DD, Wqi + DD, Wkr + DD,
                                                   Wki + DD, Wv + DD, b1h, D_);
    }
    for (int l = 0; l < L_; l++) {
        __half* base = wth + (size_t)l * WT2_PER_LAYER;
        launch_transpose(Wo + l*DD, base,           D_,   D_);
        launch_transpose(W1 + l*DF, base + DD,      D_,   DFF_);
        launch_transpose(W2 + l*DF, base + DD + DF, DFF_, D_);
    }

    for (int l = 0; l < L_; l++) {
        __half* base = wth + (size_t)l * WT2_PER_LAYER;
        const __half* woT  = base;
        const __half* w1T  = base + DD;
        const __half* w2T  = base + DD + DF;
        const float* bo_l  = bo  + (size_t)l * D_;
        const float* b1_l  = b1  + (size_t)l * DFF_;
        const float* b2_l  = b2  + (size_t)l * D_;
        const float* g1_l  = g1  + (size_t)l * D_;
        const float* be1_l = be1 + (size_t)l * D_;
        const float* g2_l  = g2  + (size_t)l * D_;
        const float* be2_l = be2 + (size_t)l * D_;

        if (l == 0)
            launch_gemm(acat, b0h, qkvh, ROWS, QKV_N, 2 * D_, nullptr, 0, 1);
        else
            launch_gemm(zrh, b1h, qkvh, ROWS, QKV_N, D_, nullptr, 0, 1);

        dim3 ag(S_ / 128, H_, B_);
        attn_tc_kernel<<<ag, 256, ATTN_SMEM_BYTES>>>(qkvh, ctxh);

        launch_gemm(ctxh, woT, t0, ROWS, D_, D_, bo_l, 0, 0);
        ln_res_kernel<<<ROWS, 128>>>(zr, t0, g1_l, be1_l, z1, z1h);
        launch_gemm(z1h, w1T, ffh, ROWS, DFF_, D_, b1_l, 1, 1);
        launch_gemm(ffh, w2T, t0, ROWS, D_, DFF_, b2_l, 0, 0);
        ln_res_kernel<<<ROWS, 128>>>(z1, t0, g2_l, be2_l, zr, zrh);
    }

    head_kernel<<<ROWS / 8, 256>>>(zr, hw, hb, out);
}